// round 10
// baseline (speedup 1.0000x reference)
#include <cuda_runtime.h>
#include <cuda_bf16.h>
#include <cuda_fp16.h>
#include <cstdint>

#define QLEN  1024
#define MLEN  1024
#define KLENN 2048
#define BATCH 4
#define NH    16
#define DH    64
#define DM    1024

// fp32 scratch
__device__ float g_Q[BATCH*NH*QLEN*DH];
__device__ float g_K[BATCH*NH*KLENN*DH];
__device__ float g_V[BATCH*NH*KLENN*DH];
__device__ float g_R[NH*KLENN*DH];
__device__ float g_AV[QLEN*BATCH*DM];
__device__ float g_O[QLEN*BATCH*DM];
// bf16 hi/lo planes (GEMMs)
__device__ __nv_bfloat16 g_Ah[8192*DM],  g_Al[8192*DM];
__device__ __nv_bfloat16 g_W3h[DM*3072], g_W3l[DM*3072];
__device__ __nv_bfloat16 g_Rph[KLENN*DM],g_Rpl[KLENN*DM];
__device__ __nv_bfloat16 g_Wrh[DM*DM],   g_Wrl[DM*DM];
__device__ __nv_bfloat16 g_Woh[DM*DM],   g_Wol[DM*DM];
__device__ __nv_bfloat16 g_AVh[4096*DM], g_AVl[4096*DM];
// fp16 attention operands
__device__ __half g_Qah[BATCH*NH*QLEN*DH];
__device__ __half g_Qbh[BATCH*NH*QLEN*DH];
__device__ __half g_Kh[BATCH*NH*KLENN*DH];
__device__ __half g_Vh[BATCH*NH*KLENN*DH];
__device__ __half g_Rh[NH*KLENN*DH];

__device__ __forceinline__ float ex2(float x) {
    float y; asm("ex2.approx.ftz.f32 %0, %1;" : "=f"(y) : "f"(x)); return y;
}

// ---------------------------------------------------------------------------
// bf16 split kernel (GEMM precision): hi = bf16(x), lo = bf16(x - hi)
// ---------------------------------------------------------------------------
__global__ __launch_bounds__(256)
void k_splitb(const float* __restrict__ src, __nv_bfloat16* __restrict__ hi,
              __nv_bfloat16* __restrict__ lo, int n4)
{
    int i = blockIdx.x*256 + threadIdx.x;
    if (i < n4) {
        float4 v = ((const float4*)src)[i];
        float f[4] = {v.x, v.y, v.z, v.w};
        uint32_t hp[2], lp[2];
        #pragma unroll
        for (int p = 0; p < 2; p++) {
            __nv_bfloat16 h0 = __float2bfloat16(f[2*p]);
            __nv_bfloat16 h1 = __float2bfloat16(f[2*p+1]);
            __nv_bfloat16 l0 = __float2bfloat16(f[2*p]   - __bfloat162float(h0));
            __nv_bfloat16 l1 = __float2bfloat16(f[2*p+1] - __bfloat162float(h1));
            hp[p] = (uint32_t)__bfloat16_as_ushort(h0) | ((uint32_t)__bfloat16_as_ushort(h1)<<16);
            lp[p] = (uint32_t)__bfloat16_as_ushort(l0) | ((uint32_t)__bfloat16_as_ushort(l1)<<16);
        }
        ((uint2*)hi)[i] = make_uint2(hp[0], hp[1]);
        ((uint2*)lo)[i] = make_uint2(lp[0], lp[1]);
    }
}

// fp32 -> fp16 cast (attention operands)
__global__ __launch_bounds__(256)
void k_tohalf(const float* __restrict__ src, __half* __restrict__ dst, int n4)
{
    int i = blockIdx.x*256 + threadIdx.x;
    if (i < n4) {
        float4 v = ((const float4*)src)[i];
        __half2 h01 = __floats2half2_rn(v.x, v.y);
        __half2 h23 = __floats2half2_rn(v.z, v.w);
        ((uint2*)dst)[i] = make_uint2(*(uint32_t*)&h01, *(uint32_t*)&h23);
    }
}

// Q + biases -> fp16 Qa/Qb planes. g_Q layout ((b*16+n)*1024+q)*64+d
__global__ __launch_bounds__(256)
void k_qprep(const float* __restrict__ rwb, const float* __restrict__ rrb)
{
    int i = blockIdx.x*256 + threadIdx.x;     // over 1M float4
    if (i >= BATCH*NH*QLEN*DH/4) return;
    float4 v = ((const float4*)g_Q)[i];
    int d = (i & 15) * 4;
    int n = (i >> 14) & 15;
    float4 wa = *(const float4*)&rwb[n*DH + d];
    float4 wb = *(const float4*)&rrb[n*DH + d];
    __half2 a01 = __floats2half2_rn(v.x+wa.x, v.y+wa.y);
    __half2 a23 = __floats2half2_rn(v.z+wa.z, v.w+wa.w);
    __half2 b01 = __floats2half2_rn(v.x+wb.x, v.y+wb.y);
    __half2 b23 = __floats2half2_rn(v.z+wb.z, v.w+wb.w);
    ((uint2*)g_Qah)[i] = make_uint2(*(uint32_t*)&a01, *(uint32_t*)&a23);
    ((uint2*)g_Qbh)[i] = make_uint2(*(uint32_t*)&b01, *(uint32_t*)&b23);
}

// ---------------------------------------------------------------------------
// MMA primitives
// ---------------------------------------------------------------------------
__device__ __forceinline__ void ldsm4(uint32_t (&r)[4], uint32_t addr) {
    asm volatile("ldmatrix.sync.aligned.m8n8.x4.shared.b16 {%0,%1,%2,%3}, [%4];"
        : "=r"(r[0]), "=r"(r[1]), "=r"(r[2]), "=r"(r[3]) : "r"(addr));
}
__device__ __forceinline__ void ldsm4t(uint32_t (&r)[4], uint32_t addr) {
    asm volatile("ldmatrix.sync.aligned.m8n8.x4.trans.shared.b16 {%0,%1,%2,%3}, [%4];"
        : "=r"(r[0]), "=r"(r[1]), "=r"(r[2]), "=r"(r[3]) : "r"(addr));
}
__device__ __forceinline__ void mma16b(float (&c)[4], const uint32_t (&a)[4],
                                       uint32_t b0, uint32_t b1) {
    asm volatile(
        "mma.sync.aligned.m16n8k16.row.col.f32.bf16.bf16.f32 "
        "{%0,%1,%2,%3},{%4,%5,%6,%7},{%8,%9},{%0,%1,%2,%3};"
        : "+f"(c[0]), "+f"(c[1]), "+f"(c[2]), "+f"(c[3])
        : "r"(a[0]), "r"(a[1]), "r"(a[2]), "r"(a[3]), "r"(b0), "r"(b1));
}
__device__ __forceinline__ void mma16h(float (&c)[4], const uint32_t (&a)[4],
                                       uint32_t b0, uint32_t b1) {
    asm volatile(
        "mma.sync.aligned.m16n8k16.row.col.f32.f16.f16.f32 "
        "{%0,%1,%2,%3},{%4,%5,%6,%7},{%8,%9},{%0,%1,%2,%3};"
        : "+f"(c[0]), "+f"(c[1]), "+f"(c[2]), "+f"(c[3])
        : "r"(a[0]), "r"(a[1]), "r"(a[2]), "r"(a[3]), "r"(b0), "r"(b1));
}
__device__ __forceinline__ void cpa16(uint32_t dst, const void* src) {
    asm volatile("cp.async.cg.shared.global [%0], [%1], 16;" :: "r"(dst), "l"(src));
}
__device__ __forceinline__ void cpa16z(uint32_t dst, const void* src, int nbytes) {
    asm volatile("cp.async.cg.shared.global [%0], [%1], 16, %2;"
                 :: "r"(dst), "l"(src), "r"(nbytes));
}

// ---------------------------------------------------------------------------
// bf16-split GEMM (unchanged from round 7)
// ---------------------------------------------------------------------------
#define KS 32
#define A_PAD 40
#define B_PAD 136
#define A_PLANE (128*A_PAD)
#define A_BUF   (2*A_PLANE)
#define B_PLANE (KS*B_PAD)
#define B_BUF   (2*B_PLANE)
#define BUF_ELEMS (A_BUF + B_BUF)
#define SMEM_GEMM (2*BUF_ELEMS*2)

__device__ __forceinline__ void cta_load(
    uint32_t sb, int buf,
    const __nv_bfloat16* __restrict__ Ah, const __nv_bfloat16* __restrict__ Al, size_t m0,
    const __nv_bfloat16* __restrict__ Bh, const __nv_bfloat16* __restrict__ Bl,
    int ldb, int n0, int kt, int t)
{
    uint32_t bo = sb + (uint32_t)buf * (BUF_ELEMS*2);
    #pragma unroll
    for (int i = 0; i < 4; i++) {
        int c = t + 256*i;
        int p = c >> 9, rc = c & 511;
        int row = rc >> 2, seg = rc & 3;
        const __nv_bfloat16* src = (p ? Al : Ah) + (m0 + row)*DM + kt + seg*8;
        cpa16(bo + (uint32_t)(p*A_PLANE + row*A_PAD + seg*8)*2, src);
    }
    #pragma unroll
    for (int i = 0; i < 4; i++) {
        int c = t + 256*i;
        int p = c >> 9, rc = c & 511;
        int row = rc >> 4, seg = rc & 15;
        const __nv_bfloat16* src = (p ? Bl : Bh) + (size_t)(kt + row)*ldb + n0 + seg*8;
        cpa16(bo + (uint32_t)(A_BUF*2 + (p*B_PLANE + row*B_PAD + seg*8)*2), src);
    }
}

__device__ __forceinline__ void gemm_bf16(
    const __nv_bfloat16* __restrict__ Ah, const __nv_bfloat16* __restrict__ Al, size_t m0,
    const __nv_bfloat16* __restrict__ Bh, const __nv_bfloat16* __restrict__ Bl,
    int ldb, int n0, float (&C)[4][4][4], char* smem, int t)
{
    uint32_t sb = (uint32_t)__cvta_generic_to_shared(smem);
    const int lane = t&31, w = t>>5, wm = w>>2, wn = w&3;
    const uint32_t aBase = (uint32_t)(((wm*64 + (lane&15))*A_PAD + ((lane>>4)<<3))*2);
    const uint32_t bBase = (uint32_t)(A_BUF*2 + (((lane&15))*B_PAD + wn*32 + ((lane>>4)<<3))*2);

    cta_load(sb, 0, Ah, Al, m0, Bh, Bl, ldb, n0, 0, t);
    asm volatile("cp.async.commit_group;");

    for (int it = 0; it < DM/KS; ++it) {
        int buf = it & 1;
        if (it + 1 < DM/KS) {
            cta_load(sb, 1-buf, Ah, Al, m0, Bh, Bl, ldb, n0, (it+1)*KS, t);
            asm volatile("cp.async.commit_group;");
            asm volatile("cp.async.wait_group 1;");
        } else {
            asm volatile("cp.async.wait_group 0;");
        }
        __syncthreads();

        uint32_t bo = sb + (uint32_t)buf*(BUF_ELEMS*2);
        #pragma unroll
        for (int c16 = 0; c16 < 2; c16++) {
            uint32_t bb = bo + bBase + (uint32_t)(c16*16*B_PAD*2);
            uint32_t bH0[4], bS0[4], bH1[4], bS1[4];
            ldsm4t(bH0, bb);
            ldsm4t(bS0, bb + B_PLANE*2);
            ldsm4t(bH1, bb + 32);
            ldsm4t(bS1, bb + 32 + B_PLANE*2);
            #pragma unroll
            for (int mt = 0; mt < 4; mt++) {
                uint32_t ab = bo + aBase + (uint32_t)(mt*16*A_PAD*2 + c16*32);
                uint32_t aH[4], aS[4];
                ldsm4(aH, ab);
                ldsm4(aS, ab + A_PLANE*2);
                mma16b(C[mt][0], aH, bH0[0], bH0[1]);
                mma16b(C[mt][0], aH, bS0[0], bS0[1]);
                mma16b(C[mt][0], aS, bH0[0], bH0[1]);
                mma16b(C[mt][1], aH, bH0[2], bH0[3]);
                mma16b(C[mt][1], aH, bS0[2], bS0[3]);
                mma16b(C[mt][1], aS, bH0[2], bH0[3]);
                mma16b(C[mt][2], aH, bH1[0], bH1[1]);
                mma16b(C[mt][2], aH, bS1[0], bS1[1]);
                mma16b(C[mt][2], aS, bH1[0], bH1[1]);
                mma16b(C[mt][3], aH, bH1[2], bH1[3]);
                mma16b(C[mt][3], aH, bS1[2], bS1[3]);
                mma16b(C[mt][3], aS, bH1[2], bH1[3]);
            }
        }
        __syncthreads();
    }
}

__global__ __launch_bounds__(256)
void k_qkv()
{
    extern __shared__ char smg[];
    const int t = threadIdx.x, n0 = blockIdx.x<<7, m0 = blockIdx.y<<7;
    const int lane = t&31, w = t>>5, wm = w>>2, wn = w&3;
    const int tig = lane&3, grp = lane>>2;
    float C[4][4][4];
    #pragma unroll
    for (int i = 0; i < 4; i++) {
        #pragma unroll
        for (int j = 0; j < 4; j++) {
            #pragma unroll
            for (int k = 0; k < 4; k++) C[i][j][k] = 0.f;
        }
    }
    gemm_bf16(g_Ah, g_Al, (size_t)m0, g_W3h, g_W3l, 3072, n0, C, smg, t);

    #pragma unroll
    for (int mt = 0; mt < 4; mt++) {
        #pragma unroll
        for (int h = 0; h < 2; h++) {
            int m = m0 + wm*64 + mt*16 + grp + 8*h;
            int row = m >> 2, bb = m & 3;
            #pragma unroll
            for (int nt = 0; nt < 4; nt++) {
                int col = n0 + wn*32 + nt*8 + 2*tig;
                int sec = col >> 10, nn = (col>>6)&15, dd = col & 63;
                float2 v = make_float2(C[mt][nt][2*h], C[mt][nt][2*h+1]);
                if (sec == 0) {
                    if (row >= MLEN)
                        *(float2*)&g_Q[(((size_t)bb*NH+nn)*QLEN + (row-MLEN))*DH + dd] = v;
                } else if (sec == 1) {
                    *(float2*)&g_K[(((size_t)bb*NH+nn)*KLENN + row)*DH + dd] = v;
                } else {
                    *(float2*)&g_V[(((size_t)bb*NH+nn)*KLENN + row)*DH + dd] = v;
                }
            }
        }
    }
}

__global__ __launch_bounds__(256)
void k_rproj()
{
    extern __shared__ char smg[];
    const int t = threadIdx.x, n0 = blockIdx.x<<7, m0 = blockIdx.y<<7;
    const int lane = t&31, w = t>>5, wm = w>>2, wn = w&3;
    const int tig = lane&3, grp = lane>>2;
    float C[4][4][4];
    #pragma unroll
    for (int i = 0; i < 4; i++) {
        #pragma unroll
        for (int j = 0; j < 4; j++) {
            #pragma unroll
            for (int k = 0; k < 4; k++) C[i][j][k] = 0.f;
        }
    }
    gemm_bf16(g_Rph, g_Rpl, (size_t)m0, g_Wrh, g_Wrl, DM, n0, C, smg, t);

    #pragma unroll
    for (int mt = 0; mt < 4; mt++) {
        #pragma unroll
        for (int h = 0; h < 2; h++) {
            int m = m0 + wm*64 + mt*16 + grp + 8*h;
            #pragma unroll
            for (int nt = 0; nt < 4; nt++) {
                int col = n0 + wn*32 + nt*8 + 2*tig;
                int nn = col >> 6, dd = col & 63;
                float2 v = make_float2(C[mt][nt][2*h], C[mt][nt][2*h+1]);
                *(float2*)&g_R[((size_t)nn*KLENN + m)*DH + dd] = v;
            }
        }
    }
}

__global__ __launch_bounds__(256)
void k_out(const float* __restrict__ content)
{
    extern __shared__ char smg[];
    const int t = threadIdx.x, n0 = blockIdx.x<<7, m0 = blockIdx.y<<7;
    const int lane = t&31, w = t>>5, wm = w>>2, wn = w&3;
    const int tig = lane&3, grp = lane>>2;
    float C[4][4][4];
    #pragma unroll
    for (int i = 0; i < 4; i++) {
        #pragma unroll
        for (int j = 0; j < 4; j++) {
            #pragma unroll
            for (int k = 0; k < 4; k++) C[i][j][k] = 0.f;
        }
    }
    gemm_bf16(g_AVh, g_AVl, (size_t)m0, g_Woh, g_Wol, DM, n0, C, smg, t);

    #pragma unroll
    for (int mt = 0; mt < 4; mt++) {
        #pragma unroll
        for (int h = 0; h < 2; h++) {
            size_t m = m0 + wm*64 + mt*16 + grp + 8*h;
            #pragma unroll
            for (int nt = 0; nt < 4; nt++) {
                int col = n0 + wn*32 + nt*8 + 2*tig;
                float2 c4 = *(const float2*)(content + m*DM + col);
                float2 v = make_float2(C[mt][nt][2*h] + c4.x, C[mt][nt][2*h+1] + c4.y);
                *(float2*)&g_O[m*DM + col] = v;
            }
        }
    }
}

// ---------------------------------------------------------------------------
// MMA flash attention with XL rel-shift. 64 q-rows/CTA, 256 thr.
// S1 = Qa K^T (64x64), S2 = Qb Rwin^T (64x128); gather S2[il][jc-il+63].
// ---------------------------------------------------------------------------
#define OQA 0
#define OQB 9216
#define OKT 18432
#define OVT 27648
#define ORT 36864
#define OS1 55296
#define OS2 72704
#define OPS 106496
#define OCF 115712
#define OLI 115968
#define SMEM_ATTN 116224

__global__ __launch_bounds__(256)
void k_attn()
{
    extern __shared__ char sm[];
    uint32_t sb = (uint32_t)__cvta_generic_to_shared(sm);
    float* sS1 = (float*)(sm + OS1);   // [64][68]
    float* sS2 = (float*)(sm + OS2);   // [64][132]
    __half* pS = (__half*)(sm + OPS);  // [64][72]
    float* cfs = (float*)(sm + OCF);
    float* lis = (float*)(sm + OLI);

    const int t = threadIdx.x, lane = t&31, w = t>>5;
    const int tx = t&15, ty = t>>4;
    const int wm = w&3, wn = w>>2;
    const int tig = lane&3, grp = lane>>2;
    const int i0 = blockIdx.x<<6, n = blockIdx.y, b = blockIdx.z;

    const __half* Qag = g_Qah + ((size_t)(b*NH+n)*QLEN + i0)*DH;
    const __half* Qbg = g_Qbh + ((size_t)(b*NH+n)*QLEN + i0)*DH;
    const __half* Kg  = g_Kh  + (size_t)(b*NH+n)*KLENN*DH;
    const __half* Vg  = g_Vh  + (size_t)(b*NH+n)*KLENN*DH;
    const __half* Rg  = g_Rh  + (size_t)n*KLENN*DH;

    // Q tiles -> smem (once)
    #pragma unroll
    for (int i = 0; i < 4; i++) {
        int c = t + 256*i;
        int which = c >> 9, rc = c & 511;
        int row = rc >> 3, seg = rc & 7;
        const __half* src = (which ? Qbg : Qag) + row*DH + seg*8;
        cpa16(sb + (which ? OQB : OQA) + (uint32_t)(row*72 + seg*8)*2, src);
    }
    asm volatile("cp.async.commit_group;");
    asm volatile("cp.async.wait_group 0;");
    __syncthreads();

    // Qa/Qb A-fragments (persist)
    uint32_t aQa[4][4], aQb[4][4];
    #pragma unroll
    for (int ks = 0; ks < 4; ks++) {
        uint32_t off = (uint32_t)(((wm*16 + (lane&15))*72 + ks*16 + ((lane>>4)<<3))*2);
        ldsm4(aQa[ks], sb + OQA + off);
        ldsm4(aQb[ks], sb + OQB + off);
    }

    float mrow[4], lrow[4], oC[4][4];
    #pragma unroll
    for (int a = 0; a < 4; a++) { mrow[a] = -1e30f; lrow[a] = 0.f; }
    #pragma unroll
    for (int nb = 0; nb < 4; nb++) {
        #pragma unroll
        for (int k = 0; k < 4; k++) oC[nb][k] = 0.f;
    }

    const float fscale = 0.18033688011112042f;  // (1/8)*log2(e)
    const int ntiles = (i0>>6) + 17;

    for (int tile = 0; tile < ntiles; tile++) {
        const int j0 = tile<<6;
        __syncthreads();
        // load K, V, R(window) fp16 via cp.async
        #pragma unroll
        for (int i = 0; i < 8; i++) {
            int c = t + 256*i;
            if (c < 512) {
                int row = c >> 3, seg = c & 7;
                cpa16(sb + OKT + (uint32_t)(row*72 + seg*8)*2, Kg + (size_t)(j0+row)*DH + seg*8);
            } else if (c < 1024) {
                int rc = c - 512, row = rc >> 3, seg = rc & 7;
                cpa16(sb + OVT + (uint32_t)(row*72 + seg*8)*2, Vg + (size_t)(j0+row)*DH + seg*8);
            } else {
                int rc = c - 1024, row = rc >> 3, seg = rc & 7;
                int mg = j0 + 960 - i0 + row;
                int ok = (mg < KLENN) ? 16 : 0;
                if (mg >= KLENN) mg = KLENN - 1;
                cpa16z(sb + ORT + (uint32_t)(row*72 + seg*8)*2, Rg + (size_t)mg*DH + seg*8, ok);
            }
        }
        asm volatile("cp.async.commit_group;");
        asm volatile("cp.async.wait_group 0;");
        __syncthreads();

        // S-MMA: 24 n-blocks of 8 across wn halves (0..7 = K, 8..23 = R)
        float sC[12][4];
        #pragma unroll
        for (int p = 0; p < 12; p++) {
            #pragma unroll
            for (int k = 0; k < 4; k++) sC[p][k] = 0.f;
        }
        #pragma unroll
        for (int ks = 0; ks < 4; ks++) {
            uint32_t bf[6][4];
            #pragma unroll
            for (int p = 0; p < 6; p++) {
                int blk = wn*12 + 2*p;
                uint32_t base = (blk < 8) ? (sb + OKT) : (sb + ORT);
                int nrow = (blk < 8) ? blk*8 : (blk-8)*8;
                uint32_t addr = base + (uint32_t)(((nrow + (lane&7) + ((lane>>4)<<3))*72
                                 + ks*16 + (((lane>>3)&1)<<3))*2);
                ldsm4(bf[p], addr);
            }
            #pragma unroll
            for (int p = 0; p < 6; p++) {
                int blk = wn*12 + 2*p;
                if (blk < 8) { mma16h(sC[2*p], aQa[ks], bf[p][0], bf[p][1]); }
                else         { mma16h(sC[2*p], aQb[ks], bf[p][0], bf[p][1]); }
                if (blk+1 < 8) { mma16h(sC[2*p+1], aQa[ks], bf[p][2], bf[p][3]); }
                else           { mma16h(sC[2*p+1], aQb[ks], bf[p][2], bf[p][3]); }
            }
        }
        // spill S to smem
        #pragma unroll
        for (int p = 0; p < 12; p++) {
            int blk = wn*12 + p;
            int r0 = wm*16 + grp;
            if (blk < 8) {
                int col = blk*8 + 2*tig;
                *(float2*)&sS1[r0*68 + col]     = make_float2(sC[p][0], sC[p][1]);
                *(float2*)&sS1[(r0+8)*68 + col] = make_float2(sC[p][2], sC[p][3]);
            } else {
                int col = (blk-8)*8 + 2*tig;
                *(float2*)&sS2[r0*132 + col]     = make_float2(sC[p][0], sC[p][1]);
                *(float2*)&sS2[(r0+8)*132 + col] = make_float2(sC[p][2], sC[p][3]);
            }
        }
        __syncthreads();

        // softmax (scalar, 16x16 thread grid)
        #pragma unroll
        for (int a = 0; a < 4; a++) {
            const int il = ty*4 + a;
            const int iq = i0 + il;
            float4 s1 = *(const float4*)&sS1[il*68 + tx*4];
            int gb = tx*4 - il + 63;
            float s[4];
            s[0] = s1.x + sS2[il*132 + gb];
            s[1] = s1.y + sS2[il*132 + gb+1];
            s[2] = s1.z + sS2[il*132 + gb+2];
            s[3] = s1.w + sS2[il*132 + gb+3];
            #pragma unroll
            for (int c = 0; c < 4; c++) {
                int jk = j0 + tx*4 + c;
                s[c] = (jk > iq + MLEN) ? -1e30f : s[c]*fscale;
            }
            float tm = fmaxf(fmaxf(s[0],s[1]), fmaxf(s[2],s[3]));
            tm = fmaxf(tm, __shfl_xor_sync(0xffffffffu, tm, 8));
            tm = fmaxf(tm, __shfl_xor_sync(0xffffffffu, tm, 4));
            tm = fmaxf(tm, __shfl_xor_sync(0xffffffffu, tm, 2));
            tm = fmaxf(tm, __shfl_xor_sync(0xffffffffu, tm, 1));
            float mn = fmaxf(mrow[a], tm);
            float cf = ex2(mrow[a] - mn);
            mrow[a] = mn;
            float p0=ex2(s[0]-mn), p1=ex2(s[1]-mn), p2=ex2(s[2]-mn), p3=ex2(s[3]-mn);
            lrow[a] = lrow[a]*cf + (p0+p1+p2+p3);
            __half2 h01 = __floats2half2_rn(p0, p1);
            __half2 h23 = __floats2half2_rn(p2, p3);
            *(uint2*)&pS[il*72 + tx*4] = make_uint2(*(uint32_t*)&h01, *(uint32_t*)&h23);
            if (tx == 0) cfs[il] = cf;
        }
        __syncthreads();

        // PV: rescale O, accumulate P*V
        {
            int r0 = wm*16 + grp;
            float cf0 = cfs[r0], cf1 = cfs[r0+8];
            #pragma unroll
            for (int nb = 0; nb < 4; nb++) {
                oC[nb][0] *= cf0; oC[nb][1] *= cf0;
                oC[nb][2] *= cf1; oC[nb][3] *= cf1;
            }
        }
        #pragma unroll
        for (int ks = 0; ks < 4; ks++) {
            uint32_t aP[4];
            ldsm4(aP, sb + OPS + (uint32_t)(((wm*16 + (lane&15))*72 + ks*16 + ((lane>>4)<<3))*2));
            uint32_t bv0[4], bv1[4];
            uint32_t vb = sb + OVT + (uint32_t)(((ks*16 + (lane&15))*72 + wn*32 + ((lane>>4)<<3))*2);
            ldsm4t(bv0, vb);
            ldsm4t(bv1, vb + 32);
            mma16h(oC[0], aP, bv0[0], bv0[1]);
            mma16h(oC[1], aP, bv0[2], bv0[3]);
            mma16h(oC[2], aP, bv1[0], bv1[1]);
            mma16h(oC[3], aP, bv1[2], bv1[3]);
        }
    }

    // final normalize + store
    #pragma unroll
    for (int a = 0; a < 4; a++) {
        float lt = lrow[a];
        lt += __shfl_xor_sync(0xffffffffu, lt, 8);
        lt += __shfl_xor_sync(0xffffffffu, lt, 4);
        lt += __shfl_xor_sync(0xffffffffu, lt, 2);
        lt += __shfl_xor_sync(0xffffffffu, lt, 1);
        if (tx == 0) lis[ty*4+a] = 1.f / lt;
    }
    __syncthreads();
    {
        int r0 = wm*16 + grp;
        float li0 = lis[r0], li1 = lis[r0+8];
        #pragma unroll
        for (int nb = 0; nb < 4; nb++) {
            int col = n*DH + wn*32 + nb*8 + 2*tig;
            size_t row0 = (size_t)(i0 + r0)*BATCH + b;
            size_t row1 = (size_t)(i0 + r0 + 8)*BATCH + b;
            *(float2*)&g_AV[row0*DM + col] = make_float2(oC[nb][0]*li0, oC[nb][1]*li0);
            *(float2*)&g_AV[row1*DM + col] = make_float2(oC[nb][2]*li1, oC[nb][3]*li1);
        }
    }
}

// LayerNorm over g_O rows -> d_out
__global__ __launch_bounds__(256)
void k_ln(const float* __restrict__ gamma, const float* __restrict__ beta,
          float* __restrict__ out)
{
    __shared__ float red[16];
    const int t = threadIdx.x;
    const size_t row = blockIdx.x;
    float4 x = *(const float4*)&g_O[row*DM + t*4];
    float s = x.x + x.y + x.z + x.w;
    float ss = x.x*x.x + x.y*x.y + x.z*x.z + x.w*x.w;
    #pragma unroll
    for (int m = 16; m > 0; m >>= 1) {
        s  += __shfl_xor_sync(0xffffffffu, s, m);
        ss += __shfl_xor_sync(0xffffffffu, ss, m);
    }
    if ((t&31) == 0) { red[t>>5] = s; red[8 + (t>>5)] = ss; }
    __syncthreads();
    if (t < 8) {
        float a = red[t], bsum = red[8+t];
        #pragma unroll
        for (int m = 4; m > 0; m >>= 1) {
            a    += __shfl_xor_sync(0xffu, a, m);
            bsum += __shfl_xor_sync(0xffu, bsum, m);
        }
        if (t == 0) { red[0] = a; red[8] = bsum; }
    }
    __syncthreads();
    float mu = red[0] * (1.f/DM);
    float var = red[8] * (1.f/DM) - mu*mu;
    float rs = rsqrtf(var + 1e-5f);
    float4 g = *(const float4*)&gamma[t*4];
    float4 be = *(const float4*)&beta[t*4];
    float4 y;
    y.x = (x.x-mu)*rs*g.x + be.x;
    y.y = (x.y-mu)*rs*g.y + be.y;
    y.z = (x.z-mu)*rs*g.z + be.z;
    y.w = (x.w-mu)*rs*g.w + be.w;
    *(float4*)&out[row*DM + t*4] = y;
}

extern "C" void kernel_launch(void* const* d_in, const int* in_sizes, int n_in,
                              void* d_out, int out_size)
{
    const float* content = (const float*)d_in[0];
    const float* rel_pos = (const float*)d_in[1];
    const float* mems    = (const float*)d_in[2];
    const float* rwb     = (const float*)d_in[3];
    const float* rrb     = (const float*)d_in[4];
    const float* Wqkv    = (const float*)d_in[5];
    const float* Wr      = (const float*)d_in[6];
    const float* Wo      = (const float*)d_in[7];
    const float* gamma   = (const float*)d_in[8];
    const float* beta    = (const float*)d_in[9];
    float* out = (float*)d_out;

    cudaFuncSetAttribute(k_attn,  cudaFuncAttributeMaxDynamicSharedMemorySize, SMEM_ATTN);
    cudaFuncSetAttribute(k_qkv,   cudaFuncAttributeMaxDynamicSharedMemorySize, SMEM_GEMM);
    cudaFuncSetAttribute(k_rproj, cudaFuncAttributeMaxDynamicSharedMemorySize, SMEM_GEMM);
    cudaFuncSetAttribute(k_out,   cudaFuncAttributeMaxDynamicSharedMemorySize, SMEM_GEMM);

    __nv_bfloat16 *Ah, *Al, *W3h, *W3l, *Rph, *Rpl, *Wrh, *Wrl, *Woh, *Wol, *AVh, *AVl;
    float *AV, *Kf, *Vf, *Rf;
    __half *Kh, *Vh, *Rh;
    cudaGetSymbolAddress((void**)&Ah,  g_Ah);
    cudaGetSymbolAddress((void**)&Al,  g_Al);
    cudaGetSymbolAddress((void**)&W3h, g_W3h);
    cudaGetSymbolAddress((void**)&W3l, g_W3l);
    cudaGetSymbolAddress((void**)&Rph, g_Rph);
    cudaGetSymbolAddress((void**)&Rpl, g_Rpl);
    cudaGetSymbolAddress((void**)&Wrh, g_Wrh);
    cudaGetSymbolAddress((void**)&Wrl, g_Wrl);
    cudaGetSymbolAddress((void**)&Woh, g_Woh);
    cudaGetSymbolAddress((void**)&Wol, g_Wol);
    cudaGetSymbolAddress((void**)&AVh, g_AVh);
    cudaGetSymbolAddress((void**)&AVl, g_AVl);
    cudaGetSymbolAddress((void**)&AV,  g_AV);
    cudaGetSymbolAddress((void**)&Kf,  g_K);
    cudaGetSymbolAddress((void**)&Vf,  g_V);
    cudaGetSymbolAddress((void**)&Rf,  g_R);
    cudaGetSymbolAddress((void**)&Kh,  g_Kh);
    cudaGetSymbolAddress((void**)&Vh,  g_Vh);
    cudaGetSymbolAddress((void**)&Rh,  g_Rh);

    const int MB = 4096*DM/4;
    k_splitb<<<(MB+255)/256, 256>>>(mems,    Ah,           Al,           MB);
    k_splitb<<<(MB+255)/256, 256>>>(content, Ah + 4096*DM, Al + 4096*DM, MB);
    k_splitb<<<(DM*3072/4+255)/256, 256>>>(Wqkv,    W3h, W3l, DM*3072/4);
    k_splitb<<<(KLENN*DM/4+255)/256, 256>>>(rel_pos, Rph, Rpl, KLENN*DM/4);
    k_splitb<<<(DM*DM/4+255)/256, 256>>>(Wr, Wrh, Wrl, DM*DM/4);
    k_splitb<<<(DM*DM/4+255)/256, 256>>>(Wo, Woh, Wol, DM*DM/4);

    k_qkv  <<<dim3(24, 64), 256, SMEM_GEMM>>>();
    k_rproj<<<dim3(8, 16),  256, SMEM_GEMM>>>();

    const int QN4 = BATCH*NH*QLEN*DH/4;
    const int KN4 = BATCH*NH*KLENN*DH/4;
    const int RN4 = NH*KLENN*DH/4;
    k_qprep <<<(QN4+255)/256, 256>>>(rwb, rrb);
    k_tohalf<<<(KN4+255)/256, 256>>>(Kf, Kh, KN4);
    k_tohalf<<<(KN4+255)/256, 256>>>(Vf, Vh, KN4);
    k_tohalf<<<(RN4+255)/256, 256>>>(Rf, Rh, RN4);

    k_attn <<<dim3(QLEN/64, NH, BATCH), 256, SMEM_ATTN>>>();

    k_splitb<<<(MB+255)/256, 256>>>(AV, AVh, AVl, MB);
    k_out  <<<dim3(8, 32),  256, SMEM_GEMM>>>(content);
    k_ln   <<<QLEN*BATCH, 256>>>(gamma, beta, out);
}

// round 11
// speedup vs baseline: 1.0906x; 1.0906x over previous
#include <cuda_runtime.h>
#include <cuda_bf16.h>
#include <cuda_fp16.h>
#include <cstdint>

#define QLEN  1024
#define MLEN  1024
#define KLENN 2048
#define BATCH 4
#define NH    16
#define DH    64
#define DM    1024

// fp32 scratch
__device__ float g_O[QLEN*BATCH*DM];
// bf16 hi/lo planes (GEMMs)
__device__ __nv_bfloat16 g_Ah[8192*DM],  g_Al[8192*DM];
__device__ __nv_bfloat16 g_W3h[DM*3072], g_W3l[DM*3072];
__device__ __nv_bfloat16 g_Rph[KLENN*DM],g_Rpl[KLENN*DM];
__device__ __nv_bfloat16 g_Wrh[DM*DM],   g_Wrl[DM*DM];
__device__ __nv_bfloat16 g_Woh[DM*DM],   g_Wol[DM*DM];
__device__ __nv_bfloat16 g_AVh[4096*DM], g_AVl[4096*DM];
// fp16 attention operands
__device__ __half g_Qah[BATCH*NH*QLEN*DH];
__device__ __half g_Qbh[BATCH*NH*QLEN*DH];
__device__ __half g_Kh[BATCH*NH*KLENN*DH];
__device__ __half g_Vh[BATCH*NH*KLENN*DH];
__device__ __half g_Rh[NH*KLENN*DH];

__device__ __forceinline__ float ex2(float x) {
    float y; asm("ex2.approx.ftz.f32 %0, %1;" : "=f"(y) : "f"(x)); return y;
}

__device__ __forceinline__ uint32_t bfsplit2(float a, float b, uint32_t& lo) {
    __nv_bfloat16 ha = __float2bfloat16(a), hb = __float2bfloat16(b);
    __nv_bfloat16 la = __float2bfloat16(a - __bfloat162float(ha));
    __nv_bfloat16 lb = __float2bfloat16(b - __bfloat162float(hb));
    lo = (uint32_t)__bfloat16_as_ushort(la) | ((uint32_t)__bfloat16_as_ushort(lb)<<16);
    return (uint32_t)__bfloat16_as_ushort(ha) | ((uint32_t)__bfloat16_as_ushort(hb)<<16);
}

// ---------------------------------------------------------------------------
// bf16 split kernel: hi = bf16(x), lo = bf16(x - hi)
// ---------------------------------------------------------------------------
__global__ __launch_bounds__(256)
void k_splitb(const float* __restrict__ src, __nv_bfloat16* __restrict__ hi,
              __nv_bfloat16* __restrict__ lo, int n4)
{
    int i = blockIdx.x*256 + threadIdx.x;
    if (i < n4) {
        float4 v = ((const float4*)src)[i];
        uint32_t h0, l0, h1, l1;
        h0 = bfsplit2(v.x, v.y, l0);
        h1 = bfsplit2(v.z, v.w, l1);
        ((uint2*)hi)[i] = make_uint2(h0, h1);
        ((uint2*)lo)[i] = make_uint2(l0, l1);
    }
}

// ---------------------------------------------------------------------------
// MMA primitives
// ---------------------------------------------------------------------------
__device__ __forceinline__ void ldsm4(uint32_t (&r)[4], uint32_t addr) {
    asm volatile("ldmatrix.sync.aligned.m8n8.x4.shared.b16 {%0,%1,%2,%3}, [%4];"
        : "=r"(r[0]), "=r"(r[1]), "=r"(r[2]), "=r"(r[3]) : "r"(addr));
}
__device__ __forceinline__ void ldsm4t(uint32_t (&r)[4], uint32_t addr) {
    asm volatile("ldmatrix.sync.aligned.m8n8.x4.trans.shared.b16 {%0,%1,%2,%3}, [%4];"
        : "=r"(r[0]), "=r"(r[1]), "=r"(r[2]), "=r"(r[3]) : "r"(addr));
}
__device__ __forceinline__ void mma16b(float (&c)[4], const uint32_t (&a)[4],
                                       uint32_t b0, uint32_t b1) {
    asm volatile(
        "mma.sync.aligned.m16n8k16.row.col.f32.bf16.bf16.f32 "
        "{%0,%1,%2,%3},{%4,%5,%6,%7},{%8,%9},{%0,%1,%2,%3};"
        : "+f"(c[0]), "+f"(c[1]), "+f"(c[2]), "+f"(c[3])
        : "r"(a[0]), "r"(a[1]), "r"(a[2]), "r"(a[3]), "r"(b0), "r"(b1));
}
__device__ __forceinline__ void mma16h(float (&c)[4], const uint32_t (&a)[4],
                                       uint32_t b0, uint32_t b1) {
    asm volatile(
        "mma.sync.aligned.m16n8k16.row.col.f32.f16.f16.f32 "
        "{%0,%1,%2,%3},{%4,%5,%6,%7},{%8,%9},{%0,%1,%2,%3};"
        : "+f"(c[0]), "+f"(c[1]), "+f"(c[2]), "+f"(c[3])
        : "r"(a[0]), "r"(a[1]), "r"(a[2]), "r"(a[3]), "r"(b0), "r"(b1));
}
__device__ __forceinline__ void cpa16(uint32_t dst, const void* src) {
    asm volatile("cp.async.cg.shared.global [%0], [%1], 16;" :: "r"(dst), "l"(src));
}
__device__ __forceinline__ void cpa16z(uint32_t dst, const void* src, int nbytes) {
    asm volatile("cp.async.cg.shared.global [%0], [%1], 16, %2;"
                 :: "r"(dst), "l"(src), "r"(nbytes));
}

// ---------------------------------------------------------------------------
// bf16-split GEMM core (round-7-validated)
// ---------------------------------------------------------------------------
#define KS 32
#define A_PAD 40
#define B_PAD 136
#define A_PLANE (128*A_PAD)
#define A_BUF   (2*A_PLANE)
#define B_PLANE (KS*B_PAD)
#define B_BUF   (2*B_PLANE)
#define BUF_ELEMS (A_BUF + B_BUF)
#define SMEM_GEMM (2*BUF_ELEMS*2)

__device__ __forceinline__ void cta_load(
    uint32_t sb, int buf,
    const __nv_bfloat16* __restrict__ Ah, const __nv_bfloat16* __restrict__ Al, size_t m0,
    const __nv_bfloat16* __restrict__ Bh, const __nv_bfloat16* __restrict__ Bl,
    int ldb, int n0, int kt, int t)
{
    uint32_t bo = sb + (uint32_t)buf * (BUF_ELEMS*2);
    #pragma unroll
    for (int i = 0; i < 4; i++) {
        int c = t + 256*i;
        int p = c >> 9, rc = c & 511;
        int row = rc >> 2, seg = rc & 3;
        const __nv_bfloat16* src = (p ? Al : Ah) + (m0 + row)*DM + kt + seg*8;
        cpa16(bo + (uint32_t)(p*A_PLANE + row*A_PAD + seg*8)*2, src);
    }
    #pragma unroll
    for (int i = 0; i < 4; i++) {
        int c = t + 256*i;
        int p = c >> 9, rc = c & 511;
        int row = rc >> 4, seg = rc & 15;
        const __nv_bfloat16* src = (p ? Bl : Bh) + (size_t)(kt + row)*ldb + n0 + seg*8;
        cpa16(bo + (uint32_t)(A_BUF*2 + (p*B_PLANE + row*B_PAD + seg*8)*2), src);
    }
}

__device__ __forceinline__ void gemm_bf16(
    const __nv_bfloat16* __restrict__ Ah, const __nv_bfloat16* __restrict__ Al, size_t m0,
    const __nv_bfloat16* __restrict__ Bh, const __nv_bfloat16* __restrict__ Bl,
    int ldb, int n0, float (&C)[4][4][4], char* smem, int t)
{
    uint32_t sb = (uint32_t)__cvta_generic_to_shared(smem);
    const int lane = t&31, w = t>>5, wm = w>>2, wn = w&3;
    const uint32_t aBase = (uint32_t)(((wm*64 + (lane&15))*A_PAD + ((lane>>4)<<3))*2);
    const uint32_t bBase = (uint32_t)(A_BUF*2 + (((lane&15))*B_PAD + wn*32 + ((lane>>4)<<3))*2);

    cta_load(sb, 0, Ah, Al, m0, Bh, Bl, ldb, n0, 0, t);
    asm volatile("cp.async.commit_group;");

    for (int it = 0; it < DM/KS; ++it) {
        int buf = it & 1;
        if (it + 1 < DM/KS) {
            cta_load(sb, 1-buf, Ah, Al, m0, Bh, Bl, ldb, n0, (it+1)*KS, t);
            asm volatile("cp.async.commit_group;");
            asm volatile("cp.async.wait_group 1;");
        } else {
            asm volatile("cp.async.wait_group 0;");
        }
        __syncthreads();

        uint32_t bo = sb + (uint32_t)buf*(BUF_ELEMS*2);
        #pragma unroll
        for (int c16 = 0; c16 < 2; c16++) {
            uint32_t bb = bo + bBase + (uint32_t)(c16*16*B_PAD*2);
            uint32_t bH0[4], bS0[4], bH1[4], bS1[4];
            ldsm4t(bH0, bb);
            ldsm4t(bS0, bb + B_PLANE*2);
            ldsm4t(bH1, bb + 32);
            ldsm4t(bS1, bb + 32 + B_PLANE*2);
            #pragma unroll
            for (int mt = 0; mt < 4; mt++) {
                uint32_t ab = bo + aBase + (uint32_t)(mt*16*A_PAD*2 + c16*32);
                uint32_t aH[4], aS[4];
                ldsm4(aH, ab);
                ldsm4(aS, ab + A_PLANE*2);
                mma16b(C[mt][0], aH, bH0[0], bH0[1]);
                mma16b(C[mt][0], aH, bS0[0], bS0[1]);
                mma16b(C[mt][0], aS, bH0[0], bH0[1]);
                mma16b(C[mt][1], aH, bH0[2], bH0[3]);
                mma16b(C[mt][1], aH, bS0[2], bS0[3]);
                mma16b(C[mt][1], aS, bH0[2], bH0[3]);
                mma16b(C[mt][2], aH, bH1[0], bH1[1]);
                mma16b(C[mt][2], aH, bS1[0], bS1[1]);
                mma16b(C[mt][2], aS, bH1[0], bH1[1]);
                mma16b(C[mt][3], aH, bH1[2], bH1[3]);
                mma16b(C[mt][3], aH, bS1[2], bS1[3]);
                mma16b(C[mt][3], aS, bH1[2], bH1[3]);
            }
        }
        __syncthreads();
    }
}

// GEMM 1: cat @ W_qkv -> fp16 Qa/Qb (biases folded) + Kh + Vh directly.
__global__ __launch_bounds__(256)
void k_qkv(const float* __restrict__ rwb, const float* __restrict__ rrb)
{
    extern __shared__ char smg[];
    const int bx = blockIdx.x, by = blockIdx.y;
    // Q-section CTAs whose rows are all mems (discarded): skip entirely.
    if (bx < 8 && by < 32) return;
    const int t = threadIdx.x, n0 = bx<<7, m0 = by<<7;
    const int lane = t&31, w = t>>5, wm = w>>2, wn = w&3;
    const int tig = lane&3, grp = lane>>2;
    float C[4][4][4];
    #pragma unroll
    for (int i = 0; i < 4; i++) {
        #pragma unroll
        for (int j = 0; j < 4; j++) {
            #pragma unroll
            for (int k = 0; k < 4; k++) C[i][j][k] = 0.f;
        }
    }
    gemm_bf16(g_Ah, g_Al, (size_t)m0, g_W3h, g_W3l, 3072, n0, C, smg, t);

    #pragma unroll
    for (int mt = 0; mt < 4; mt++) {
        #pragma unroll
        for (int h = 0; h < 2; h++) {
            int m = m0 + wm*64 + mt*16 + grp + 8*h;
            int row = m >> 2, bb = m & 3;
            #pragma unroll
            for (int nt = 0; nt < 4; nt++) {
                int col = n0 + wn*32 + nt*8 + 2*tig;
                int sec = col >> 10, nn = (col>>6)&15, dd = col & 63;
                float c0 = C[mt][nt][2*h], c1 = C[mt][nt][2*h+1];
                if (sec == 0) {
                    if (row >= MLEN) {
                        size_t idx = (((size_t)bb*NH+nn)*QLEN + (row-MLEN))*DH + dd;
                        float2 wa = *(const float2*)&rwb[nn*DH + dd];
                        float2 wb = *(const float2*)&rrb[nn*DH + dd];
                        *(__half2*)&g_Qah[idx] = __floats2half2_rn(c0+wa.x, c1+wa.y);
                        *(__half2*)&g_Qbh[idx] = __floats2half2_rn(c0+wb.x, c1+wb.y);
                    }
                } else if (sec == 1) {
                    *(__half2*)&g_Kh[(((size_t)bb*NH+nn)*KLENN + row)*DH + dd] =
                        __floats2half2_rn(c0, c1);
                } else {
                    *(__half2*)&g_Vh[(((size_t)bb*NH+nn)*KLENN + row)*DH + dd] =
                        __floats2half2_rn(c0, c1);
                }
            }
        }
    }
}

// GEMM 2: rel_pos @ W_r -> fp16 g_Rh[n][m][d] directly.
__global__ __launch_bounds__(256)
void k_rproj()
{
    extern __shared__ char smg[];
    const int t = threadIdx.x, n0 = blockIdx.x<<7, m0 = blockIdx.y<<7;
    const int lane = t&31, w = t>>5, wm = w>>2, wn = w&3;
    const int tig = lane&3, grp = lane>>2;
    float C[4][4][4];
    #pragma unroll
    for (int i = 0; i < 4; i++) {
        #pragma unroll
        for (int j = 0; j < 4; j++) {
            #pragma unroll
            for (int k = 0; k < 4; k++) C[i][j][k] = 0.f;
        }
    }
    gemm_bf16(g_Rph, g_Rpl, (size_t)m0, g_Wrh, g_Wrl, DM, n0, C, smg, t);

    #pragma unroll
    for (int mt = 0; mt < 4; mt++) {
        #pragma unroll
        for (int h = 0; h < 2; h++) {
            int m = m0 + wm*64 + mt*16 + grp + 8*h;
            #pragma unroll
            for (int nt = 0; nt < 4; nt++) {
                int col = n0 + wn*32 + nt*8 + 2*tig;
                int nn = col >> 6, dd = col & 63;
                *(__half2*)&g_Rh[((size_t)nn*KLENN + m)*DH + dd] =
                    __floats2half2_rn(C[mt][nt][2*h], C[mt][nt][2*h+1]);
            }
        }
    }
}

// GEMM 3: AV @ W_o + content -> g_O
__global__ __launch_bounds__(256)
void k_out(const float* __restrict__ content)
{
    extern __shared__ char smg[];
    const int t = threadIdx.x, n0 = blockIdx.x<<7, m0 = blockIdx.y<<7;
    const int lane = t&31, w = t>>5, wm = w>>2, wn = w&3;
    const int tig = lane&3, grp = lane>>2;
    float C[4][4][4];
    #pragma unroll
    for (int i = 0; i < 4; i++) {
        #pragma unroll
        for (int j = 0; j < 4; j++) {
            #pragma unroll
            for (int k = 0; k < 4; k++) C[i][j][k] = 0.f;
        }
    }
    gemm_bf16(g_AVh, g_AVl, (size_t)m0, g_Woh, g_Wol, DM, n0, C, smg, t);

    #pragma unroll
    for (int mt = 0; mt < 4; mt++) {
        #pragma unroll
        for (int h = 0; h < 2; h++) {
            size_t m = m0 + wm*64 + mt*16 + grp + 8*h;
            #pragma unroll
            for (int nt = 0; nt < 4; nt++) {
                int col = n0 + wn*32 + nt*8 + 2*tig;
                float2 c4 = *(const float2*)(content + m*DM + col);
                float2 v = make_float2(C[mt][nt][2*h] + c4.x, C[mt][nt][2*h+1] + c4.y);
                *(float2*)&g_O[m*DM + col] = v;
            }
        }
    }
}

// ---------------------------------------------------------------------------
// MMA flash attention with XL rel-shift (round-9-validated), epilogue writes
// the bf16 hi/lo AV split directly.
// ---------------------------------------------------------------------------
#define OQA 0
#define OQB 9216
#define OKT 18432
#define OVT 27648
#define ORT 36864
#define OS1 55296
#define OS2 72704
#define OPS 106496
#define OCF 115712
#define OLI 115968
#define SMEM_ATTN 116224

__global__ __launch_bounds__(256)
void k_attn()
{
    extern __shared__ char sm[];
    uint32_t sb = (uint32_t)__cvta_generic_to_shared(sm);
    float* sS1 = (float*)(sm + OS1);   // [64][68]
    float* sS2 = (float*)(sm + OS2);   // [64][132]
    __half* pS = (__half*)(sm + OPS);  // [64][72]
    float* cfs = (float*)(sm + OCF);
    float* lis = (float*)(sm + OLI);

    const int t = threadIdx.x, lane = t&31, w = t>>5;
    const int tx = t&15, ty = t>>4;
    const int wm = w&3, wn = w>>2;
    const int tig = lane&3, grp = lane>>2;
    const int i0 = blockIdx.x<<6, n = blockIdx.y, b = blockIdx.z;

    const __half* Qag = g_Qah + ((size_t)(b*NH+n)*QLEN + i0)*DH;
    const __half* Qbg = g_Qbh + ((size_t)(b*NH+n)*QLEN + i0)*DH;
    const __half* Kg  = g_Kh  + (size_t)(b*NH+n)*KLENN*DH;
    const __half* Vg  = g_Vh  + (size_t)(b*NH+n)*KLENN*DH;
    const __half* Rg  = g_Rh  + (size_t)n*KLENN*DH;

    #pragma unroll
    for (int i = 0; i < 4; i++) {
        int c = t + 256*i;
        int which = c >> 9, rc = c & 511;
        int row = rc >> 3, seg = rc & 7;
        const __half* src = (which ? Qbg : Qag) + row*DH + seg*8;
        cpa16(sb + (which ? OQB : OQA) + (uint32_t)(row*72 + seg*8)*2, src);
    }
    asm volatile("cp.async.commit_group;");
    asm volatile("cp.async.wait_group 0;");
    __syncthreads();

    uint32_t aQa[4][4], aQb[4][4];
    #pragma unroll
    for (int ks = 0; ks < 4; ks++) {
        uint32_t off = (uint32_t)(((wm*16 + (lane&15))*72 + ks*16 + ((lane>>4)<<3))*2);
        ldsm4(aQa[ks], sb + OQA + off);
        ldsm4(aQb[ks], sb + OQB + off);
    }

    float mrow[4], lrow[4], oC[4][4];
    #pragma unroll
    for (int a = 0; a < 4; a++) { mrow[a] = -1e30f; lrow[a] = 0.f; }
    #pragma unroll
    for (int nb = 0; nb < 4; nb++) {
        #pragma unroll
        for (int k = 0; k < 4; k++) oC[nb][k] = 0.f;
    }

    const float fscale = 0.18033688011112042f;
    const int ntiles = (i0>>6) + 17;

    for (int tile = 0; tile < ntiles; tile++) {
        const int j0 = tile<<6;
        __syncthreads();
        #pragma unroll
        for (int i = 0; i < 8; i++) {
            int c = t + 256*i;
            if (c < 512) {
                int row = c >> 3, seg = c & 7;
                cpa16(sb + OKT + (uint32_t)(row*72 + seg*8)*2, Kg + (size_t)(j0+row)*DH + seg*8);
            } else if (c < 1024) {
                int rc = c - 512, row = rc >> 3, seg = rc & 7;
                cpa16(sb + OVT + (uint32_t)(row*72 + seg*8)*2, Vg + (size_t)(j0+row)*DH + seg*8);
            } else {
                int rc = c - 1024, row = rc >> 3, seg = rc & 7;
                int mg = j0 + 960 - i0 + row;
                int ok = (mg < KLENN) ? 16 : 0;
                if (mg >= KLENN) mg = KLENN - 1;
                cpa16z(sb + ORT + (uint32_t)(row*72 + seg*8)*2, Rg + (size_t)mg*DH + seg*8, ok);
            }
        }
        asm volatile("cp.async.commit_group;");
        asm volatile("cp.async.wait_group 0;");
        __syncthreads();

        float sC[12][4];
        #pragma unroll
        for (int p = 0; p < 12; p++) {
            #pragma unroll
            for (int k = 0; k < 4; k++) sC[p][k] = 0.f;
        }
        #pragma unroll
        for (int ks = 0; ks < 4; ks++) {
            uint32_t bf[6][4];
            #pragma unroll
            for (int p = 0; p < 6; p++) {
                int blk = wn*12 + 2*p;
                uint32_t base = (blk < 8) ? (sb + OKT) : (sb + ORT);
                int nrow = (blk < 8) ? blk*8 : (blk-8)*8;
                uint32_t addr = base + (uint32_t)(((nrow + (lane&7) + ((lane>>4)<<3))*72
                                 + ks*16 + (((lane>>3)&1)<<3))*2);
                ldsm4(bf[p], addr);
            }
            #pragma unroll
            for (int p = 0; p < 6; p++) {
                int blk = wn*12 + 2*p;
                if (blk < 8) { mma16h(sC[2*p], aQa[ks], bf[p][0], bf[p][1]); }
                else         { mma16h(sC[2*p], aQb[ks], bf[p][0], bf[p][1]); }
                if (blk+1 < 8) { mma16h(sC[2*p+1], aQa[ks], bf[p][2], bf[p][3]); }
                else           { mma16h(sC[2*p+1], aQb[ks], bf[p][2], bf[p][3]); }
            }
        }
        #pragma unroll
        for (int p = 0; p < 12; p++) {
            int blk = wn*12 + p;
            int r0 = wm*16 + grp;
            if (blk < 8) {
                int col = blk*8 + 2*tig;
                *(float2*)&sS1[r0*68 + col]     = make_float2(sC[p][0], sC[p][1]);
                *(float2*)&sS1[(r0+8)*68 + col] = make_float2(sC[p][2], sC[p][3]);
            } else {
                int col = (blk-8)*8 + 2*tig;
                *(float2*)&sS2[r0*132 + col]     = make_float2(sC[p][0], sC[p][1]);
                *(float2*)&sS2[(r0+8)*132 + col] = make_float2(sC[p][2], sC[p][3]);
            }
        }
        __syncthreads();

        #pragma unroll
        for (int a = 0; a < 4; a++) {
            const int il = ty*4 + a;
            const int iq = i0 + il;
            float4 s1 = *(const float4*)&sS1[il*68 + tx*4];
            int gb = tx*4 - il + 63;
            float s[4];
            s[0] = s1.x + sS2[il*132 + gb];
            s[1] = s1.y + sS2[il*132 + gb+1];
            s[2] = s1.z + sS2[il*132 + gb+2];
            s[3] = s1.w + sS2[il*132 + gb+3];
            #pragma unroll
            for (int c = 0; c < 4; c++) {
                int jk = j0 + tx*4 + c;
                s[c] = (jk > iq + MLEN) ? -1e30f : s[c]*fscale;
            }
            float tm = fmaxf(fmaxf(s[0],s[1]), fmaxf(s[2],s[3]));
            tm = fmaxf(tm, __shfl_xor_sync(0xffffffffu, tm, 8));
            tm = fmaxf(tm, __shfl_xor_sync(0xffffffffu, tm, 4));
            tm = fmaxf(tm, __shfl_xor_sync(0xffffffffu, tm, 2));
            tm = fmaxf(tm, __shfl_xor_sync(0xffffffffu, tm, 1));
            float mn = fmaxf(mrow[a], tm);
            float cf = ex2(mrow[a] - mn);
            mrow[a] = mn;
            float p0=ex2(s[0]-mn), p1=ex2(s[1]-mn), p2=ex2(s[2]-mn), p3=ex2(s[3]-mn);
            lrow[a] = lrow[a]*cf + (p0+p1+p2+p3);
            __half2 h01 = __floats2half2_rn(p0, p1);
            __half2 h23 = __floats2half2_rn(p2, p3);
            *(uint2*)&pS[il*72 + tx*4] = make_uint2(*(uint32_t*)&h01, *(uint32_t*)&h23);
            if (tx == 0) cfs[il] = cf;
        }
        __syncthreads();

        {
            int r0 = wm*16 + grp;
            float cf0 = cfs[r0], cf1 = cfs[r0+8];
            #pragma unroll
            for (int nb = 0; nb < 4; nb++) {
                oC[nb][0] *= cf0; oC[nb][1] *= cf0;
                oC[nb][2] *= cf1; oC[nb][3] *= cf1;
            }
        }
        #pragma unroll
        for (int ks = 0; ks < 4; ks++) {
            uint32_t aP[4];
            ldsm4(aP, sb + OPS + (uint32_t)(((wm*16 + (lane&15))*72 + ks*16 + ((lane>>4)<<3))*2));
            uint32_t bv0[4], bv1[4];
            uint32_t vb = sb + OVT + (uint32_t)(((ks*16 + (lane&15))*72 + wn*32 + ((lane>>4)<<3))*2);
            ldsm4t(bv0, vb);
            ldsm4t(bv1, vb + 32);
            mma16h(oC[0], aP, bv0[0], bv0[1]);
            mma16h(oC[1], aP, bv0[2], bv0[3]);
            mma16h(oC[2], aP, bv1[0], bv1[1]);
            mma16h(oC[3], aP, bv1[2], bv1[3]);
        }
    }

    #pragma unroll
    for (int a = 0; a < 4; a++) {
        float lt = lrow[a];
        lt += __shfl_xor_sync(0xffffffffu, lt, 8);
        lt += __shfl_xor_sync(0xffffffffu, lt, 4);
        lt += __shfl_xor_sync(0xffffffffu, lt, 2);
        lt += __shfl_xor_sync(0xffffffffu, lt, 1);
        if (tx == 0) lis[ty*4+a] = 1.f / lt;
    }
    __syncthreads();
    {
        int r0 = wm*16 + grp;
        float li0 = lis[r0], li1 = lis[r0+8];
        #pragma unroll
        for (int nb = 0; nb < 4; nb++) {
            int col = n*DH + wn*32 + nb*8 + 2*tig;
            size_t row0 = (size_t)(i0 + r0)*BATCH + b;
            size_t row1 = (size_t)(i0 + r0 + 8)*BATCH + b;
            uint32_t lo0, lo1;
            uint32_t hi0 = bfsplit2(oC[nb][0]*li0, oC[nb][1]*li0, lo0);
            uint32_t hi1 = bfsplit2(oC[nb][2]*li1, oC[nb][3]*li1, lo1);
            *(uint32_t*)&g_AVh[row0*DM + col] = hi0;
            *(uint32_t*)&g_AVl[row0*DM + col] = lo0;
            *(uint32_t*)&g_AVh[row1*DM + col] = hi1;
            *(uint32_t*)&g_AVl[row1*DM + col] = lo1;
        }
    }
}

// LayerNorm over g_O rows -> d_out
__global__ __launch_bounds__(256)
void k_ln(const float* __restrict__ gamma, const float* __restrict__ beta,
          float* __restrict__ out)
{
    __shared__ float red[16];
    const int t = threadIdx.x;
    const size_t row = blockIdx.x;
    float4 x = *(const float4*)&g_O[row*DM + t*4];
    float s = x.x + x.y + x.z + x.w;
    float ss = x.x*x.x + x.y*x.y + x.z*x.z + x.w*x.w;
    #pragma unroll
    for (int m = 16; m > 0; m >>= 1) {
        s  += __shfl_xor_sync(0xffffffffu, s, m);
        ss += __shfl_xor_sync(0xffffffffu, ss, m);
    }
    if ((t&31) == 0) { red[t>>5] = s; red[8 + (t>>5)] = ss; }
    __syncthreads();
    if (t < 8) {
        float a = red[t], bsum = red[8+t];
        #pragma unroll
        for (int m = 4; m > 0; m >>= 1) {
            a    += __shfl_xor_sync(0xffu, a, m);
            bsum += __shfl_xor_sync(0xffu, bsum, m);
        }
        if (t == 0) { red[0] = a; red[8] = bsum; }
    }
    __syncthreads();
    float mu = red[0] * (1.f/DM);
    float var = red[8] * (1.f/DM) - mu*mu;
    float rs = rsqrtf(var + 1e-5f);
    float4 g = *(const float4*)&gamma[t*4];
    float4 be = *(const float4*)&beta[t*4];
    float4 y;
    y.x = (x.x-mu)*rs*g.x + be.x;
    y.y = (x.y-mu)*rs*g.y + be.y;
    y.z = (x.z-mu)*rs*g.z + be.z;
    y.w = (x.w-mu)*rs*g.w + be.w;
    *(float4*)&out[row*DM + t*4] = y;
}

extern "C" void kernel_launch(void* const* d_in, const int* in_sizes, int n_in,
                              void* d_out, int out_size)
{
    const float* content = (const float*)d_in[0];
    const float* rel_pos = (const float*)d_in[1];
    const float* mems    = (const float*)d_in[2];
    const float* rwb     = (const float*)d_in[3];
    const float* rrb     = (const float*)d_in[4];
    const float* Wqkv    = (const float*)d_in[5];
    const float* Wr      = (const float*)d_in[6];
    const float* Wo      = (const float*)d_in[7];
    const float* gamma   = (const float*)d_in[8];
    const float* beta    = (const float*)d_in[9];
    float* out = (float*)d_out;

    cudaFuncSetAttribute(k_attn,  cudaFuncAttributeMaxDynamicSharedMemorySize, SMEM_ATTN);
    cudaFuncSetAttribute(k_qkv,   cudaFuncAttributeMaxDynamicSharedMemorySize, SMEM_GEMM);
    cudaFuncSetAttribute(k_rproj, cudaFuncAttributeMaxDynamicSharedMemorySize, SMEM_GEMM);
    cudaFuncSetAttribute(k_out,   cudaFuncAttributeMaxDynamicSharedMemorySize, SMEM_GEMM);

    __nv_bfloat16 *Ah, *Al, *W3h, *W3l, *Rph, *Rpl, *Wrh, *Wrl, *Woh, *Wol;
    cudaGetSymbolAddress((void**)&Ah,  g_Ah);
    cudaGetSymbolAddress((void**)&Al,  g_Al);
    cudaGetSymbolAddress((void**)&W3h, g_W3h);
    cudaGetSymbolAddress((void**)&W3l, g_W3l);
    cudaGetSymbolAddress((void**)&Rph, g_Rph);
    cudaGetSymbolAddress((void**)&Rpl, g_Rpl);
    cudaGetSymbolAddress((void**)&Wrh, g_Wrh);
    cudaGetSymbolAddress((void**)&Wrl, g_Wrl);
    cudaGetSymbolAddress((void**)&Woh, g_Woh);
    cudaGetSymbolAddress((void**)&Wol, g_Wol);

    const int MB = 4096*DM/4;
    k_splitb<<<(MB+255)/256, 256>>>(mems,    Ah,           Al,           MB);
    k_splitb<<<(MB+255)/256, 256>>>(content, Ah + 4096*DM, Al + 4096*DM, MB);
    k_splitb<<<(DM*3072/4+255)/256, 256>>>(Wqkv,    W3h, W3l, DM*3072/4);
    k_splitb<<<(KLENN*DM/4+255)/256, 256>>>(rel_pos, Rph, Rpl, KLENN*DM/4);
    k_splitb<<<(DM*DM/4+255)/256, 256>>>(Wr, Wrh, Wrl, DM*DM/4);
    k_splitb<<<(DM*DM/4+255)/256, 256>>>(Wo, Woh, Wol, DM*DM/4);

    k_qkv  <<<dim3(24, 64), 256, SMEM_GEMM>>>(rwb, rrb);
    k_rproj<<<dim3(8, 16),  256, SMEM_GEMM>>>();
    k_attn <<<dim3(QLEN/64, NH, BATCH), 256, SMEM_ATTN>>>();
    k_out  <<<dim3(8, 32),  256, SMEM_GEMM>>>(content);
    k_ln   <<<QLEN*BATCH, 256>>>(gamma, beta, out);
}

// round 12
// speedup vs baseline: 1.5396x; 1.4118x over previous
#include <cuda_runtime.h>
#include <cuda_fp16.h>
#include <cstdint>

#define QLEN  1024
#define MLEN  1024
#define KLENN 2048
#define BATCH 4
#define NH    16
#define DH    64
#define DM    1024

// fp32 scratch
__device__ float g_O[QLEN*BATCH*DM];
// fp16 operand planes
__device__ __half g_A16[8192*DM];      // cat([mems;content])
__device__ __half g_W316[DM*3072];     // W_qkv
__device__ __half g_Rp16[KLENN*DM];    // rel_pos
__device__ __half g_Wr16[DM*DM];       // W_r
__device__ __half g_Wo16[DM*DM];       // W_o
__device__ __half g_AVf[4096*DM];      // attn_vec
// fp16 attention operands
__device__ __half g_Qah[BATCH*NH*QLEN*DH];
__device__ __half g_Qbh[BATCH*NH*QLEN*DH];
__device__ __half g_Kh[BATCH*NH*KLENN*DH];
__device__ __half g_Vh[BATCH*NH*KLENN*DH];
__device__ __half g_Rh[NH*KLENN*DH];

__device__ __forceinline__ float ex2(float x) {
    float y; asm("ex2.approx.ftz.f32 %0, %1;" : "=f"(y) : "f"(x)); return y;
}

// fp32 -> fp16 cast
__global__ __launch_bounds__(256)
void k_toh(const float* __restrict__ src, __half* __restrict__ dst, int n4)
{
    int i = blockIdx.x*256 + threadIdx.x;
    if (i < n4) {
        float4 v = ((const float4*)src)[i];
        __half2 h01 = __floats2half2_rn(v.x, v.y);
        __half2 h23 = __floats2half2_rn(v.z, v.w);
        ((uint2*)dst)[i] = make_uint2(*(uint32_t*)&h01, *(uint32_t*)&h23);
    }
}

// ---------------------------------------------------------------------------
// MMA primitives
// ---------------------------------------------------------------------------
__device__ __forceinline__ void ldsm4(uint32_t (&r)[4], uint32_t addr) {
    asm volatile("ldmatrix.sync.aligned.m8n8.x4.shared.b16 {%0,%1,%2,%3}, [%4];"
        : "=r"(r[0]), "=r"(r[1]), "=r"(r[2]), "=r"(r[3]) : "r"(addr));
}
__device__ __forceinline__ void ldsm4t(uint32_t (&r)[4], uint32_t addr) {
    asm volatile("ldmatrix.sync.aligned.m8n8.x4.trans.shared.b16 {%0,%1,%2,%3}, [%4];"
        : "=r"(r[0]), "=r"(r[1]), "=r"(r[2]), "=r"(r[3]) : "r"(addr));
}
__device__ __forceinline__ void mma16h(float (&c)[4], const uint32_t (&a)[4],
                                       uint32_t b0, uint32_t b1) {
    asm volatile(
        "mma.sync.aligned.m16n8k16.row.col.f32.f16.f16.f32 "
        "{%0,%1,%2,%3},{%4,%5,%6,%7},{%8,%9},{%0,%1,%2,%3};"
        : "+f"(c[0]), "+f"(c[1]), "+f"(c[2]), "+f"(c[3])
        : "r"(a[0]), "r"(a[1]), "r"(a[2]), "r"(a[3]), "r"(b0), "r"(b1));
}
__device__ __forceinline__ void cpa16(uint32_t dst, const void* src) {
    asm volatile("cp.async.cg.shared.global [%0], [%1], 16;" :: "r"(dst), "l"(src));
}
__device__ __forceinline__ void cpa16z(uint32_t dst, const void* src, int nbytes) {
    asm volatile("cp.async.cg.shared.global [%0], [%1], 16, %2;"
                 :: "r"(dst), "l"(src), "r"(nbytes));
}

// ---------------------------------------------------------------------------
// fp16 GEMM core: 128x128 CTA tile, k-step 32, ldmatrix + cp.async pipeline.
// Addressing identical to the round-7-validated bf16 core minus the lo planes.
// ---------------------------------------------------------------------------
#define KS 32
#define A_PAD 40
#define B_PAD 136
#define A_PLANE (128*A_PAD)               // 5120 halves
#define B_PLANE (KS*B_PAD)                // 4352 halves
#define BUF_ELEMS (A_PLANE + B_PLANE)     // 9472
#define SMEM_GEMM (2*BUF_ELEMS*2)         // 37888 bytes

__device__ __forceinline__ void cta_load_h(
    uint32_t sb, int buf,
    const __half* __restrict__ A, size_t m0,
    const __half* __restrict__ B, int ldb, int n0, int kt, int t)
{
    uint32_t bo = sb + (uint32_t)buf * (BUF_ELEMS*2);
    #pragma unroll
    for (int i = 0; i < 2; i++) {           // A: 512 x 16B chunks
        int c = t + 256*i;
        int row = c >> 2, seg = c & 3;
        const __half* src = A + (m0 + row)*DM + kt + seg*8;
        cpa16(bo + (uint32_t)(row*A_PAD + seg*8)*2, src);
    }
    #pragma unroll
    for (int i = 0; i < 2; i++) {           // B: 512 x 16B chunks
        int c = t + 256*i;
        int row = c >> 4, seg = c & 15;
        const __half* src = B + (size_t)(kt + row)*ldb + n0 + seg*8;
        cpa16(bo + (uint32_t)(A_PLANE*2 + (row*B_PAD + seg*8)*2), src);
    }
}

__device__ __forceinline__ void gemm_h(
    const __half* __restrict__ A, size_t m0,
    const __half* __restrict__ B, int ldb, int n0,
    float (&C)[4][4][4], char* smem, int t)
{
    uint32_t sb = (uint32_t)__cvta_generic_to_shared(smem);
    const int lane = t&31, w = t>>5, wm = w>>2, wn = w&3;
    const uint32_t aBase = (uint32_t)(((wm*64 + (lane&15))*A_PAD + ((lane>>4)<<3))*2);
    const uint32_t bBase = (uint32_t)(A_PLANE*2 + (((lane&15))*B_PAD + wn*32 + ((lane>>4)<<3))*2);

    cta_load_h(sb, 0, A, m0, B, ldb, n0, 0, t);
    asm volatile("cp.async.commit_group;");

    for (int it = 0; it < DM/KS; ++it) {
        int buf = it & 1;
        if (it + 1 < DM/KS) {
            cta_load_h(sb, 1-buf, A, m0, B, ldb, n0, (it+1)*KS, t);
            asm volatile("cp.async.commit_group;");
            asm volatile("cp.async.wait_group 1;");
        } else {
            asm volatile("cp.async.wait_group 0;");
        }
        __syncthreads();

        uint32_t bo = sb + (uint32_t)buf*(BUF_ELEMS*2);
        #pragma unroll
        for (int c16 = 0; c16 < 2; c16++) {
            uint32_t bb = bo + bBase + (uint32_t)(c16*16*B_PAD*2);
            uint32_t bH0[4], bH1[4];
            ldsm4t(bH0, bb);
            ldsm4t(bH1, bb + 32);
            #pragma unroll
            for (int mt = 0; mt < 4; mt++) {
                uint32_t ab = bo + aBase + (uint32_t)(mt*16*A_PAD*2 + c16*32);
                uint32_t aH[4];
                ldsm4(aH, ab);
                mma16h(C[mt][0], aH, bH0[0], bH0[1]);
                mma16h(C[mt][1], aH, bH0[2], bH0[3]);
                mma16h(C[mt][2], aH, bH1[0], bH1[1]);
                mma16h(C[mt][3], aH, bH1[2], bH1[3]);
            }
        }
        __syncthreads();
    }
}

// GEMM 1: cat @ W_qkv -> fp16 Qa/Qb (biases folded) + Kh + Vh directly.
__global__ __launch_bounds__(256)
void k_qkv(const float* __restrict__ rwb, const float* __restrict__ rrb)
{
    extern __shared__ char smg[];
    const int bx = blockIdx.x, by = blockIdx.y;
    if (bx < 8 && by < 32) return;   // mems-rows Q-section: discarded output
    const int t = threadIdx.x, n0 = bx<<7, m0 = by<<7;
    const int lane = t&31, w = t>>5, wm = w>>2, wn = w&3;
    const int tig = lane&3, grp = lane>>2;
    float C[4][4][4];
    #pragma unroll
    for (int i = 0; i < 4; i++) {
        #pragma unroll
        for (int j = 0; j < 4; j++) {
            #pragma unroll
            for (int k = 0; k < 4; k++) C[i][j][k] = 0.f;
        }
    }
    gemm_h(g_A16, (size_t)m0, g_W316, 3072, n0, C, smg, t);

    #pragma unroll
    for (int mt = 0; mt < 4; mt++) {
        #pragma unroll
        for (int h = 0; h < 2; h++) {
            int m = m0 + wm*64 + mt*16 + grp + 8*h;
            int row = m >> 2, bb = m & 3;
            #pragma unroll
            for (int nt = 0; nt < 4; nt++) {
                int col = n0 + wn*32 + nt*8 + 2*tig;
                int sec = col >> 10, nn = (col>>6)&15, dd = col & 63;
                float c0 = C[mt][nt][2*h], c1 = C[mt][nt][2*h+1];
                if (sec == 0) {
                    if (row >= MLEN) {
                        size_t idx = (((size_t)bb*NH+nn)*QLEN + (row-MLEN))*DH + dd;
                        float2 wa = *(const float2*)&rwb[nn*DH + dd];
                        float2 wb = *(const float2*)&rrb[nn*DH + dd];
                        *(__half2*)&g_Qah[idx] = __floats2half2_rn(c0+wa.x, c1+wa.y);
                        *(__half2*)&g_Qbh[idx] = __floats2half2_rn(c0+wb.x, c1+wb.y);
                    }
                } else if (sec == 1) {
                    *(__half2*)&g_Kh[(((size_t)bb*NH+nn)*KLENN + row)*DH + dd] =
                        __floats2half2_rn(c0, c1);
                } else {
                    *(__half2*)&g_Vh[(((size_t)bb*NH+nn)*KLENN + row)*DH + dd] =
                        __floats2half2_rn(c0, c1);
                }
            }
        }
    }
}

// GEMM 2: rel_pos @ W_r -> fp16 g_Rh[n][m][d] directly.
__global__ __launch_bounds__(256)
void k_rproj()
{
    extern __shared__ char smg[];
    const int t = threadIdx.x, n0 = blockIdx.x<<7, m0 = blockIdx.y<<7;
    const int lane = t&31, w = t>>5, wm = w>>2, wn = w&3;
    const int tig = lane&3, grp = lane>>2;
    float C[4][4][4];
    #pragma unroll
    for (int i = 0; i < 4; i++) {
        #pragma unroll
        for (int j = 0; j < 4; j++) {
            #pragma unroll
            for (int k = 0; k < 4; k++) C[i][j][k] = 0.f;
        }
    }
    gemm_h(g_Rp16, (size_t)m0, g_Wr16, DM, n0, C, smg, t);

    #pragma unroll
    for (int mt = 0; mt < 4; mt++) {
        #pragma unroll
        for (int h = 0; h < 2; h++) {
            int m = m0 + wm*64 + mt*16 + grp + 8*h;
            #pragma unroll
            for (int nt = 0; nt < 4; nt++) {
                int col = n0 + wn*32 + nt*8 + 2*tig;
                int nn = col >> 6, dd = col & 63;
                *(__half2*)&g_Rh[((size_t)nn*KLENN + m)*DH + dd] =
                    __floats2half2_rn(C[mt][nt][2*h], C[mt][nt][2*h+1]);
            }
        }
    }
}

// GEMM 3: AV @ W_o + content -> g_O
__global__ __launch_bounds__(256)
void k_out(const float* __restrict__ content)
{
    extern __shared__ char smg[];
    const int t = threadIdx.x, n0 = blockIdx.x<<7, m0 = blockIdx.y<<7;
    const int lane = t&31, w = t>>5, wm = w>>2, wn = w&3;
    const int tig = lane&3, grp = lane>>2;
    float C[4][4][4];
    #pragma unroll
    for (int i = 0; i < 4; i++) {
        #pragma unroll
        for (int j = 0; j < 4; j++) {
            #pragma unroll
            for (int k = 0; k < 4; k++) C[i][j][k] = 0.f;
        }
    }
    gemm_h(g_AVf, (size_t)m0, g_Wo16, DM, n0, C, smg, t);

    #pragma unroll
    for (int mt = 0; mt < 4; mt++) {
        #pragma unroll
        for (int h = 0; h < 2; h++) {
            size_t m = m0 + wm*64 + mt*16 + grp + 8*h;
            #pragma unroll
            for (int nt = 0; nt < 4; nt++) {
                int col = n0 + wn*32 + nt*8 + 2*tig;
                float2 c4 = *(const float2*)(content + m*DM + col);
                float2 v = make_float2(C[mt][nt][2*h] + c4.x, C[mt][nt][2*h+1] + c4.y);
                *(float2*)&g_O[m*DM + col] = v;
            }
        }
    }
}

// ---------------------------------------------------------------------------
// MMA flash attention with XL rel-shift (round-9-validated); epilogue writes
// fp16 AV directly.
// ---------------------------------------------------------------------------
#define OQA 0
#define OQB 9216
#define OKT 18432
#define OVT 27648
#define ORT 36864
#define OS1 55296
#define OS2 72704
#define OPS 106496
#define OCF 115712
#define OLI 115968
#define SMEM_ATTN 116224

__global__ __launch_bounds__(256)
void k_attn()
{
    extern __shared__ char sm[];
    uint32_t sb = (uint32_t)__cvta_generic_to_shared(sm);
    float* sS1 = (float*)(sm + OS1);   // [64][68]
    float* sS2 = (float*)(sm + OS2);   // [64][132]
    __half* pS = (__half*)(sm + OPS);  // [64][72]
    float* cfs = (float*)(sm + OCF);
    float* lis = (float*)(sm + OLI);

    const int t = threadIdx.x, lane = t&31, w = t>>5;
    const int tx = t&15, ty = t>>4;
    const int wm = w&3, wn = w>>2;
    const int tig = lane&3, grp = lane>>2;
    const int i0 = blockIdx.x<<6, n = blockIdx.y, b = blockIdx.z;

    const __half* Qag = g_Qah + ((size_t)(b*NH+n)*QLEN + i0)*DH;
    const __half* Qbg = g_Qbh + ((size_t)(b*NH+n)*QLEN + i0)*DH;
    const __half* Kg  = g_Kh  + (size_t)(b*NH+n)*KLENN*DH;
    const __half* Vg  = g_Vh  + (size_t)(b*NH+n)*KLENN*DH;
    const __half* Rg  = g_Rh  + (size_t)n*KLENN*DH;

    #pragma unroll
    for (int i = 0; i < 4; i++) {
        int c = t + 256*i;
        int which = c >> 9, rc = c & 511;
        int row = rc >> 3, seg = rc & 7;
        const __half* src = (which ? Qbg : Qag) + row*DH + seg*8;
        cpa16(sb + (which ? OQB : OQA) + (uint32_t)(row*72 + seg*8)*2, src);
    }
    asm volatile("cp.async.commit_group;");
    asm volatile("cp.async.wait_group 0;");
    __syncthreads();

    uint32_t aQa[4][4], aQb[4][4];
    #pragma unroll
    for (int ks = 0; ks < 4; ks++) {
        uint32_t off = (uint32_t)(((wm*16 + (lane&15))*72 + ks*16 + ((lane>>4)<<3))*2);
        ldsm4(aQa[ks], sb + OQA + off);
        ldsm4(aQb[ks], sb + OQB + off);
    }

    float mrow[4], lrow[4], oC[4][4];
    #pragma unroll
    for (int a = 0; a < 4; a++) { mrow[a] = -1e30f; lrow[a] = 0.f; }
    #pragma unroll
    for (int nb = 0; nb < 4; nb++) {
        #pragma unroll
        for (int k = 0; k < 4; k++) oC[nb][k] = 0.f;
    }

    const float fscale = 0.18033688011112042f;
    const int ntiles = (i0>>6) + 17;

    for (int tile = 0; tile < ntiles; tile++) {
        const int j0 = tile<<6;
        __syncthreads();
        #pragma unroll
        for (int i = 0; i < 8; i++) {
            int c = t + 256*i;
            if (c < 512) {
                int row = c >> 3, seg = c & 7;
                cpa16(sb + OKT + (uint32_t)(row*72 + seg*8)*2, Kg + (size_t)(j0+row)*DH + seg*8);
            } else if (c < 1024) {
                int rc = c - 512, row = rc >> 3, seg = rc & 7;
                cpa16(sb + OVT + (uint32_t)(row*72 + seg*8)*2, Vg + (size_t)(j0+row)*DH + seg*8);
            } else {
                int rc = c - 1024, row = rc >> 3, seg = rc & 7;
                int mg = j0 + 960 - i0 + row;
                int ok = (mg < KLENN) ? 16 : 0;
                if (mg >= KLENN) mg = KLENN - 1;
                cpa16z(sb + ORT + (uint32_t)(row*72 + seg*8)*2, Rg + (size_t)mg*DH + seg*8, ok);
            }
        }
        asm volatile("cp.async.commit_group;");
        asm volatile("cp.async.wait_group 0;");
        __syncthreads();

        float sC[12][4];
        #pragma unroll
        for (int p = 0; p < 12; p++) {
            #pragma unroll
            for (int k = 0; k < 4; k++) sC[p][k] = 0.f;
        }
        #pragma unroll
        for (int ks = 0; ks < 4; ks++) {
            uint32_t bf[6][4];
            #pragma unroll
            for (int p = 0; p < 6; p++) {
                int blk = wn*12 + 2*p;
                uint32_t base = (blk < 8) ? (sb + OKT) : (sb + ORT);
                int nrow = (blk < 8) ? blk*8 : (blk-8)*8;
                uint32_t addr = base + (uint32_t)(((nrow + (lane&7) + ((lane>>4)<<3))*72
                                 + ks*16 + (((lane>>3)&1)<<3))*2);
                ldsm4(bf[p], addr);
            }
            #pragma unroll
            for (int p = 0; p < 6; p++) {
                int blk = wn*12 + 2*p;
                if (blk < 8) { mma16h(sC[2*p], aQa[ks], bf[p][0], bf[p][1]); }
                else         { mma16h(sC[2*p], aQb[ks], bf[p][0], bf[p][1]); }
                if (blk+1 < 8) { mma16h(sC[2*p+1], aQa[ks], bf[p][2], bf[p][3]); }
                else           { mma16h(sC[2*p+1], aQb[ks], bf[p][2], bf[p][3]); }
            }
        }
        #pragma unroll
        for (int p = 0; p < 12; p++) {
            int blk = wn*12 + p;
            int r0 = wm*16 + grp;
            if (blk < 8) {
                int col = blk*8 + 2*tig;
                *(float2*)&sS1[r0*68 + col]     = make_float2(sC[p][0], sC[p][1]);
                *(float2*)&sS1[(r0+8)*68 + col] = make_float2(sC[p][2], sC[p][3]);
            } else {
                int col = (blk-8)*8 + 2*tig;
                *(float2*)&sS2[r0*132 + col]     = make_float2(sC[p][0], sC[p][1]);
                *(float2*)&sS2[(r0+8)*132 + col] = make_float2(sC[p][2], sC[p][3]);
            }
        }
        __syncthreads();

        #pragma unroll
        for (int a = 0; a < 4; a++) {
            const int il = ty*4 + a;
            const int iq = i0 + il;
            float4 s1 = *(const float4*)&sS1[il*68 + tx*4];
            int gb = tx*4 - il + 63;
            float s[4];
            s[0] = s1.x + sS2[il*132 + gb];
            s[1] = s1.y + sS2[il*132 + gb+1];
            s[2] = s1.z + sS2[il*132 + gb+2];
            s[3] = s1.w + sS2[il*132 + gb+3];
            #pragma unroll
            for (int c = 0; c < 4; c++) {
                int jk = j0 + tx*4 + c;
                s[c] = (jk > iq + MLEN) ? -1e30f : s[c]*fscale;
            }
            float tm = fmaxf(fmaxf(s[0],s[1]), fmaxf(s[2],s[3]));
            tm = fmaxf(tm, __shfl_xor_sync(0xffffffffu, tm, 8));
            tm = fmaxf(tm, __shfl_xor_sync(0xffffffffu, tm, 4));
            tm = fmaxf(tm, __shfl_xor_sync(0xffffffffu, tm, 2));
            tm = fmaxf(tm, __shfl_xor_sync(0xffffffffu, tm, 1));
            float mn = fmaxf(mrow[a], tm);
            float cf = ex2(mrow[a] - mn);
            mrow[a] = mn;
            float p0=ex2(s[0]-mn), p1=ex2(s[1]-mn), p2=ex2(s[2]-mn), p3=ex2(s[3]-mn);
            lrow[a] = lrow[a]*cf + (p0+p1+p2+p3);
            __half2 h01 = __floats2half2_rn(p0, p1);
            __half2 h23 = __floats2half2_rn(p2, p3);
            *(uint2*)&pS[il*72 + tx*4] = make_uint2(*(uint32_t*)&h01, *(uint32_t*)&h23);
            if (tx == 0) cfs[il] = cf;
        }
        __syncthreads();

        {
            int r0 = wm*16 + grp;
            float cf0 = cfs[r0], cf1 = cfs[r0+8];
            #pragma unroll
            for (int nb = 0; nb < 4; nb++) {
                oC[nb][0] *= cf0; oC[nb][1] *= cf0;
                oC[nb][2] *= cf1; oC[nb][3] *= cf1;
            }
        }
        #pragma unroll
        for (int ks = 0; ks < 4; ks++) {
            uint32_t aP[4];
            ldsm4(aP, sb + OPS + (uint32_t)(((wm*16 + (lane&15))*72 + ks*16 + ((lane>>4)<<3))*2));
            uint32_t bv0[4], bv1[4];
            uint32_t vb = sb + OVT + (uint32_t)(((ks*16 + (lane&15))*72 + wn*32 + ((lane>>4)<<3))*2);
            ldsm4t(bv0, vb);
            ldsm4t(bv1, vb + 32);
            mma16h(oC[0], aP, bv0[0], bv0[1]);
            mma16h(oC[1], aP, bv0[2], bv0[3]);
            mma16h(oC[2], aP, bv1[0], bv1[1]);
            mma16h(oC[3], aP, bv1[2], bv1[3]);
        }
    }

    #pragma unroll
    for (int a = 0; a < 4; a++) {
        float lt = lrow[a];
        lt += __shfl_xor_sync(0xffffffffu, lt, 8);
        lt += __shfl_xor_sync(0xffffffffu, lt, 4);
        lt += __shfl_xor_sync(0xffffffffu, lt, 2);
        lt += __shfl_xor_sync(0xffffffffu, lt, 1);
        if (tx == 0) lis[ty*4+a] = 1.f / lt;
    }
    __syncthreads();
    {
        int r0 = wm*16 + grp;
        float li0 = lis[r0], li1 = lis[r0+8];
        #pragma unroll
        for (int nb = 0; nb < 4; nb++) {
            int col = n*DH + wn*32 + nb*8 + 2*tig;
            size_t row0 = (size_t)(i0 + r0)*BATCH + b;
            size_t row1 = (size_t)(i0 + r0 + 8)*BATCH + b;
            *(__half2*)&g_AVf[row0*DM + col] = __floats2half2_rn(oC[nb][0]*li0, oC[nb][1]*li0);
            *(__half2*)&g_AVf[row1*DM + col] = __floats2half2_rn(oC[nb][2]*li1, oC[nb][3]*li1);
        }
    }
}

// LayerNorm over g_O rows -> d_out
__global__ __launch_bounds__(256)
void k_ln(const float* __restrict__ gamma, const float* __restrict__ beta,
          float* __restrict__ out)
{
    __shared__ float red[16];
    const int t = threadIdx.x;
    const size_t row = blockIdx.x;
    float4 x = *(const float4*)&g_O[row*DM + t*4];
    float s = x.x + x.y + x.z + x.w;
    float ss = x.x*x.x + x.y*x.y + x.z*x.z + x.w*x.w;
    #pragma unroll
    for (int m = 16; m > 0; m >>= 1) {
        s  += __shfl_xor_sync(0xffffffffu, s, m);
        ss += __shfl_xor_sync(0xffffffffu, ss, m);
    }
    if ((t&31) == 0) { red[t>>5] = s; red[8 + (t>>5)] = ss; }
    __syncthreads();
    if (t < 8) {
        float a = red[t], bsum = red[8+t];
        #pragma unroll
        for (int m = 4; m > 0; m >>= 1) {
            a    += __shfl_xor_sync(0xffu, a, m);
            bsum += __shfl_xor_sync(0xffu, bsum, m);
        }
        if (t == 0) { red[0] = a; red[8] = bsum; }
    }
    __syncthreads();
    float mu = red[0] * (1.f/DM);
    float var = red[8] * (1.f/DM) - mu*mu;
    float rs = rsqrtf(var + 1e-5f);
    float4 g = *(const float4*)&gamma[t*4];
    float4 be = *(const float4*)&beta[t*4];
    float4 y;
    y.x = (x.x-mu)*rs*g.x + be.x;
    y.y = (x.y-mu)*rs*g.y + be.y;
    y.z = (x.z-mu)*rs*g.z + be.z;
    y.w = (x.w-mu)*rs*g.w + be.w;
    *(float4*)&out[row*DM + t*4] = y;
}

extern "C" void kernel_launch(void* const* d_in, const int* in_sizes, int n_in,
                              void* d_out, int out_size)
{
    const float* content = (const float*)d_in[0];
    const float* rel_pos = (const float*)d_in[1];
    const float* mems    = (const float*)d_in[2];
    const float* rwb     = (const float*)d_in[3];
    const float* rrb     = (const float*)d_in[4];
    const float* Wqkv    = (const float*)d_in[5];
    const float* Wr      = (const float*)d_in[6];
    const float* Wo      = (const float*)d_in[7];
    const float* gamma   = (const float*)d_in[8];
    const float* beta    = (const float*)d_in[9];
    float* out = (float*)d_out;

    cudaFuncSetAttribute(k_attn,  cudaFuncAttributeMaxDynamicSharedMemorySize, SMEM_ATTN);
    cudaFuncSetAttribute(k_qkv,   cudaFuncAttributeMaxDynamicSharedMemorySize, SMEM_GEMM);
    cudaFuncSetAttribute(k_rproj, cudaFuncAttributeMaxDynamicSharedMemorySize, SMEM_GEMM);
    cudaFuncSetAttribute(k_out,   cudaFuncAttributeMaxDynamicSharedMemorySize, SMEM_GEMM);

    __half *A16, *W316, *Rp16, *Wr16, *Wo16;
    cudaGetSymbolAddress((void**)&A16,  g_A16);
    cudaGetSymbolAddress((void**)&W316, g_W316);
    cudaGetSymbolAddress((void**)&Rp16, g_Rp16);
    cudaGetSymbolAddress((void**)&Wr16, g_Wr16);
    cudaGetSymbolAddress((void**)&Wo16, g_Wo16);

    const int MB = 4096*DM/4;
    k_toh<<<(MB+255)/256, 256>>>(mems,    A16,           MB);
    k_toh<<<(MB+255)/256, 256>>>(content, A16 + 4096*DM, MB);
    k_toh<<<(DM*3072/4+255)/256, 256>>>(Wqkv,    W316, DM*3072/4);
    k_toh<<<(KLENN*DM/4+255)/256, 256>>>(rel_pos, Rp16, KLENN*DM/4);
    k_toh<<<(DM*DM/4+255)/256, 256>>>(Wr, Wr16, DM*DM/4);
    k_toh<<<(DM*DM/4+255)/256, 256>>>(Wo, Wo16, DM*DM/4);

    k_qkv  <<<dim3(24, 64), 256, SMEM_GEMM>>>(rwb, rrb);
    k_rproj<<<dim3(8, 16),  256, SMEM_GEMM>>>();
    k_attn <<<dim3(QLEN/64, NH, BATCH), 256, SMEM_ATTN>>>();
    k_out  <<<dim3(8, 32),  256, SMEM_GEMM>>>(content);
    k_ln   <<<QLEN*BATCH, 256>>>(gamma, beta, out);
}

// round 13
// speedup vs baseline: 1.6160x; 1.0496x over previous
#include <cuda_runtime.h>
#include <cuda_fp16.h>
#include <cstdint>

#define QLEN  1024
#define MLEN  1024
#define KLENN 2048
#define BATCH 4
#define NH    16
#define DH    64
#define DM    1024

// fp32 scratch
__device__ float g_O[QLEN*BATCH*DM];
// fp16 operand planes
__device__ __half g_A16[8192*DM];
__device__ __half g_W316[DM*3072];
__device__ __half g_Rp16[KLENN*DM];
__device__ __half g_Wr16[DM*DM];
__device__ __half g_Wo16[DM*DM];
__device__ __half g_AVf[4096*DM];
// fp16 attention operands
__device__ __half g_Qah[BATCH*NH*QLEN*DH];
__device__ __half g_Qbh[BATCH*NH*QLEN*DH];
__device__ __half g_Kh[BATCH*NH*KLENN*DH];
__device__ __half g_Vh[BATCH*NH*KLENN*DH];
__device__ __half g_Rh[NH*KLENN*DH];

__device__ __forceinline__ float ex2(float x) {
    float y; asm("ex2.approx.ftz.f32 %0, %1;" : "=f"(y) : "f"(x)); return y;
}

// fp32 -> fp16 cast
__global__ __launch_bounds__(256)
void k_toh(const float* __restrict__ src, __half* __restrict__ dst, int n4)
{
    int i = blockIdx.x*256 + threadIdx.x;
    if (i < n4) {
        float4 v = ((const float4*)src)[i];
        __half2 h01 = __floats2half2_rn(v.x, v.y);
        __half2 h23 = __floats2half2_rn(v.z, v.w);
        ((uint2*)dst)[i] = make_uint2(*(uint32_t*)&h01, *(uint32_t*)&h23);
    }
}

// ---------------------------------------------------------------------------
// MMA primitives
// ---------------------------------------------------------------------------
__device__ __forceinline__ void ldsm4(uint32_t (&r)[4], uint32_t addr) {
    asm volatile("ldmatrix.sync.aligned.m8n8.x4.shared.b16 {%0,%1,%2,%3}, [%4];"
        : "=r"(r[0]), "=r"(r[1]), "=r"(r[2]), "=r"(r[3]) : "r"(addr));
}
__device__ __forceinline__ void ldsm4t(uint32_t (&r)[4], uint32_t addr) {
    asm volatile("ldmatrix.sync.aligned.m8n8.x4.trans.shared.b16 {%0,%1,%2,%3}, [%4];"
        : "=r"(r[0]), "=r"(r[1]), "=r"(r[2]), "=r"(r[3]) : "r"(addr));
}
__device__ __forceinline__ void mma16h(float (&c)[4], const uint32_t (&a)[4],
                                       uint32_t b0, uint32_t b1) {
    asm volatile(
        "mma.sync.aligned.m16n8k16.row.col.f32.f16.f16.f32 "
        "{%0,%1,%2,%3},{%4,%5,%6,%7},{%8,%9},{%0,%1,%2,%3};"
        : "+f"(c[0]), "+f"(c[1]), "+f"(c[2]), "+f"(c[3])
        : "r"(a[0]), "r"(a[1]), "r"(a[2]), "r"(a[3]), "r"(b0), "r"(b1));
}
__device__ __forceinline__ void cpa16(uint32_t dst, const void* src) {
    asm volatile("cp.async.cg.shared.global [%0], [%1], 16;" :: "r"(dst), "l"(src));
}
__device__ __forceinline__ void cpa16z(uint32_t dst, const void* src, int nbytes) {
    asm volatile("cp.async.cg.shared.global [%0], [%1], 16, %2;"
                 :: "r"(dst), "l"(src), "r"(nbytes));
}

// ---------------------------------------------------------------------------
// fp16 GEMM core: 128x128 CTA tile, k-step 32, 3-stage cp.async pipeline.
// ---------------------------------------------------------------------------
#define KS 32
#define A_PAD 40
#define B_PAD 136
#define A_PLANE (128*A_PAD)               // 5120 halves
#define B_PLANE (KS*B_PAD)                // 4352 halves
#define BUF_ELEMS (A_PLANE + B_PLANE)     // 9472
#define SMEM_GEMM (3*BUF_ELEMS*2)         // 56832 bytes

__device__ __forceinline__ void cta_load_h(
    uint32_t sb, int buf,
    const __half* __restrict__ A, size_t m0,
    const __half* __restrict__ B, int ldb, int n0, int kt, int t)
{
    uint32_t bo = sb + (uint32_t)buf * (BUF_ELEMS*2);
    #pragma unroll
    for (int i = 0; i < 2; i++) {
        int c = t + 256*i;
        int row = c >> 2, seg = c & 3;
        const __half* src = A + (m0 + row)*DM + kt + seg*8;
        cpa16(bo + (uint32_t)(row*A_PAD + seg*8)*2, src);
    }
    #pragma unroll
    for (int i = 0; i < 2; i++) {
        int c = t + 256*i;
        int row = c >> 4, seg = c & 15;
        const __half* src = B + (size_t)(kt + row)*ldb + n0 + seg*8;
        cpa16(bo + (uint32_t)(A_PLANE*2 + (row*B_PAD + seg*8)*2), src);
    }
}

__device__ __forceinline__ void gemm_h(
    const __half* __restrict__ A, size_t m0,
    const __half* __restrict__ B, int ldb, int n0,
    float (&C)[4][4][4], char* smem, int t)
{
    uint32_t sb = (uint32_t)__cvta_generic_to_shared(smem);
    const int lane = t&31, w = t>>5, wm = w>>2, wn = w&3;
    const uint32_t aBase = (uint32_t)(((wm*64 + (lane&15))*A_PAD + ((lane>>4)<<3))*2);
    const uint32_t bBase = (uint32_t)(A_PLANE*2 + (((lane&15))*B_PAD + wn*32 + ((lane>>4)<<3))*2);
    const int NIT = DM/KS;

    cta_load_h(sb, 0, A, m0, B, ldb, n0, 0, t);
    asm volatile("cp.async.commit_group;");
    cta_load_h(sb, 1, A, m0, B, ldb, n0, KS, t);
    asm volatile("cp.async.commit_group;");

    int buf = 0;
    for (int it = 0; it < NIT; ++it) {
        if (it + 2 < NIT) {
            int nb = buf + 2; if (nb >= 3) nb -= 3;
            cta_load_h(sb, nb, A, m0, B, ldb, n0, (it+2)*KS, t);
            asm volatile("cp.async.commit_group;");
            asm volatile("cp.async.wait_group 2;");
        } else if (it + 1 < NIT) {
            asm volatile("cp.async.wait_group 1;");
        } else {
            asm volatile("cp.async.wait_group 0;");
        }
        __syncthreads();

        uint32_t bo = sb + (uint32_t)buf*(BUF_ELEMS*2);
        #pragma unroll
        for (int c16 = 0; c16 < 2; c16++) {
            uint32_t bb = bo + bBase + (uint32_t)(c16*16*B_PAD*2);
            uint32_t bH0[4], bH1[4];
            ldsm4t(bH0, bb);
            ldsm4t(bH1, bb + 32);
            #pragma unroll
            for (int mt = 0; mt < 4; mt++) {
                uint32_t ab = bo + aBase + (uint32_t)(mt*16*A_PAD*2 + c16*32);
                uint32_t aH[4];
                ldsm4(aH, ab);
                mma16h(C[mt][0], aH, bH0[0], bH0[1]);
                mma16h(C[mt][1], aH, bH0[2], bH0[3]);
                mma16h(C[mt][2], aH, bH1[0], bH1[1]);
                mma16h(C[mt][3], aH, bH1[2], bH1[3]);
            }
        }
        __syncthreads();
        if (++buf == 3) buf = 0;
    }
}

// GEMM 1: cat @ W_qkv -> fp16 Qa/Qb (biases folded) + Kh + Vh directly.
__global__ __launch_bounds__(256)
void k_qkv(const float* __restrict__ rwb, const float* __restrict__ rrb)
{
    extern __shared__ char smg[];
    const int bx = blockIdx.x, by = blockIdx.y;
    if (bx < 8 && by < 32) return;   // mems-rows Q-section: discarded output
    const int t = threadIdx.x, n0 = bx<<7, m0 = by<<7;
    const int lane = t&31, w = t>>5, wm = w>>2, wn = w&3;
    const int tig = lane&3, grp = lane>>2;
    float C[4][4][4];
    #pragma unroll
    for (int i = 0; i < 4; i++) {
        #pragma unroll
        for (int j = 0; j < 4; j++) {
            #pragma unroll
            for (int k = 0; k < 4; k++) C[i][j][k] = 0.f;
        }
    }
    gemm_h(g_A16, (size_t)m0, g_W316, 3072, n0, C, smg, t);

    #pragma unroll
    for (int mt = 0; mt < 4; mt++) {
        #pragma unroll
        for (int h = 0; h < 2; h++) {
            int m = m0 + wm*64 + mt*16 + grp + 8*h;
            int row = m >> 2, bb = m & 3;
            #pragma unroll
            for (int nt = 0; nt < 4; nt++) {
                int col = n0 + wn*32 + nt*8 + 2*tig;
                int sec = col >> 10, nn = (col>>6)&15, dd = col & 63;
                float c0 = C[mt][nt][2*h], c1 = C[mt][nt][2*h+1];
                if (sec == 0) {
                    if (row >= MLEN) {
                        size_t idx = (((size_t)bb*NH+nn)*QLEN + (row-MLEN))*DH + dd;
                        float2 wa = *(const float2*)&rwb[nn*DH + dd];
                        float2 wb = *(const float2*)&rrb[nn*DH + dd];
                        *(__half2*)&g_Qah[idx] = __floats2half2_rn(c0+wa.x, c1+wa.y);
                        *(__half2*)&g_Qbh[idx] = __floats2half2_rn(c0+wb.x, c1+wb.y);
                    }
                } else if (sec == 1) {
                    *(__half2*)&g_Kh[(((size_t)bb*NH+nn)*KLENN + row)*DH + dd] =
                        __floats2half2_rn(c0, c1);
                } else {
                    *(__half2*)&g_Vh[(((size_t)bb*NH+nn)*KLENN + row)*DH + dd] =
                        __floats2half2_rn(c0, c1);
                }
            }
        }
    }
}

// GEMM 2: rel_pos @ W_r -> fp16 g_Rh[n][m][d] directly.
__global__ __launch_bounds__(256)
void k_rproj()
{
    extern __shared__ char smg[];
    const int t = threadIdx.x, n0 = blockIdx.x<<7, m0 = blockIdx.y<<7;
    const int lane = t&31, w = t>>5, wm = w>>2, wn = w&3;
    const int tig = lane&3, grp = lane>>2;
    float C[4][4][4];
    #pragma unroll
    for (int i = 0; i < 4; i++) {
        #pragma unroll
        for (int j = 0; j < 4; j++) {
            #pragma unroll
            for (int k = 0; k < 4; k++) C[i][j][k] = 0.f;
        }
    }
    gemm_h(g_Rp16, (size_t)m0, g_Wr16, DM, n0, C, smg, t);

    #pragma unroll
    for (int mt = 0; mt < 4; mt++) {
        #pragma unroll
        for (int h = 0; h < 2; h++) {
            int m = m0 + wm*64 + mt*16 + grp + 8*h;
            #pragma unroll
            for (int nt = 0; nt < 4; nt++) {
                int col = n0 + wn*32 + nt*8 + 2*tig;
                int nn = col >> 6, dd = col & 63;
                *(__half2*)&g_Rh[((size_t)nn*KLENN + m)*DH + dd] =
                    __floats2half2_rn(C[mt][nt][2*h], C[mt][nt][2*h+1]);
            }
        }
    }
}

// GEMM 3: AV @ W_o + content -> g_O
__global__ __launch_bounds__(256)
void k_out(const float* __restrict__ content)
{
    extern __shared__ char smg[];
    const int t = threadIdx.x, n0 = blockIdx.x<<7, m0 = blockIdx.y<<7;
    const int lane = t&31, w = t>>5, wm = w>>2, wn = w&3;
    const int tig = lane&3, grp = lane>>2;
    float C[4][4][4];
    #pragma unroll
    for (int i = 0; i < 4; i++) {
        #pragma unroll
        for (int j = 0; j < 4; j++) {
            #pragma unroll
            for (int k = 0; k < 4; k++) C[i][j][k] = 0.f;
        }
    }
    gemm_h(g_AVf, (size_t)m0, g_Wo16, DM, n0, C, smg, t);

    #pragma unroll
    for (int mt = 0; mt < 4; mt++) {
        #pragma unroll
        for (int h = 0; h < 2; h++) {
            size_t m = m0 + wm*64 + mt*16 + grp + 8*h;
            #pragma unroll
            for (int nt = 0; nt < 4; nt++) {
                int col = n0 + wn*32 + nt*8 + 2*tig;
                float2 c4 = *(const float2*)(content + m*DM + col);
                float2 v = make_float2(C[mt][nt][2*h] + c4.x, C[mt][nt][2*h+1] + c4.y);
                *(float2*)&g_O[m*DM + col] = v;
            }
        }
    }
}

// ---------------------------------------------------------------------------
// MMA flash attention with XL rel-shift; KVR tiles double-buffered.
// ---------------------------------------------------------------------------
#define OQA 0
#define OQB 9216
#define OKV 18432
#define KVSTRIDE 36864
#define OS1 92160
#define OS2 109568
#define OPS 143360
#define OCF 152576
#define OLI 152832
#define SMEM_ATTN 153088

__global__ __launch_bounds__(256)
void k_attn()
{
    extern __shared__ char sm[];
    uint32_t sb = (uint32_t)__cvta_generic_to_shared(sm);
    float* sS1 = (float*)(sm + OS1);   // [64][68]
    float* sS2 = (float*)(sm + OS2);   // [64][132]
    __half* pS = (__half*)(sm + OPS);  // [64][72]
    float* cfs = (float*)(sm + OCF);
    float* lis = (float*)(sm + OLI);

    const int t = threadIdx.x, lane = t&31, w = t>>5;
    const int tx = t&15, ty = t>>4;
    const int wm = w&3, wn = w>>2;
    const int tig = lane&3, grp = lane>>2;
    const int i0 = blockIdx.x<<6, n = blockIdx.y, b = blockIdx.z;

    const __half* Qag = g_Qah + ((size_t)(b*NH+n)*QLEN + i0)*DH;
    const __half* Qbg = g_Qbh + ((size_t)(b*NH+n)*QLEN + i0)*DH;
    const __half* Kg  = g_Kh  + (size_t)(b*NH+n)*KLENN*DH;
    const __half* Vg  = g_Vh  + (size_t)(b*NH+n)*KLENN*DH;
    const __half* Rg  = g_Rh  + (size_t)n*KLENN*DH;

    const int ntiles = (i0>>6) + 17;

    // Q tiles (group 0)
    #pragma unroll
    for (int i = 0; i < 4; i++) {
        int c = t + 256*i;
        int which = c >> 9, rc = c & 511;
        int row = rc >> 3, seg = rc & 7;
        const __half* src = (which ? Qbg : Qag) + row*DH + seg*8;
        cpa16(sb + (which ? OQB : OQA) + (uint32_t)(row*72 + seg*8)*2, src);
    }
    asm volatile("cp.async.commit_group;");

    // tile 0 KVR -> buf0 (group 1)
    {
        uint32_t kvb = sb + OKV;
        #pragma unroll
        for (int i = 0; i < 8; i++) {
            int c = t + 256*i;
            if (c < 512) {
                int row = c >> 3, seg = c & 7;
                cpa16(kvb + (uint32_t)(row*72 + seg*8)*2, Kg + (size_t)row*DH + seg*8);
            } else if (c < 1024) {
                int rc = c - 512, row = rc >> 3, seg = rc & 7;
                cpa16(kvb + 9216 + (uint32_t)(row*72 + seg*8)*2, Vg + (size_t)row*DH + seg*8);
            } else {
                int rc = c - 1024, row = rc >> 3, seg = rc & 7;
                int mg = 960 - i0 + row;
                cpa16(kvb + 18432 + (uint32_t)(row*72 + seg*8)*2, Rg + (size_t)mg*DH + seg*8);
            }
        }
        asm volatile("cp.async.commit_group;");
    }

    // wait for Q (tile0 may still be in flight), build Q fragments
    asm volatile("cp.async.wait_group 1;");
    __syncthreads();
    uint32_t aQa[4][4], aQb[4][4];
    #pragma unroll
    for (int ks = 0; ks < 4; ks++) {
        uint32_t off = (uint32_t)(((wm*16 + (lane&15))*72 + ks*16 + ((lane>>4)<<3))*2);
        ldsm4(aQa[ks], sb + OQA + off);
        ldsm4(aQb[ks], sb + OQB + off);
    }

    float mrow[4], lrow[4], oC[4][4];
    #pragma unroll
    for (int a = 0; a < 4; a++) { mrow[a] = -1e30f; lrow[a] = 0.f; }
    #pragma unroll
    for (int nb = 0; nb < 4; nb++) {
        #pragma unroll
        for (int k = 0; k < 4; k++) oC[nb][k] = 0.f;
    }

    const float fscale = 0.18033688011112042f;

    for (int tile = 0; tile < ntiles; tile++) {
        const int j0 = tile<<6;
        __syncthreads();   // all warps done reading buf[(tile+1)&1] from iter tile-1

        if (tile + 1 < ntiles) {
            const int j1 = (tile+1)<<6;
            uint32_t kvb = sb + OKV + (uint32_t)((tile+1)&1)*KVSTRIDE;
            #pragma unroll
            for (int i = 0; i < 8; i++) {
                int c = t + 256*i;
                if (c < 512) {
                    int row = c >> 3, seg = c & 7;
                    cpa16(kvb + (uint32_t)(row*72 + seg*8)*2, Kg + (size_t)(j1+row)*DH + seg*8);
                } else if (c < 1024) {
                    int rc = c - 512, row = rc >> 3, seg = rc & 7;
                    cpa16(kvb + 9216 + (uint32_t)(row*72 + seg*8)*2, Vg + (size_t)(j1+row)*DH + seg*8);
                } else {
                    int rc = c - 1024, row = rc >> 3, seg = rc & 7;
                    int mg = j1 + 960 - i0 + row;
                    int ok = (mg < KLENN) ? 16 : 0;
                    if (mg >= KLENN) mg = KLENN - 1;
                    cpa16z(kvb + 18432 + (uint32_t)(row*72 + seg*8)*2, Rg + (size_t)mg*DH + seg*8, ok);
                }
            }
            asm volatile("cp.async.commit_group;");
            asm volatile("cp.async.wait_group 1;");
        } else {
            asm volatile("cp.async.wait_group 0;");
        }
        __syncthreads();

        const uint32_t kvb = sb + OKV + (uint32_t)(tile&1)*KVSTRIDE;

        float sC[12][4];
        #pragma unroll
        for (int p = 0; p < 12; p++) {
            #pragma unroll
            for (int k = 0; k < 4; k++) sC[p][k] = 0.f;
        }
        #pragma unroll
        for (int ks = 0; ks < 4; ks++) {
            uint32_t bf[6][4];
            #pragma unroll
            for (int p = 0; p < 6; p++) {
                int blk = wn*12 + 2*p;
                uint32_t base = (blk < 8) ? kvb : (kvb + 18432);
                int nrow = (blk < 8) ? blk*8 : (blk-8)*8;
                uint32_t addr = base + (uint32_t)(((nrow + (lane&7) + ((lane>>4)<<3))*72
                                 + ks*16 + (((lane>>3)&1)<<3))*2);
                ldsm4(bf[p], addr);
            }
            #pragma unroll
            for (int p = 0; p < 6; p++) {
                int blk = wn*12 + 2*p;
                if (blk < 8) { mma16h(sC[2*p], aQa[ks], bf[p][0], bf[p][1]); }
                else         { mma16h(sC[2*p], aQb[ks], bf[p][0], bf[p][1]); }
                if (blk+1 < 8) { mma16h(sC[2*p+1], aQa[ks], bf[p][2], bf[p][3]); }
                else           { mma16h(sC[2*p+1], aQb[ks], bf[p][2], bf[p][3]); }
            }
        }
        #pragma unroll
        for (int p = 0; p < 12; p++) {
            int blk = wn*12 + p;
            int r0 = wm*16 + grp;
            if (blk < 8) {
                int col = blk*8 + 2*tig;
                *(float2*)&sS1[r0*68 + col]     = make_float2(sC[p][0], sC[p][1]);
                *(float2*)&sS1[(r0+8)*68 + col] = make_float2(sC[p][2], sC[p][3]);
            } else {
                int col = (blk-8)*8 + 2*tig;
                *(float2*)&sS2[r0*132 + col]     = make_float2(sC[p][0], sC[p][1]);
                *(float2*)&sS2[(r0+8)*132 + col] = make_float2(sC[p][2], sC[p][3]);
            }
        }
        __syncthreads();

        #pragma unroll
        for (int a = 0; a < 4; a++) {
            const int il = ty*4 + a;
            const int iq = i0 + il;
            float4 s1 = *(const float4*)&sS1[il*68 + tx*4];
            int gb = tx*4 - il + 63;
            float s[4];
            s[0] = s1.x + sS2[il*132 + gb];
            s[1] = s1.y + sS2[il*132 + gb+1];
            s[2] = s1.z + sS2[il*132 + gb+2];
            s[3] = s1.w + sS2[il*132 + gb+3];
            #pragma unroll
            for (int c = 0; c < 4; c++) {
                int jk = j0 + tx*4 + c;
                s[c] = (jk > iq + MLEN) ? -1e30f : s[c]*fscale;
            }
            float tm = fmaxf(fmaxf(s[0],s[1]), fmaxf(s[2],s[3]));
            tm = fmaxf(tm, __shfl_xor_sync(0xffffffffu, tm, 8));
            tm = fmaxf(tm, __shfl_xor_sync(0xffffffffu, tm, 4));
            tm = fmaxf(tm, __shfl_xor_sync(0xffffffffu, tm, 2));
            tm = fmaxf(tm, __shfl_xor_sync(0xffffffffu, tm, 1));
            float mn = fmaxf(mrow[a], tm);
            float cf = ex2(mrow[a] - mn);
            mrow[a] = mn;
            float p0=ex2(s[0]-mn), p1=ex2(s[1]-mn), p2=ex2(s[2]-mn), p3=ex2(s[3]-mn);
            lrow[a] = lrow[a]*cf + (p0+p1+p2+p3);
            __half2 h01 = __floats2half2_rn(p0, p1);
            __half2 h23 = __floats2half2_rn(p2, p3);
            *(uint2*)&pS[il*72 + tx*4] = make_uint2(*(uint32_t*)&h01, *(uint32_t*)&h23);
            if (tx == 0) cfs[il] = cf;
        }
        __syncthreads();

        {
            int r0 = wm*16 + grp;
            float cf0 = cfs[r0], cf1 = cfs[r0+8];
            #pragma unroll
            for (int nb = 0; nb < 4; nb++) {
                oC[nb][0] *= cf0; oC[nb][1] *= cf0;
                oC[nb][2] *= cf1; oC[nb][3] *= cf1;
            }
        }
        #pragma unroll
        for (int ks = 0; ks < 4; ks++) {
            uint32_t aP[4];
            ldsm4(aP, sb + OPS + (uint32_t)(((wm*16 + (lane&15))*72 + ks*16 + ((lane>>4)<<3))*2));
            uint32_t bv0[4], bv1[4];
            uint32_t vb = kvb + 9216 + (uint32_t)(((ks*16 + (lane&15))*72 + wn*32 + ((lane>>4)<<3))*2);
            ldsm4t(bv0, vb);
            ldsm4t(bv1, vb + 32);
            mma16h(oC[0], aP, bv0[0], bv0[1]);
            mma16h(oC[1], aP, bv0[2], bv0[3]);
            mma16h(oC[2], aP, bv1[0], bv1[1]);
            mma16h(oC[3], aP, bv1[2], bv1[3]);
        }
    }

    #pragma unroll
    for (int a = 0; a < 4; a++) {
        float lt = lrow[a];
        lt += __shfl_xor_sync(0xffffffffu, lt, 8);
        lt += __shfl_xor_sync(0xffffffffu, lt, 4);
        lt += __shfl_xor_sync(0xffffffffu, lt, 2);
        lt += __shfl_xor_sync(0xffffffffu, lt, 1);
        if (tx == 0) lis[ty*4+a] = 1.f / lt;
    }
    __syncthreads();
    {
        int r0 = wm*16 + grp;
        float li0 = lis[r0], li1 = lis[r0+8];
        #pragma unroll
        for (int nb = 0; nb < 4; nb++) {
            int col = n*DH + wn*32 + nb*8 + 2*tig;
            size_t row0 = (size_t)(i0 + r0)*BATCH + b;
            size_t row1 = (size_t)(i0 + r0 + 8)*BATCH + b;
            *(__half2*)&g_AVf[row0*DM + col] = __floats2half2_rn(oC[nb][0]*li0, oC[nb][1]*li0);
            *(__half2*)&g_AVf[row1*DM + col] = __floats2half2_rn(oC[nb][2]*li1, oC[nb][3]*li1);
        }
    }
}

// LayerNorm over g_O rows -> d_out
__global__ __launch_bounds__(256)
void k_ln(const float* __restrict__ gamma, const float* __restrict__ beta,
          float* __restrict__ out)
{
    __shared__ float red[16];
    const int t = threadIdx.x;
    const size_t row = blockIdx.x;
    float4 x = *(const float4*)&g_O[row*DM + t*4];
    float s = x.x + x.y + x.z + x.w;
    float ss = x.x*x.x + x.y*x.y + x.z*x.z + x.w*x.w;
    #pragma unroll
    for (int m = 16; m > 0; m >>= 1) {
        s  += __shfl_xor_sync(0xffffffffu, s, m);
        ss += __shfl_xor_sync(0xffffffffu, ss, m);
    }
    if ((t&31) == 0) { red[t>>5] = s; red[8 + (t>>5)] = ss; }
    __syncthreads();
    if (t < 8) {
        float a = red[t], bsum = red[8+t];
        #pragma unroll
        for (int m = 4; m > 0; m >>= 1) {
            a    += __shfl_xor_sync(0xffu, a, m);
            bsum += __shfl_xor_sync(0xffu, bsum, m);
        }
        if (t == 0) { red[0] = a; red[8] = bsum; }
    }
    __syncthreads();
    float mu = red[0] * (1.f/DM);
    float var = red[8] * (1.f/DM) - mu*mu;
    float rs = rsqrtf(var + 1e-5f);
    float4 g = *(const float4*)&gamma[t*4];
    float4 be = *(const float4*)&beta[t*4];
    float4 y;
    y.x = (x.x-mu)*rs*g.x + be.x;
    y.y = (x.y-mu)*rs*g.y + be.y;
    y.z = (x.z-mu)*rs*g.z + be.z;
    y.w = (x.w-mu)*rs*g.w + be.w;
    *(float4*)&out[row*DM + t*4] = y;
}

extern "C" void kernel_launch(void* const* d_in, const int* in_sizes, int n_in,
                              void* d_out, int out_size)
{
    const float* content = (const float*)d_in[0];
    const float* rel_pos = (const float*)d_in[1];
    const float* mems    = (const float*)d_in[2];
    const float* rwb     = (const float*)d_in[3];
    const float* rrb     = (const float*)d_in[4];
    const float* Wqkv    = (const float*)d_in[5];
    const float* Wr      = (const float*)d_in[6];
    const float* Wo      = (const float*)d_in[7];
    const float* gamma   = (const float*)d_in[8];
    const float* beta    = (const float*)d_in[9];
    float* out = (float*)d_out;

    cudaFuncSetAttribute(k_attn,  cudaFuncAttributeMaxDynamicSharedMemorySize, SMEM_ATTN);
    cudaFuncSetAttribute(k_qkv,   cudaFuncAttributeMaxDynamicSharedMemorySize, SMEM_GEMM);
    cudaFuncSetAttribute(k_rproj, cudaFuncAttributeMaxDynamicSharedMemorySize, SMEM_GEMM);
    cudaFuncSetAttribute(k_out,   cudaFuncAttributeMaxDynamicSharedMemorySize, SMEM_GEMM);

    __half *A16, *W316, *Rp16, *Wr16, *Wo16;
    cudaGetSymbolAddress((void**)&A16,  g_A16);
    cudaGetSymbolAddress((void**)&W316, g_W316);
    cudaGetSymbolAddress((void**)&Rp16, g_Rp16);
    cudaGetSymbolAddress((void**)&Wr16, g_Wr16);
    cudaGetSymbolAddress((void**)&Wo16, g_Wo16);

    const int MB = 4096*DM/4;
    k_toh<<<(MB+255)/256, 256>>>(mems,    A16,           MB);
    k_toh<<<(MB+255)/256, 256>>>(content, A16 + 4096*DM, MB);
    k_toh<<<(DM*3072/4+255)/256, 256>>>(Wqkv,    W316, DM*3072/4);
    k_toh<<<(KLENN*DM/4+255)/256, 256>>>(rel_pos, Rp16, KLENN*DM/4);
    k_toh<<<(DM*DM/4+255)/256, 256>>>(Wr, Wr16, DM*DM/4);
    k_toh<<<(DM*DM/4+255)/256, 256>>>(Wo, Wo16, DM*DM/4);

    k_qkv  <<<dim3(24, 64), 256, SMEM_GEMM>>>(rwb, rrb);
    k_rproj<<<dim3(8, 16),  256, SMEM_GEMM>>>();
    k_attn <<<dim3(QLEN/64, NH, BATCH), 256, SMEM_ATTN>>>();
    k_out  <<<dim3(8, 32),  256, SMEM_GEMM>>>(content);
    k_ln   <<<QLEN*BATCH, 256>>>(gamma, beta, out);
}

// round 14
// speedup vs baseline: 2.0816x; 1.2882x over previous
#include <cuda_runtime.h>
#include <cuda_fp16.h>
#include <cstdint>

#define QLEN  1024
#define MLEN  1024
#define KLENN 2048
#define BATCH 4
#define NH    16
#define DH    64
#define DM    1024

// fp32 scratch
__device__ float g_O[QLEN*BATCH*DM];
// fp16 operand planes
__device__ __half g_A16[8192*DM];
__device__ __half g_W316[DM*3072];
__device__ __half g_Rp16[KLENN*DM];
__device__ __half g_Wr16[DM*DM];
__device__ __half g_Wo16[DM*DM];
__device__ __half g_AVf[4096*DM];
// fp16 attention operands
__device__ __half g_Qah[BATCH*NH*QLEN*DH];
__device__ __half g_Qbh[BATCH*NH*QLEN*DH];
__device__ __half g_Kh[BATCH*NH*KLENN*DH];
__device__ __half g_Vh[BATCH*NH*KLENN*DH];
__device__ __half g_Rh[NH*KLENN*DH];

__device__ __forceinline__ float ex2(float x) {
    float y; asm("ex2.approx.ftz.f32 %0, %1;" : "=f"(y) : "f"(x)); return y;
}

// fp32 -> fp16 cast
__global__ __launch_bounds__(256)
void k_toh(const float* __restrict__ src, __half* __restrict__ dst, int n4)
{
    int i = blockIdx.x*256 + threadIdx.x;
    if (i < n4) {
        float4 v = ((const float4*)src)[i];
        __half2 h01 = __floats2half2_rn(v.x, v.y);
        __half2 h23 = __floats2half2_rn(v.z, v.w);
        ((uint2*)dst)[i] = make_uint2(*(uint32_t*)&h01, *(uint32_t*)&h23);
    }
}

// ---------------------------------------------------------------------------
// MMA primitives
// ---------------------------------------------------------------------------
__device__ __forceinline__ void ldsm4(uint32_t (&r)[4], uint32_t addr) {
    asm volatile("ldmatrix.sync.aligned.m8n8.x4.shared.b16 {%0,%1,%2,%3}, [%4];"
        : "=r"(r[0]), "=r"(r[1]), "=r"(r[2]), "=r"(r[3]) : "r"(addr));
}
__device__ __forceinline__ void ldsm4t(uint32_t (&r)[4], uint32_t addr) {
    asm volatile("ldmatrix.sync.aligned.m8n8.x4.trans.shared.b16 {%0,%1,%2,%3}, [%4];"
        : "=r"(r[0]), "=r"(r[1]), "=r"(r[2]), "=r"(r[3]) : "r"(addr));
}
__device__ __forceinline__ void mma16h(float (&c)[4], const uint32_t (&a)[4],
                                       uint32_t b0, uint32_t b1) {
    asm volatile(
        "mma.sync.aligned.m16n8k16.row.col.f32.f16.f16.f32 "
        "{%0,%1,%2,%3},{%4,%5,%6,%7},{%8,%9},{%0,%1,%2,%3};"
        : "+f"(c[0]), "+f"(c[1]), "+f"(c[2]), "+f"(c[3])
        : "r"(a[0]), "r"(a[1]), "r"(a[2]), "r"(a[3]), "r"(b0), "r"(b1));
}
__device__ __forceinline__ void cpa16(uint32_t dst, const void* src) {
    asm volatile("cp.async.cg.shared.global [%0], [%1], 16;" :: "r"(dst), "l"(src));
}
__device__ __forceinline__ void cpa16z(uint32_t dst, const void* src, int nbytes) {
    asm volatile("cp.async.cg.shared.global [%0], [%1], 16, %2;"
                 :: "r"(dst), "l"(src), "r"(nbytes));
}

// ---------------------------------------------------------------------------
// fp16 GEMM core: 128x128 CTA tile, k-step 32, 3-stage cp.async pipeline.
// (unchanged from round 12)
// ---------------------------------------------------------------------------
#define KS 32
#define A_PAD 40
#define B_PAD 136
#define A_PLANE (128*A_PAD)
#define B_PLANE (KS*B_PAD)
#define BUF_ELEMS (A_PLANE + B_PLANE)
#define SMEM_GEMM (3*BUF_ELEMS*2)

__device__ __forceinline__ void cta_load_h(
    uint32_t sb, int buf,
    const __half* __restrict__ A, size_t m0,
    const __half* __restrict__ B, int ldb, int n0, int kt, int t)
{
    uint32_t bo = sb + (uint32_t)buf * (BUF_ELEMS*2);
    #pragma unroll
    for (int i = 0; i < 2; i++) {
        int c = t + 256*i;
        int row = c >> 2, seg = c & 3;
        const __half* src = A + (m0 + row)*DM + kt + seg*8;
        cpa16(bo + (uint32_t)(row*A_PAD + seg*8)*2, src);
    }
    #pragma unroll
    for (int i = 0; i < 2; i++) {
        int c = t + 256*i;
        int row = c >> 4, seg = c & 15;
        const __half* src = B + (size_t)(kt + row)*ldb + n0 + seg*8;
        cpa16(bo + (uint32_t)(A_PLANE*2 + (row*B_PAD + seg*8)*2), src);
    }
}

__device__ __forceinline__ void gemm_h(
    const __half* __restrict__ A, size_t m0,
    const __half* __restrict__ B, int ldb, int n0,
    float (&C)[4][4][4], char* smem, int t)
{
    uint32_t sb = (uint32_t)__cvta_generic_to_shared(smem);
    const int lane = t&31, w = t>>5, wm = w>>2, wn = w&3;
    const uint32_t aBase = (uint32_t)(((wm*64 + (lane&15))*A_PAD + ((lane>>4)<<3))*2);
    const uint32_t bBase = (uint32_t)(A_PLANE*2 + (((lane&15))*B_PAD + wn*32 + ((lane>>4)<<3))*2);
    const int NIT = DM/KS;

    cta_load_h(sb, 0, A, m0, B, ldb, n0, 0, t);
    asm volatile("cp.async.commit_group;");
    cta_load_h(sb, 1, A, m0, B, ldb, n0, KS, t);
    asm volatile("cp.async.commit_group;");

    int buf = 0;
    for (int it = 0; it < NIT; ++it) {
        if (it + 2 < NIT) {
            int nb = buf + 2; if (nb >= 3) nb -= 3;
            cta_load_h(sb, nb, A, m0, B, ldb, n0, (it+2)*KS, t);
            asm volatile("cp.async.commit_group;");
            asm volatile("cp.async.wait_group 2;");
        } else if (it + 1 < NIT) {
            asm volatile("cp.async.wait_group 1;");
        } else {
            asm volatile("cp.async.wait_group 0;");
        }
        __syncthreads();

        uint32_t bo = sb + (uint32_t)buf*(BUF_ELEMS*2);
        #pragma unroll
        for (int c16 = 0; c16 < 2; c16++) {
            uint32_t bb = bo + bBase + (uint32_t)(c16*16*B_PAD*2);
            uint32_t bH0[4], bH1[4];
            ldsm4t(bH0, bb);
            ldsm4t(bH1, bb + 32);
            #pragma unroll
            for (int mt = 0; mt < 4; mt++) {
                uint32_t ab = bo + aBase + (uint32_t)(mt*16*A_PAD*2 + c16*32);
                uint32_t aH[4];
                ldsm4(aH, ab);
                mma16h(C[mt][0], aH, bH0[0], bH0[1]);
                mma16h(C[mt][1], aH, bH0[2], bH0[3]);
                mma16h(C[mt][2], aH, bH1[0], bH1[1]);
                mma16h(C[mt][3], aH, bH1[2], bH1[3]);
            }
        }
        __syncthreads();
        if (++buf == 3) buf = 0;
    }
}

// GEMM 1: cat @ W_qkv -> fp16 Qa/Qb (biases folded) + Kh + Vh directly.
__global__ __launch_bounds__(256)
void k_qkv(const float* __restrict__ rwb, const float* __restrict__ rrb)
{
    extern __shared__ char smg[];
    const int bx = blockIdx.x, by = blockIdx.y;
    if (bx < 8 && by < 32) return;
    const int t = threadIdx.x, n0 = bx<<7, m0 = by<<7;
    const int lane = t&31, w = t>>5, wm = w>>2, wn = w&3;
    const int tig = lane&3, grp = lane>>2;
    float C[4][4][4];
    #pragma unroll
    for (int i = 0; i < 4; i++) {
        #pragma unroll
        for (int j = 0; j < 4; j++) {
            #pragma unroll
            for (int k = 0; k < 4; k++) C[i][j][k] = 0.f;
        }
    }
    gemm_h(g_A16, (size_t)m0, g_W316, 3072, n0, C, smg, t);

    #pragma unroll
    for (int mt = 0; mt < 4; mt++) {
        #pragma unroll
        for (int h = 0; h < 2; h++) {
            int m = m0 + wm*64 + mt*16 + grp + 8*h;
            int row = m >> 2, bb = m & 3;
            #pragma unroll
            for (int nt = 0; nt < 4; nt++) {
                int col = n0 + wn*32 + nt*8 + 2*tig;
                int sec = col >> 10, nn = (col>>6)&15, dd = col & 63;
                float c0 = C[mt][nt][2*h], c1 = C[mt][nt][2*h+1];
                if (sec == 0) {
                    if (row >= MLEN) {
                        size_t idx = (((size_t)bb*NH+nn)*QLEN + (row-MLEN))*DH + dd;
                        float2 wa = *(const float2*)&rwb[nn*DH + dd];
                        float2 wb = *(const float2*)&rrb[nn*DH + dd];
                        *(__half2*)&g_Qah[idx] = __floats2half2_rn(c0+wa.x, c1+wa.y);
                        *(__half2*)&g_Qbh[idx] = __floats2half2_rn(c0+wb.x, c1+wb.y);
                    }
                } else if (sec == 1) {
                    *(__half2*)&g_Kh[(((size_t)bb*NH+nn)*KLENN + row)*DH + dd] =
                        __floats2half2_rn(c0, c1);
                } else {
                    *(__half2*)&g_Vh[(((size_t)bb*NH+nn)*KLENN + row)*DH + dd] =
                        __floats2half2_rn(c0, c1);
                }
            }
        }
    }
}

// GEMM 2: rel_pos @ W_r -> fp16 g_Rh[n][m][d] directly.
__global__ __launch_bounds__(256)
void k_rproj()
{
    extern __shared__ char smg[];
    const int t = threadIdx.x, n0 = blockIdx.x<<7, m0 = blockIdx.y<<7;
    const int lane = t&31, w = t>>5, wm = w>>2, wn = w&3;
    const int tig = lane&3, grp = lane>>2;
    float C[4][4][4];
    #pragma unroll
    for (int i = 0; i < 4; i++) {
        #pragma unroll
        for (int j = 0; j < 4; j++) {
            #pragma unroll
            for (int k = 0; k < 4; k++) C[i][j][k] = 0.f;
        }
    }
    gemm_h(g_Rp16, (size_t)m0, g_Wr16, DM, n0, C, smg, t);

    #pragma unroll
    for (int mt = 0; mt < 4; mt++) {
        #pragma unroll
        for (int h = 0; h < 2; h++) {
            int m = m0 + wm*64 + mt*16 + grp + 8*h;
            #pragma unroll
            for (int nt = 0; nt < 4; nt++) {
                int col = n0 + wn*32 + nt*8 + 2*tig;
                int nn = col >> 6, dd = col & 63;
                *(__half2*)&g_Rh[((size_t)nn*KLENN + m)*DH + dd] =
                    __floats2half2_rn(C[mt][nt][2*h], C[mt][nt][2*h+1]);
            }
        }
    }
}

// GEMM 3: AV @ W_o + content -> g_O
__global__ __launch_bounds__(256)
void k_out(const float* __restrict__ content)
{
    extern __shared__ char smg[];
    const int t = threadIdx.x, n0 = blockIdx.x<<7, m0 = blockIdx.y<<7;
    const int lane = t&31, w = t>>5, wm = w>>2, wn = w&3;
    const int tig = lane&3, grp = lane>>2;
    float C[4][4][4];
    #pragma unroll
    for (int i = 0; i < 4; i++) {
        #pragma unroll
        for (int j = 0; j < 4; j++) {
            #pragma unroll
            for (int k = 0; k < 4; k++) C[i][j][k] = 0.f;
        }
    }
    gemm_h(g_AVf, (size_t)m0, g_Wo16, DM, n0, C, smg, t);

    #pragma unroll
    for (int mt = 0; mt < 4; mt++) {
        #pragma unroll
        for (int h = 0; h < 2; h++) {
            size_t m = m0 + wm*64 + mt*16 + grp + 8*h;
            #pragma unroll
            for (int nt = 0; nt < 4; nt++) {
                int col = n0 + wn*32 + nt*8 + 2*tig;
                float2 c4 = *(const float2*)(content + m*DM + col);
                float2 v = make_float2(C[mt][nt][2*h] + c4.x, C[mt][nt][2*h+1] + c4.y);
                *(float2*)&g_O[m*DM + col] = v;
            }
        }
    }
}

// ---------------------------------------------------------------------------
// MMA flash attention with XL rel-shift. Single KVR buffer, fp16 S spill,
// 2 CTAs/SM. Heavy q-tiles scheduled first (reversed bx).
// ---------------------------------------------------------------------------
#define OQA  0
#define OQB  9216
#define OKT  18432
#define OVT  27648
#define ORT  36864
#define OS1H 55296
#define OS2H 64512
#define OPS  81920
#define OCF  91136
#define OLI  91392
#define SMEM_ATTN 91648

__global__ __launch_bounds__(256, 2)
void k_attn()
{
    extern __shared__ char sm[];
    uint32_t sb = (uint32_t)__cvta_generic_to_shared(sm);
    __half* sS1 = (__half*)(sm + OS1H);   // [64][72]
    __half* sS2 = (__half*)(sm + OS2H);   // [64][136]
    __half* pS  = (__half*)(sm + OPS);    // [64][72]
    float* cfs = (float*)(sm + OCF);
    float* lis = (float*)(sm + OLI);

    const int t = threadIdx.x, lane = t&31, w = t>>5;
    const int tx = t&15, ty = t>>4;
    const int wm = w&3, wn = w>>2;
    const int tig = lane&3, grp = lane>>2;
    const int i0 = (15 - blockIdx.x)<<6;   // heavy tiles first
    const int n = blockIdx.y, b = blockIdx.z;

    const __half* Qag = g_Qah + ((size_t)(b*NH+n)*QLEN + i0)*DH;
    const __half* Qbg = g_Qbh + ((size_t)(b*NH+n)*QLEN + i0)*DH;
    const __half* Kg  = g_Kh  + (size_t)(b*NH+n)*KLENN*DH;
    const __half* Vg  = g_Vh  + (size_t)(b*NH+n)*KLENN*DH;
    const __half* Rg  = g_Rh  + (size_t)n*KLENN*DH;

    // Q tiles -> smem (once)
    #pragma unroll
    for (int i = 0; i < 4; i++) {
        int c = t + 256*i;
        int which = c >> 9, rc = c & 511;
        int row = rc >> 3, seg = rc & 7;
        const __half* src = (which ? Qbg : Qag) + row*DH + seg*8;
        cpa16(sb + (which ? OQB : OQA) + (uint32_t)(row*72 + seg*8)*2, src);
    }
    asm volatile("cp.async.commit_group;");
    asm volatile("cp.async.wait_group 0;");
    __syncthreads();

    uint32_t aQa[4][4], aQb[4][4];
    #pragma unroll
    for (int ks = 0; ks < 4; ks++) {
        uint32_t off = (uint32_t)(((wm*16 + (lane&15))*72 + ks*16 + ((lane>>4)<<3))*2);
        ldsm4(aQa[ks], sb + OQA + off);
        ldsm4(aQb[ks], sb + OQB + off);
    }

    float mrow[4], lrow[4], oC[4][4];
    #pragma unroll
    for (int a = 0; a < 4; a++) { mrow[a] = -1e30f; lrow[a] = 0.f; }
    #pragma unroll
    for (int nb = 0; nb < 4; nb++) {
        #pragma unroll
        for (int k = 0; k < 4; k++) oC[nb][k] = 0.f;
    }

    const float fscale = 0.18033688011112042f;
    const int ntiles = (i0>>6) + 17;

    for (int tile = 0; tile < ntiles; tile++) {
        const int j0 = tile<<6;
        __syncthreads();
        // load K, V, R(window)
        #pragma unroll
        for (int i = 0; i < 8; i++) {
            int c = t + 256*i;
            if (c < 512) {
                int row = c >> 3, seg = c & 7;
                cpa16(sb + OKT + (uint32_t)(row*72 + seg*8)*2, Kg + (size_t)(j0+row)*DH + seg*8);
            } else if (c < 1024) {
                int rc = c - 512, row = rc >> 3, seg = rc & 7;
                cpa16(sb + OVT + (uint32_t)(row*72 + seg*8)*2, Vg + (size_t)(j0+row)*DH + seg*8);
            } else {
                int rc = c - 1024, row = rc >> 3, seg = rc & 7;
                int mg = j0 + 960 - i0 + row;
                int ok = (mg < KLENN) ? 16 : 0;
                if (mg >= KLENN) mg = KLENN - 1;
                cpa16z(sb + ORT + (uint32_t)(row*72 + seg*8)*2, Rg + (size_t)mg*DH + seg*8, ok);
            }
        }
        asm volatile("cp.async.commit_group;");
        asm volatile("cp.async.wait_group 0;");
        __syncthreads();

        // S-MMA: 6 pairs of 8-col blocks per warp (blocks 0..7=K, 8..23=R),
        // restructured for low register pressure.
        {
            const int r0 = wm*16 + grp;
            #pragma unroll
            for (int p = 0; p < 6; p++) {
                const int blk = wn*12 + 2*p;
                const bool isK = (blk < 8);
                uint32_t base = isK ? (sb + OKT) : (sb + ORT);
                int nrow = isK ? blk*8 : (blk-8)*8;
                float c0[4] = {0.f,0.f,0.f,0.f};
                float c1[4] = {0.f,0.f,0.f,0.f};
                #pragma unroll
                for (int ks = 0; ks < 4; ks++) {
                    uint32_t bf[4];
                    uint32_t addr = base + (uint32_t)(((nrow + (lane&7) + ((lane>>4)<<3))*72
                                     + ks*16 + (((lane>>3)&1)<<3))*2);
                    ldsm4(bf, addr);
                    const uint32_t (&aQ)[4] = isK ? aQa[ks] : aQb[ks];
                    mma16h(c0, aQ, bf[0], bf[1]);
                    mma16h(c1, aQ, bf[2], bf[3]);
                }
                // spill fp16
                if (isK) {
                    int col = blk*8 + 2*tig;
                    *(__half2*)&sS1[r0*72 + col]         = __floats2half2_rn(c0[0], c0[1]);
                    *(__half2*)&sS1[(r0+8)*72 + col]     = __floats2half2_rn(c0[2], c0[3]);
                    *(__half2*)&sS1[r0*72 + col + 8]     = __floats2half2_rn(c1[0], c1[1]);
                    *(__half2*)&sS1[(r0+8)*72 + col + 8] = __floats2half2_rn(c1[2], c1[3]);
                } else {
                    int col = (blk-8)*8 + 2*tig;
                    *(__half2*)&sS2[r0*136 + col]         = __floats2half2_rn(c0[0], c0[1]);
                    *(__half2*)&sS2[(r0+8)*136 + col]     = __floats2half2_rn(c0[2], c0[3]);
                    *(__half2*)&sS2[r0*136 + col + 8]     = __floats2half2_rn(c1[0], c1[1]);
                    *(__half2*)&sS2[(r0+8)*136 + col + 8] = __floats2half2_rn(c1[2], c1[3]);
                }
            }
        }
        __syncthreads();

        // softmax (scalar, 16x16 thread grid)
        #pragma unroll
        for (int a = 0; a < 4; a++) {
            const int il = ty*4 + a;
            const int iq = i0 + il;
            int gb = tx*4 - il + 63;
            float s[4];
            #pragma unroll
            for (int c = 0; c < 4; c++) {
                float v1 = __half2float(sS1[il*72 + tx*4 + c]);
                float v2 = __half2float(sS2[il*136 + gb + c]);
                int jk = j0 + tx*4 + c;
                s[c] = (jk > iq + MLEN) ? -1e30f : (v1 + v2)*fscale;
            }
            float tm = fmaxf(fmaxf(s[0],s[1]), fmaxf(s[2],s[3]));
            tm = fmaxf(tm, __shfl_xor_sync(0xffffffffu, tm, 8));
            tm = fmaxf(tm, __shfl_xor_sync(0xffffffffu, tm, 4));
            tm = fmaxf(tm, __shfl_xor_sync(0xffffffffu, tm, 2));
            tm = fmaxf(tm, __shfl_xor_sync(0xffffffffu, tm, 1));
            float mn = fmaxf(mrow[a], tm);
            float cf = ex2(mrow[a] - mn);
            mrow[a] = mn;
            float p0=ex2(s[0]-mn), p1=ex2(s[1]-mn), p2=ex2(s[2]-mn), p3=ex2(s[3]-mn);
            lrow[a] = lrow[a]*cf + (p0+p1+p2+p3);
            __half2 h01 = __floats2half2_rn(p0, p1);
            __half2 h23 = __floats2half2_rn(p2, p3);
            *(uint2*)&pS[il*72 + tx*4] = make_uint2(*(uint32_t*)&h01, *(uint32_t*)&h23);
            if (tx == 0) cfs[il] = cf;
        }
        __syncthreads();

        // PV: rescale O, accumulate P*V
        {
            int r0 = wm*16 + grp;
            float cf0 = cfs[r0], cf1 = cfs[r0+8];
            #pragma unroll
            for (int nb = 0; nb < 4; nb++) {
                oC[nb][0] *= cf0; oC[nb][1] *= cf0;
                oC[nb][2] *= cf1; oC[nb][3] *= cf1;
            }
        }
        #pragma unroll
        for (int ks = 0; ks < 4; ks++) {
            uint32_t aP[4];
            ldsm4(aP, sb + OPS + (uint32_t)(((wm*16 + (lane&15))*72 + ks*16 + ((lane>>4)<<3))*2));
            uint32_t bv0[4], bv1[4];
            uint32_t vb = sb + OVT + (uint32_t)(((ks*16 + (lane&15))*72 + wn*32 + ((lane>>4)<<3))*2);
            ldsm4t(bv0, vb);
            ldsm4t(bv1, vb + 32);
            mma16h(oC[0], aP, bv0[0], bv0[1]);
            mma16h(oC[1], aP, bv0[2], bv0[3]);
            mma16h(oC[2], aP, bv1[0], bv1[1]);
            mma16h(oC[3], aP, bv1[2], bv1[3]);
        }
    }

    #pragma unroll
    for (int a = 0; a < 4; a++) {
        float lt = lrow[a];
        lt += __shfl_xor_sync(0xffffffffu, lt, 8);
        lt += __shfl_xor_sync(0xffffffffu, lt, 4);
        lt += __shfl_xor_sync(0xffffffffu, lt, 2);
        lt += __shfl_xor_sync(0xffffffffu, lt, 1);
        if (tx == 0) lis[ty*4+a] = 1.f / lt;
    }
    __syncthreads();
    {
        int r0 = wm*16 + grp;
        float li0 = lis[r0], li1 = lis[r0+8];
        #pragma unroll
        for (int nb = 0; nb < 4; nb++) {
            int col = n*DH + wn*32 + nb*8 + 2*tig;
            size_t row0 = (size_t)(i0 + r0)*BATCH + b;
            size_t row1 = (size_t)(i0 + r0 + 8)*BATCH + b;
            *(__half2*)&g_AVf[row0*DM + col] = __floats2half2_rn(oC[nb][0]*li0, oC[nb][1]*li0);
            *(__half2*)&g_AVf[row1*DM + col] = __floats2half2_rn(oC[nb][2]*li1, oC[nb][3]*li1);
        }
    }
}

// LayerNorm over g_O rows -> d_out
__global__ __launch_bounds__(256)
void k_ln(const float* __restrict__ gamma, const float* __restrict__ beta,
          float* __restrict__ out)
{
    __shared__ float red[16];
    const int t = threadIdx.x;
    const size_t row = blockIdx.x;
    float4 x = *(const float4*)&g_O[row*DM + t*4];
    float s = x.x + x.y + x.z + x.w;
    float ss = x.x*x.x + x.y*x.y + x.z*x.z + x.w*x.w;
    #pragma unroll
    for (int m = 16; m > 0; m >>= 1) {
        s  += __shfl_xor_sync(0xffffffffu, s, m);
        ss += __shfl_xor_sync(0xffffffffu, ss, m);
    }
    if ((t&31) == 0) { red[t>>5] = s; red[8 + (t>>5)] = ss; }
    __syncthreads();
    if (t < 8) {
        float a = red[t], bsum = red[8+t];
        #pragma unroll
        for (int m = 4; m > 0; m >>= 1) {
            a    += __shfl_xor_sync(0xffu, a, m);
            bsum += __shfl_xor_sync(0xffu, bsum, m);
        }
        if (t == 0) { red[0] = a; red[8] = bsum; }
    }
    __syncthreads();
    float mu = red[0] * (1.f/DM);
    float var = red[8] * (1.f/DM) - mu*mu;
    float rs = rsqrtf(var + 1e-5f);
    float4 g = *(const float4*)&gamma[t*4];
    float4 be = *(const float4*)&beta[t*4];
    float4 y;
    y.x = (x.x-mu)*rs*g.x + be.x;
    y.y = (x.y-mu)*rs*g.y + be.y;
    y.z = (x.z-mu)*rs*g.z + be.z;
    y.w = (x.w-mu)*rs*g.w + be.w;
    *(float4*)&out[row*DM + t*4] = y;
}

extern "C" void kernel_launch(void* const* d_in, const int* in_sizes, int n_in,
                              void* d_out, int out_size)
{
    const float* content = (const float*)d_in[0];
    const float* rel_pos = (const float*)d_in[1];
    const float* mems    = (const float*)d_in[2];
    const float* rwb     = (const float*)d_in[3];
    const float* rrb     = (const float*)d_in[4];
    const float* Wqkv    = (const float*)d_in[5];
    const float* Wr      = (const float*)d_in[6];
    const float* Wo      = (const float*)d_in[7];
    const float* gamma   = (const float*)d_in[8];
    const float* beta    = (const float*)d_in[9];
    float* out = (float*)d_out;

    cudaFuncSetAttribute(k_attn,  cudaFuncAttributeMaxDynamicSharedMemorySize, SMEM_ATTN);
    cudaFuncSetAttribute(k_qkv,   cudaFuncAttributeMaxDynamicSharedMemorySize, SMEM_GEMM);
    cudaFuncSetAttribute(k_rproj, cudaFuncAttributeMaxDynamicSharedMemorySize, SMEM_GEMM);
    cudaFuncSetAttribute(k_out,   cudaFuncAttributeMaxDynamicSharedMemorySize, SMEM_GEMM);

    __half *A16, *W316, *Rp16, *Wr16, *Wo16;
    cudaGetSymbolAddress((void**)&A16,  g_A16);
    cudaGetSymbolAddress((void**)&W316, g_W316);
    cudaGetSymbolAddress((void**)&Rp16, g_Rp16);
    cudaGetSymbolAddress((void**)&Wr16, g_Wr16);
    cudaGetSymbolAddress((void**)&Wo16, g_Wo16);

    const int MB = 4096*DM/4;
    k_toh<<<(MB+255)/256, 256>>>(mems,    A16,           MB);
    k_toh<<<(MB+255)/256, 256>>>(content, A16 + 4096*DM, MB);
    k_toh<<<(DM*3072/4+255)/256, 256>>>(Wqkv,    W316, DM*3072/4);
    k_toh<<<(KLENN*DM/4+255)/256, 256>>>(rel_pos, Rp16, KLENN*DM/4);
    k_toh<<<(DM*DM/4+255)/256, 256>>>(Wr, Wr16, DM*DM/4);
    k_toh<<<(DM*DM/4+255)/256, 256>>>(Wo, Wo16, DM*DM/4);

    k_qkv  <<<dim3(24, 64), 256, SMEM_GEMM>>>(rwb, rrb);
    k_rproj<<<dim3(8, 16),  256, SMEM_GEMM>>>();
    k_attn <<<dim3(QLEN/64, NH, BATCH), 256, SMEM_ATTN>>>();
    k_out  <<<dim3(8, 32),  256, SMEM_GEMM>>>(content);
    k_ln   <<<QLEN*BATCH, 256>>>(gamma, beta, out);
}

// round 15
// speedup vs baseline: 2.1392x; 1.0276x over previous
#include <cuda_runtime.h>
#include <cuda_fp16.h>
#include <cstdint>

#define QLEN  1024
#define MLEN  1024
#define KLENN 2048
#define BATCH 4
#define NH    16
#define DH    64
#define DM    1024

// fp32 scratch
__device__ float g_O[QLEN*BATCH*DM];
// fp16 operand planes
__device__ __half g_A16[8192*DM];
__device__ __half g_W316[DM*3072];
__device__ __half g_Rp16[KLENN*DM];
__device__ __half g_Wr16[DM*DM];
__device__ __half g_Wo16[DM*DM];
__device__ __half g_AVf[4096*DM];
// fp16 attention operands
__device__ __half g_Qah[BATCH*NH*QLEN*DH];
__device__ __half g_Qbh[BATCH*NH*QLEN*DH];
__device__ __half g_Kh[BATCH*NH*KLENN*DH];
__device__ __half g_Vh[BATCH*NH*KLENN*DH];
__device__ __half g_Rh[NH*KLENN*DH];

__device__ __forceinline__ float ex2(float x) {
    float y; asm("ex2.approx.ftz.f32 %0, %1;" : "=f"(y) : "f"(x)); return y;
}

// fp32 -> fp16 cast
__global__ __launch_bounds__(256)
void k_toh(const float* __restrict__ src, __half* __restrict__ dst, int n4)
{
    int i = blockIdx.x*256 + threadIdx.x;
    if (i < n4) {
        float4 v = ((const float4*)src)[i];
        __half2 h01 = __floats2half2_rn(v.x, v.y);
        __half2 h23 = __floats2half2_rn(v.z, v.w);
        ((uint2*)dst)[i] = make_uint2(*(uint32_t*)&h01, *(uint32_t*)&h23);
    }
}

// ---------------------------------------------------------------------------
// MMA primitives
// ---------------------------------------------------------------------------
__device__ __forceinline__ void ldsm4(uint32_t (&r)[4], uint32_t addr) {
    asm volatile("ldmatrix.sync.aligned.m8n8.x4.shared.b16 {%0,%1,%2,%3}, [%4];"
        : "=r"(r[0]), "=r"(r[1]), "=r"(r[2]), "=r"(r[3]) : "r"(addr));
}
__device__ __forceinline__ void ldsm4t(uint32_t (&r)[4], uint32_t addr) {
    asm volatile("ldmatrix.sync.aligned.m8n8.x4.trans.shared.b16 {%0,%1,%2,%3}, [%4];"
        : "=r"(r[0]), "=r"(r[1]), "=r"(r[2]), "=r"(r[3]) : "r"(addr));
}
__device__ __forceinline__ void mma16h(float (&c)[4], const uint32_t (&a)[4],
                                       uint32_t b0, uint32_t b1) {
    asm volatile(
        "mma.sync.aligned.m16n8k16.row.col.f32.f16.f16.f32 "
        "{%0,%1,%2,%3},{%4,%5,%6,%7},{%8,%9},{%0,%1,%2,%3};"
        : "+f"(c[0]), "+f"(c[1]), "+f"(c[2]), "+f"(c[3])
        : "r"(a[0]), "r"(a[1]), "r"(a[2]), "r"(a[3]), "r"(b0), "r"(b1));
}
__device__ __forceinline__ void cpa16(uint32_t dst, const void* src) {
    asm volatile("cp.async.cg.shared.global [%0], [%1], 16;" :: "r"(dst), "l"(src));
}
__device__ __forceinline__ void cpa16z(uint32_t dst, const void* src, int nbytes) {
    asm volatile("cp.async.cg.shared.global [%0], [%1], 16, %2;"
                 :: "r"(dst), "l"(src), "r"(nbytes));
}

// ---------------------------------------------------------------------------
// fp16 GEMM core: 128x128 CTA tile, k-step 32, 3-stage cp.async pipeline.
// ---------------------------------------------------------------------------
#define KS 32
#define A_PAD 40
#define B_PAD 136
#define A_PLANE (128*A_PAD)
#define B_PLANE (KS*B_PAD)
#define BUF_ELEMS (A_PLANE + B_PLANE)
#define SMEM_GEMM (3*BUF_ELEMS*2)

__device__ __forceinline__ void cta_load_h(
    uint32_t sb, int buf,
    const __half* __restrict__ A, size_t m0,
    const __half* __restrict__ B, int ldb, int n0, int kt, int t)
{
    uint32_t bo = sb + (uint32_t)buf * (BUF_ELEMS*2);
    #pragma unroll
    for (int i = 0; i < 2; i++) {
        int c = t + 256*i;
        int row = c >> 2, seg = c & 3;
        const __half* src = A + (m0 + row)*DM + kt + seg*8;
        cpa16(bo + (uint32_t)(row*A_PAD + seg*8)*2, src);
    }
    #pragma unroll
    for (int i = 0; i < 2; i++) {
        int c = t + 256*i;
        int row = c >> 4, seg = c & 15;
        const __half* src = B + (size_t)(kt + row)*ldb + n0 + seg*8;
        cpa16(bo + (uint32_t)(A_PLANE*2 + (row*B_PAD + seg*8)*2), src);
    }
}

__device__ __forceinline__ void gemm_h(
    const __half* __restrict__ A, size_t m0,
    const __half* __restrict__ B, int ldb, int n0,
    float (&C)[4][4][4], char* smem, int t)
{
    uint32_t sb = (uint32_t)__cvta_generic_to_shared(smem);
    const int lane = t&31, w = t>>5, wm = w>>2, wn = w&3;
    const uint32_t aBase = (uint32_t)(((wm*64 + (lane&15))*A_PAD + ((lane>>4)<<3))*2);
    const uint32_t bBase = (uint32_t)(A_PLANE*2 + (((lane&15))*B_PAD + wn*32 + ((lane>>4)<<3))*2);
    const int NIT = DM/KS;

    cta_load_h(sb, 0, A, m0, B, ldb, n0, 0, t);
    asm volatile("cp.async.commit_group;");
    cta_load_h(sb, 1, A, m0, B, ldb, n0, KS, t);
    asm volatile("cp.async.commit_group;");

    int buf = 0;
    for (int it = 0; it < NIT; ++it) {
        if (it + 2 < NIT) {
            int nb = buf + 2; if (nb >= 3) nb -= 3;
            cta_load_h(sb, nb, A, m0, B, ldb, n0, (it+2)*KS, t);
            asm volatile("cp.async.commit_group;");
            asm volatile("cp.async.wait_group 2;");
        } else if (it + 1 < NIT) {
            asm volatile("cp.async.wait_group 1;");
        } else {
            asm volatile("cp.async.wait_group 0;");
        }
        __syncthreads();

        uint32_t bo = sb + (uint32_t)buf*(BUF_ELEMS*2);
        #pragma unroll
        for (int c16 = 0; c16 < 2; c16++) {
            uint32_t bb = bo + bBase + (uint32_t)(c16*16*B_PAD*2);
            uint32_t bH0[4], bH1[4];
            ldsm4t(bH0, bb);
            ldsm4t(bH1, bb + 32);
            #pragma unroll
            for (int mt = 0; mt < 4; mt++) {
                uint32_t ab = bo + aBase + (uint32_t)(mt*16*A_PAD*2 + c16*32);
                uint32_t aH[4];
                ldsm4(aH, ab);
                mma16h(C[mt][0], aH, bH0[0], bH0[1]);
                mma16h(C[mt][1], aH, bH0[2], bH0[3]);
                mma16h(C[mt][2], aH, bH1[0], bH1[1]);
                mma16h(C[mt][3], aH, bH1[2], bH1[3]);
            }
        }
        __syncthreads();
        if (++buf == 3) buf = 0;
    }
}

// GEMM 1: cat @ W_qkv -> fp16 Qa/Qb (biases folded) + Kh + Vh directly.
__global__ __launch_bounds__(256)
void k_qkv(const float* __restrict__ rwb, const float* __restrict__ rrb)
{
    extern __shared__ char smg[];
    const int bx = blockIdx.x, by = blockIdx.y;
    if (bx < 8 && by < 32) return;
    const int t = threadIdx.x, n0 = bx<<7, m0 = by<<7;
    const int lane = t&31, w = t>>5, wm = w>>2, wn = w&3;
    const int tig = lane&3, grp = lane>>2;
    float C[4][4][4];
    #pragma unroll
    for (int i = 0; i < 4; i++) {
        #pragma unroll
        for (int j = 0; j < 4; j++) {
            #pragma unroll
            for (int k = 0; k < 4; k++) C[i][j][k] = 0.f;
        }
    }
    gemm_h(g_A16, (size_t)m0, g_W316, 3072, n0, C, smg, t);

    #pragma unroll
    for (int mt = 0; mt < 4; mt++) {
        #pragma unroll
        for (int h = 0; h < 2; h++) {
            int m = m0 + wm*64 + mt*16 + grp + 8*h;
            int row = m >> 2, bb = m & 3;
            #pragma unroll
            for (int nt = 0; nt < 4; nt++) {
                int col = n0 + wn*32 + nt*8 + 2*tig;
                int sec = col >> 10, nn = (col>>6)&15, dd = col & 63;
                float c0 = C[mt][nt][2*h], c1 = C[mt][nt][2*h+1];
                if (sec == 0) {
                    if (row >= MLEN) {
                        size_t idx = (((size_t)bb*NH+nn)*QLEN + (row-MLEN))*DH + dd;
                        float2 wa = *(const float2*)&rwb[nn*DH + dd];
                        float2 wb = *(const float2*)&rrb[nn*DH + dd];
                        *(__half2*)&g_Qah[idx] = __floats2half2_rn(c0+wa.x, c1+wa.y);
                        *(__half2*)&g_Qbh[idx] = __floats2half2_rn(c0+wb.x, c1+wb.y);
                    }
                } else if (sec == 1) {
                    *(__half2*)&g_Kh[(((size_t)bb*NH+nn)*KLENN + row)*DH + dd] =
                        __floats2half2_rn(c0, c1);
                } else {
                    *(__half2*)&g_Vh[(((size_t)bb*NH+nn)*KLENN + row)*DH + dd] =
                        __floats2half2_rn(c0, c1);
                }
            }
        }
    }
}

// GEMM 2: rel_pos @ W_r -> fp16 g_Rh[n][m][d] directly.
__global__ __launch_bounds__(256)
void k_rproj()
{
    extern __shared__ char smg[];
    const int t = threadIdx.x, n0 = blockIdx.x<<7, m0 = blockIdx.y<<7;
    const int lane = t&31, w = t>>5, wm = w>>2, wn = w&3;
    const int tig = lane&3, grp = lane>>2;
    float C[4][4][4];
    #pragma unroll
    for (int i = 0; i < 4; i++) {
        #pragma unroll
        for (int j = 0; j < 4; j++) {
            #pragma unroll
            for (int k = 0; k < 4; k++) C[i][j][k] = 0.f;
        }
    }
    gemm_h(g_Rp16, (size_t)m0, g_Wr16, DM, n0, C, smg, t);

    #pragma unroll
    for (int mt = 0; mt < 4; mt++) {
        #pragma unroll
        for (int h = 0; h < 2; h++) {
            int m = m0 + wm*64 + mt*16 + grp + 8*h;
            #pragma unroll
            for (int nt = 0; nt < 4; nt++) {
                int col = n0 + wn*32 + nt*8 + 2*tig;
                int nn = col >> 6, dd = col & 63;
                *(__half2*)&g_Rh[((size_t)nn*KLENN + m)*DH + dd] =
                    __floats2half2_rn(C[mt][nt][2*h], C[mt][nt][2*h+1]);
            }
        }
    }
}

// GEMM 3: AV @ W_o + content -> g_O
__global__ __launch_bounds__(256)
void k_out(const float* __restrict__ content)
{
    extern __shared__ char smg[];
    const int t = threadIdx.x, n0 = blockIdx.x<<7, m0 = blockIdx.y<<7;
    const int lane = t&31, w = t>>5, wm = w>>2, wn = w&3;
    const int tig = lane&3, grp = lane>>2;
    float C[4][4][4];
    #pragma unroll
    for (int i = 0; i < 4; i++) {
        #pragma unroll
        for (int j = 0; j < 4; j++) {
            #pragma unroll
            for (int k = 0; k < 4; k++) C[i][j][k] = 0.f;
        }
    }
    gemm_h(g_AVf, (size_t)m0, g_Wo16, DM, n0, C, smg, t);

    #pragma unroll
    for (int mt = 0; mt < 4; mt++) {
        #pragma unroll
        for (int h = 0; h < 2; h++) {
            size_t m = m0 + wm*64 + mt*16 + grp + 8*h;
            #pragma unroll
            for (int nt = 0; nt < 4; nt++) {
                int col = n0 + wn*32 + nt*8 + 2*tig;
                float2 c4 = *(const float2*)(content + m*DM + col);
                float2 v = make_float2(C[mt][nt][2*h] + c4.x, C[mt][nt][2*h+1] + c4.y);
                *(float2*)&g_O[m*DM + col] = v;
            }
        }
    }
}

// ---------------------------------------------------------------------------
// MMA flash attention with XL rel-shift. KVR double-buffered via smem
// aliasing (buf1 overlays the dead Q staging area), P in-place over S1.
// fp16 S spill, 2 CTAs/SM, heavy q-tiles first.
// ---------------------------------------------------------------------------
#define AQA   0
#define AQB   9216
#define AKV1  0          // KVR buffer 1 aliases Q area (dead after frag extract)
#define AKV0  36864
#define AS1   73728      // S1 / P (in place)
#define AS2   82944
#define ACF   100352
#define ALI   100608
#define SMEM_ATTN 100864

__global__ __launch_bounds__(256, 2)
void k_attn()
{
    extern __shared__ char sm[];
    uint32_t sb = (uint32_t)__cvta_generic_to_shared(sm);
    __half* sS1 = (__half*)(sm + AS1);   // [64][72], reused as P
    __half* sS2 = (__half*)(sm + AS2);   // [64][136]
    float* cfs = (float*)(sm + ACF);
    float* lis = (float*)(sm + ALI);

    const int t = threadIdx.x, lane = t&31, w = t>>5;
    const int tx = t&15, ty = t>>4;
    const int wm = w&3, wn = w>>2;
    const int tig = lane&3, grp = lane>>2;
    const int i0 = (15 - blockIdx.x)<<6;   // heavy tiles first
    const int n = blockIdx.y, b = blockIdx.z;

    const __half* Qag = g_Qah + ((size_t)(b*NH+n)*QLEN + i0)*DH;
    const __half* Qbg = g_Qbh + ((size_t)(b*NH+n)*QLEN + i0)*DH;
    const __half* Kg  = g_Kh  + (size_t)(b*NH+n)*KLENN*DH;
    const __half* Vg  = g_Vh  + (size_t)(b*NH+n)*KLENN*DH;
    const __half* Rg  = g_Rh  + (size_t)n*KLENN*DH;

    const int ntiles = (i0>>6) + 17;

    // Q tiles -> Q staging (group A)
    #pragma unroll
    for (int i = 0; i < 4; i++) {
        int c = t + 256*i;
        int which = c >> 9, rc = c & 511;
        int row = rc >> 3, seg = rc & 7;
        const __half* src = (which ? Qbg : Qag) + row*DH + seg*8;
        cpa16(sb + (which ? AQB : AQA) + (uint32_t)(row*72 + seg*8)*2, src);
    }
    asm volatile("cp.async.commit_group;");

    // tile0 KVR -> buf0 (group B)
    {
        uint32_t kvb = sb + AKV0;
        #pragma unroll
        for (int i = 0; i < 8; i++) {
            int c = t + 256*i;
            if (c < 512) {
                int row = c >> 3, seg = c & 7;
                cpa16(kvb + (uint32_t)(row*72 + seg*8)*2, Kg + (size_t)row*DH + seg*8);
            } else if (c < 1024) {
                int rc = c - 512, row = rc >> 3, seg = rc & 7;
                cpa16(kvb + 9216 + (uint32_t)(row*72 + seg*8)*2, Vg + (size_t)row*DH + seg*8);
            } else {
                int rc = c - 1024, row = rc >> 3, seg = rc & 7;
                int mg = 960 - i0 + row;
                cpa16(kvb + 18432 + (uint32_t)(row*72 + seg*8)*2, Rg + (size_t)mg*DH + seg*8);
            }
        }
        asm volatile("cp.async.commit_group;");
    }

    // wait for Q only, extract fragments (frees Q area for buf1)
    asm volatile("cp.async.wait_group 1;");
    __syncthreads();
    uint32_t aQa[4][4], aQb[4][4];
    #pragma unroll
    for (int ks = 0; ks < 4; ks++) {
        uint32_t off = (uint32_t)(((wm*16 + (lane&15))*72 + ks*16 + ((lane>>4)<<3))*2);
        ldsm4(aQa[ks], sb + AQA + off);
        ldsm4(aQb[ks], sb + AQB + off);
    }
    __syncthreads();   // all fragments extracted before buf1 can be written

    float mrow[4], lrow[4], oC[4][4];
    #pragma unroll
    for (int a = 0; a < 4; a++) { mrow[a] = -1e30f; lrow[a] = 0.f; }
    #pragma unroll
    for (int nb = 0; nb < 4; nb++) {
        #pragma unroll
        for (int k = 0; k < 4; k++) oC[nb][k] = 0.f;
    }

    const float fscale = 0.18033688011112042f;

    for (int tile = 0; tile < ntiles; tile++) {
        const int j0 = tile<<6;
        asm volatile("cp.async.wait_group 0;");
        __syncthreads();
        const uint32_t kvb = sb + ((tile & 1) ? AKV1 : AKV0);

        // S-MMA (low register pressure form), spill fp16
        {
            const int r0 = wm*16 + grp;
            #pragma unroll
            for (int p = 0; p < 6; p++) {
                const int blk = wn*12 + 2*p;
                const bool isK = (blk < 8);
                uint32_t base = isK ? kvb : (kvb + 18432);
                int nrow = isK ? blk*8 : (blk-8)*8;
                float c0[4] = {0.f,0.f,0.f,0.f};
                float c1[4] = {0.f,0.f,0.f,0.f};
                #pragma unroll
                for (int ks = 0; ks < 4; ks++) {
                    uint32_t bf[4];
                    uint32_t addr = base + (uint32_t)(((nrow + (lane&7) + ((lane>>4)<<3))*72
                                     + ks*16 + (((lane>>3)&1)<<3))*2);
                    ldsm4(bf, addr);
                    const uint32_t (&aQ)[4] = isK ? aQa[ks] : aQb[ks];
                    mma16h(c0, aQ, bf[0], bf[1]);
                    mma16h(c1, aQ, bf[2], bf[3]);
                }
                if (isK) {
                    int col = blk*8 + 2*tig;
                    *(__half2*)&sS1[r0*72 + col]         = __floats2half2_rn(c0[0], c0[1]);
                    *(__half2*)&sS1[(r0+8)*72 + col]     = __floats2half2_rn(c0[2], c0[3]);
                    *(__half2*)&sS1[r0*72 + col + 8]     = __floats2half2_rn(c1[0], c1[1]);
                    *(__half2*)&sS1[(r0+8)*72 + col + 8] = __floats2half2_rn(c1[2], c1[3]);
                } else {
                    int col = (blk-8)*8 + 2*tig;
                    *(__half2*)&sS2[r0*136 + col]         = __floats2half2_rn(c0[0], c0[1]);
                    *(__half2*)&sS2[(r0+8)*136 + col]     = __floats2half2_rn(c0[2], c0[3]);
                    *(__half2*)&sS2[r0*136 + col + 8]     = __floats2half2_rn(c1[0], c1[1]);
                    *(__half2*)&sS2[(r0+8)*136 + col + 8] = __floats2half2_rn(c1[2], c1[3]);
                }
            }
        }
        __syncthreads();

        // prefetch next tile's KVR into the other buffer (overlaps softmax+PV)
        if (tile + 1 < ntiles) {
            const int j1 = (tile+1)<<6;
            uint32_t nkvb = sb + (((tile+1) & 1) ? AKV1 : AKV0);
            #pragma unroll
            for (int i = 0; i < 8; i++) {
                int c = t + 256*i;
                if (c < 512) {
                    int row = c >> 3, seg = c & 7;
                    cpa16(nkvb + (uint32_t)(row*72 + seg*8)*2, Kg + (size_t)(j1+row)*DH + seg*8);
                } else if (c < 1024) {
                    int rc = c - 512, row = rc >> 3, seg = rc & 7;
                    cpa16(nkvb + 9216 + (uint32_t)(row*72 + seg*8)*2, Vg + (size_t)(j1+row)*DH + seg*8);
                } else {
                    int rc = c - 1024, row = rc >> 3, seg = rc & 7;
                    int mg = j1 + 960 - i0 + row;
                    int ok = (mg < KLENN) ? 16 : 0;
                    if (mg >= KLENN) mg = KLENN - 1;
                    cpa16z(nkvb + 18432 + (uint32_t)(row*72 + seg*8)*2, Rg + (size_t)mg*DH + seg*8, ok);
                }
            }
            asm volatile("cp.async.commit_group;");
        }

        // softmax (scalar, 16x16 grid); P written in place over S1
        #pragma unroll
        for (int a = 0; a < 4; a++) {
            const int il = ty*4 + a;
            const int iq = i0 + il;
            int gb = tx*4 - il + 63;
            float s[4];
            #pragma unroll
            for (int c = 0; c < 4; c++) {
                float v1 = __half2float(sS1[il*72 + tx*4 + c]);
                float v2 = __half2float(sS2[il*136 + gb + c]);
                int jk = j0 + tx*4 + c;
                s[c] = (jk > iq + MLEN) ? -1e30f : (v1 + v2)*fscale;
            }
            float tm = fmaxf(fmaxf(s[0],s[1]), fmaxf(s[2],s[3]));
            tm = fmaxf(tm, __shfl_xor_sync(0xffffffffu, tm, 8));
            tm = fmaxf(tm, __shfl_xor_sync(0xffffffffu, tm, 4));
            tm = fmaxf(tm, __shfl_xor_sync(0xffffffffu, tm, 2));
            tm = fmaxf(tm, __shfl_xor_sync(0xffffffffu, tm, 1));
            float mn = fmaxf(mrow[a], tm);
            float cf = ex2(mrow[a] - mn);
            mrow[a] = mn;
            float p0=ex2(s[0]-mn), p1=ex2(s[1]-mn), p2=ex2(s[2]-mn), p3=ex2(s[3]-mn);
            lrow[a] = lrow[a]*cf + (p0+p1+p2+p3);
            __half2 h01 = __floats2half2_rn(p0, p1);
            __half2 h23 = __floats2half2_rn(p2, p3);
            *(uint2*)&sS1[il*72 + tx*4] = make_uint2(*(uint32_t*)&h01, *(uint32_t*)&h23);
            if (tx == 0) cfs[il] = cf;
        }
        __syncthreads();

        // PV: rescale O, accumulate P*V
        {
            int r0 = wm*16 + grp;
            float cf0 = cfs[r0], cf1 = cfs[r0+8];
            #pragma unroll
            for (int nb = 0; nb < 4; nb++) {
                oC[nb][0] *= cf0; oC[nb][1] *= cf0;
                oC[nb][2] *= cf1; oC[nb][3] *= cf1;
            }
        }
        #pragma unroll
        for (int ks = 0; ks < 4; ks++) {
            uint32_t aP[4];
            ldsm4(aP, sb + AS1 + (uint32_t)(((wm*16 + (lane&15))*72 + ks*16 + ((lane>>4)<<3))*2));
            uint32_t bv0[4], bv1[4];
            uint32_t vb = kvb + 9216 + (uint32_t)(((ks*16 + (lane&15))*72 + wn*32 + ((lane>>4)<<3))*2);
            ldsm4t(bv0, vb);
            ldsm4t(bv1, vb + 32);
            mma16h(oC[0], aP, bv0[0], bv0[1]);
            mma16h(oC[1], aP, bv0[2], bv0[3]);
            mma16h(oC[2], aP, bv1[0], bv1[1]);
            mma16h(oC[3], aP, bv1[2], bv1[3]);
        }
    }

    #pragma unroll
    for (int a = 0; a < 4; a++) {
        float lt = lrow[a];
        lt += __shfl_xor_sync(0xffffffffu, lt, 8);
        lt += __shfl_xor_sync(0xffffffffu, lt, 4);
        lt += __shfl_xor_sync(0xffffffffu, lt, 2);
        lt += __shfl_xor_sync(0xffffffffu, lt, 1);
        if (tx == 0) lis[ty*4+a] = 1.f / lt;
    }
    __syncthreads();
    {
        int r0 = wm*16 + grp;
        float li0 = lis[r0], li1 = lis[r0+8];
        #pragma unroll
        for (int nb = 0; nb < 4; nb++) {
            int col = n*DH + wn*32 + nb*8 + 2*tig;
            size_t row0 = (size_t)(i0 + r0)*BATCH + b;
            size_t row1 = (size_t)(i0 + r0 + 8)*BATCH + b;
            *(__half2*)&g_AVf[row0*DM + col] = __floats2half2_rn(oC[nb][0]*li0, oC[nb][1]*li0);
            *(__half2*)&g_AVf[row1*DM + col] = __floats2half2_rn(oC[nb][2]*li1, oC[nb][3]*li1);
        }
    }
}

// LayerNorm over g_O rows -> d_out
__global__ __launch_bounds__(256)
void k_ln(const float* __restrict__ gamma, const float* __restrict__ beta,
          float* __restrict__ out)
{
    __shared__ float red[16];
    const int t = threadIdx.x;
    const size_t row = blockIdx.x;
    float4 x = *(const float4*)&g_O[row*DM + t*4];
    float s = x.x + x.y + x.z + x.w;
    float ss = x.x*x.x + x.y*x.y + x.z*x.z + x.w*x.w;
    #pragma unroll
    for (int m = 16; m > 0; m >>= 1) {
        s  += __shfl_xor_sync(0xffffffffu, s, m);
        ss += __shfl_xor_sync(0xffffffffu, ss, m);
    }
    if ((t&31) == 0) { red[t>>5] = s; red[8 + (t>>5)] = ss; }
    __syncthreads();
    if (t < 8) {
        float a = red[t], bsum = red[8+t];
        #pragma unroll
        for (int m = 4; m > 0; m >>= 1) {
            a    += __shfl_xor_sync(0xffu, a, m);
            bsum += __shfl_xor_sync(0xffu, bsum, m);
        }
        if (t == 0) { red[0] = a; red[8] = bsum; }
    }
    __syncthreads();
    float mu = red[0] * (1.f/DM);
    float var = red[8] * (1.f/DM) - mu*mu;
    float rs = rsqrtf(var + 1e-5f);
    float4 g = *(const float4*)&gamma[t*4];
    float4 be = *(const float4*)&beta[t*4];
    float4 y;
    y.x = (x.x-mu)*rs*g.x + be.x;
    y.y = (x.y-mu)*rs*g.y + be.y;
    y.z = (x.z-mu)*rs*g.z + be.z;
    y.w = (x.w-mu)*rs*g.w + be.w;
    *(float4*)&out[row*DM + t*4] = y;
}

extern "C" void kernel_launch(void* const* d_in, const int* in_sizes, int n_in,
                              void* d_out, int out_size)
{
    const float* content = (const float*)d_in[0];
    const float* rel_pos = (const float*)d_in[1];
    const float* mems    = (const float*)d_in[2];
    const float* rwb     = (const float*)d_in[3];
    const float* rrb     = (const float*)d_in[4];
    const float* Wqkv    = (const float*)d_in[5];
    const float* Wr      = (const float*)d_in[6];
    const float* Wo      = (const float*)d_in[7];
    const float* gamma   = (const float*)d_in[8];
    const float* beta    = (const float*)d_in[9];
    float* out = (float*)d_out;

    cudaFuncSetAttribute(k_attn,  cudaFuncAttributeMaxDynamicSharedMemorySize, SMEM_ATTN);
    cudaFuncSetAttribute(k_qkv,   cudaFuncAttributeMaxDynamicSharedMemorySize, SMEM_GEMM);
    cudaFuncSetAttribute(k_rproj, cudaFuncAttributeMaxDynamicSharedMemorySize, SMEM_GEMM);
    cudaFuncSetAttribute(k_out,   cudaFuncAttributeMaxDynamicSharedMemorySize, SMEM_GEMM);

    __half *A16, *W316, *Rp16, *Wr16, *Wo16;
    cudaGetSymbolAddress((void**)&A16,  g_A16);
    cudaGetSymbolAddress((void**)&W316, g_W316);
    cudaGetSymbolAddress((void**)&Rp16, g_Rp16);
    cudaGetSymbolAddress((void**)&Wr16, g_Wr16);
    cudaGetSymbolAddress((void**)&Wo16, g_Wo16);

    const int MB = 4096*DM/4;
    k_toh<<<(MB+255)/256, 256>>>(mems,    A16,           MB);
    k_toh<<<(MB+255)/256, 256>>>(content, A16 + 4096*DM, MB);
    k_toh<<<(DM*3072/4+255)/256, 256>>>(Wqkv,    W316, DM*3072/4);
    k_toh<<<(KLENN*DM/4+255)/256, 256>>>(rel_pos, Rp16, KLENN*DM/4);
    k_toh<<<(DM*DM/4+255)/256, 256>>>(Wr, Wr16, DM*DM/4);
    k_toh<<<(DM*DM/4+255)/256, 256>>>(Wo, Wo16, DM*DM/4);

    k_qkv  <<<dim3(24, 64), 256, SMEM_GEMM>>>(rwb, rrb);
    k_rproj<<<dim3(8, 16),  256, SMEM_GEMM>>>();
    k_attn <<<dim3(QLEN/64, NH, BATCH), 256, SMEM_ATTN>>>();
    k_out  <<<dim3(8, 32),  256, SMEM_GEMM>>>(content);
    k_ln   <<<QLEN*BATCH, 256>>>(gamma, beta, out);
}

// round 16
// speedup vs baseline: 2.1850x; 1.0214x over previous
#include <cuda_runtime.h>
#include <cuda_fp16.h>
#include <cstdint>

#define QLEN  1024
#define MLEN  1024
#define KLENN 2048
#define BATCH 4
#define NH    16
#define DH    64
#define DM    1024

// fp32 scratch
__device__ float g_O[QLEN*BATCH*DM];
// fp16 operand planes
__device__ __half g_A16[8192*DM];
__device__ __half g_W316[DM*3072];
__device__ __half g_Rp16[KLENN*DM];
__device__ __half g_Wr16[DM*DM];
__device__ __half g_Wo16[DM*DM];
__device__ __half g_AVf[4096*DM];
// fp16 attention operands
__device__ __half g_Qah[BATCH*NH*QLEN*DH];
__device__ __half g_Qbh[BATCH*NH*QLEN*DH];
__device__ __half g_Kh[BATCH*NH*KLENN*DH];
__device__ __half g_Vh[BATCH*NH*KLENN*DH];
__device__ __half g_Rh[NH*KLENN*DH];

__device__ __forceinline__ float ex2(float x) {
    float y; asm("ex2.approx.ftz.f32 %0, %1;" : "=f"(y) : "f"(x)); return y;
}

// ---------------------------------------------------------------------------
// Fused fp32 -> fp16 cast of all six input tensors in ONE launch.
// Segment sizes in float4 units; grid covers the exact total (15360 x 256).
// ---------------------------------------------------------------------------
#define C0 1048576                 // mems        (4096*1024/4)
#define C1 (C0+1048576)            // content
#define C2 (C1+786432)             // W_qkv       (1024*3072/4)
#define C3 (C2+524288)             // rel_pos     (2048*1024/4)
#define C4 (C3+262144)             // W_r
#define C5 (C4+262144)             // W_o -> total 3932160 = 15360*256

__global__ __launch_bounds__(256)
void k_toh_all(const float* __restrict__ mems, const float* __restrict__ content,
               const float* __restrict__ Wqkv, const float* __restrict__ relpos,
               const float* __restrict__ Wr, const float* __restrict__ Wo)
{
    int i = blockIdx.x*256 + threadIdx.x;
    const float* src; __half* dst; int off;
    if (i < C0)      { src = mems;    dst = g_A16;           off = i; }
    else if (i < C1) { src = content; dst = g_A16 + 4096*DM; off = i - C0; }
    else if (i < C2) { src = Wqkv;    dst = g_W316;          off = i - C1; }
    else if (i < C3) { src = relpos;  dst = g_Rp16;          off = i - C2; }
    else if (i < C4) { src = Wr;      dst = g_Wr16;          off = i - C3; }
    else             { src = Wo;      dst = g_Wo16;          off = i - C4; }
    float4 v = ((const float4*)src)[off];
    __half2 h01 = __floats2half2_rn(v.x, v.y);
    __half2 h23 = __floats2half2_rn(v.z, v.w);
    ((uint2*)dst)[off] = make_uint2(*(uint32_t*)&h01, *(uint32_t*)&h23);
}

// ---------------------------------------------------------------------------
// MMA primitives
// ---------------------------------------------------------------------------
__device__ __forceinline__ void ldsm4(uint32_t (&r)[4], uint32_t addr) {
    asm volatile("ldmatrix.sync.aligned.m8n8.x4.shared.b16 {%0,%1,%2,%3}, [%4];"
        : "=r"(r[0]), "=r"(r[1]), "=r"(r[2]), "=r"(r[3]) : "r"(addr));
}
__device__ __forceinline__ void ldsm4t(uint32_t (&r)[4], uint32_t addr) {
    asm volatile("ldmatrix.sync.aligned.m8n8.x4.trans.shared.b16 {%0,%1,%2,%3}, [%4];"
        : "=r"(r[0]), "=r"(r[1]), "=r"(r[2]), "=r"(r[3]) : "r"(addr));
}
__device__ __forceinline__ void mma16h(float (&c)[4], const uint32_t (&a)[4],
                                       uint32_t b0, uint32_t b1) {
    asm volatile(
        "mma.sync.aligned.m16n8k16.row.col.f32.f16.f16.f32 "
        "{%0,%1,%2,%3},{%4,%5,%6,%7},{%8,%9},{%0,%1,%2,%3};"
        : "+f"(c[0]), "+f"(c[1]), "+f"(c[2]), "+f"(c[3])
        : "r"(a[0]), "r"(a[1]), "r"(a[2]), "r"(a[3]), "r"(b0), "r"(b1));
}
__device__ __forceinline__ void cpa16(uint32_t dst, const void* src) {
    asm volatile("cp.async.cg.shared.global [%0], [%1], 16;" :: "r"(dst), "l"(src));
}
__device__ __forceinline__ void cpa16z(uint32_t dst, const void* src, int nbytes) {
    asm volatile("cp.async.cg.shared.global [%0], [%1], 16, %2;"
                 :: "r"(dst), "l"(src), "r"(nbytes));
}

// ---------------------------------------------------------------------------
// fp16 GEMM core: 128x128 CTA tile, k-step 32, 3-stage cp.async pipeline.
// ---------------------------------------------------------------------------
#define KS 32
#define A_PAD 40
#define B_PAD 136
#define A_PLANE (128*A_PAD)
#define B_PLANE (KS*B_PAD)
#define BUF_ELEMS (A_PLANE + B_PLANE)
#define SMEM_GEMM (3*BUF_ELEMS*2)

__device__ __forceinline__ void cta_load_h(
    uint32_t sb, int buf,
    const __half* __restrict__ A, size_t m0,
    const __half* __restrict__ B, int ldb, int n0, int kt, int t)
{
    uint32_t bo = sb + (uint32_t)buf * (BUF_ELEMS*2);
    #pragma unroll
    for (int i = 0; i < 2; i++) {
        int c = t + 256*i;
        int row = c >> 2, seg = c & 3;
        const __half* src = A + (m0 + row)*DM + kt + seg*8;
        cpa16(bo + (uint32_t)(row*A_PAD + seg*8)*2, src);
    }
    #pragma unroll
    for (int i = 0; i < 2; i++) {
        int c = t + 256*i;
        int row = c >> 4, seg = c & 15;
        const __half* src = B + (size_t)(kt + row)*ldb + n0 + seg*8;
        cpa16(bo + (uint32_t)(A_PLANE*2 + (row*B_PAD + seg*8)*2), src);
    }
}

__device__ __forceinline__ void gemm_h(
    const __half* __restrict__ A, size_t m0,
    const __half* __restrict__ B, int ldb, int n0,
    float (&C)[4][4][4], char* smem, int t)
{
    uint32_t sb = (uint32_t)__cvta_generic_to_shared(smem);
    const int lane = t&31, w = t>>5, wm = w>>2, wn = w&3;
    const uint32_t aBase = (uint32_t)(((wm*64 + (lane&15))*A_PAD + ((lane>>4)<<3))*2);
    const uint32_t bBase = (uint32_t)(A_PLANE*2 + (((lane&15))*B_PAD + wn*32 + ((lane>>4)<<3))*2);
    const int NIT = DM/KS;

    cta_load_h(sb, 0, A, m0, B, ldb, n0, 0, t);
    asm volatile("cp.async.commit_group;");
    cta_load_h(sb, 1, A, m0, B, ldb, n0, KS, t);
    asm volatile("cp.async.commit_group;");

    int buf = 0;
    for (int it = 0; it < NIT; ++it) {
        if (it + 2 < NIT) {
            int nb = buf + 2; if (nb >= 3) nb -= 3;
            cta_load_h(sb, nb, A, m0, B, ldb, n0, (it+2)*KS, t);
            asm volatile("cp.async.commit_group;");
            asm volatile("cp.async.wait_group 2;");
        } else if (it + 1 < NIT) {
            asm volatile("cp.async.wait_group 1;");
        } else {
            asm volatile("cp.async.wait_group 0;");
        }
        __syncthreads();

        uint32_t bo = sb + (uint32_t)buf*(BUF_ELEMS*2);
        #pragma unroll
        for (int c16 = 0; c16 < 2; c16++) {
            uint32_t bb = bo + bBase + (uint32_t)(c16*16*B_PAD*2);
            uint32_t bH0[4], bH1[4];
            ldsm4t(bH0, bb);
            ldsm4t(bH1, bb + 32);
            #pragma unroll
            for (int mt = 0; mt < 4; mt++) {
                uint32_t ab = bo + aBase + (uint32_t)(mt*16*A_PAD*2 + c16*32);
                uint32_t aH[4];
                ldsm4(aH, ab);
                mma16h(C[mt][0], aH, bH0[0], bH0[1]);
                mma16h(C[mt][1], aH, bH0[2], bH0[3]);
                mma16h(C[mt][2], aH, bH1[0], bH1[1]);
                mma16h(C[mt][3], aH, bH1[2], bH1[3]);
            }
        }
        __syncthreads();
        if (++buf == 3) buf = 0;
    }
}

// GEMM 1: cat @ W_qkv -> fp16 Qa/Qb (biases folded) + Kh + Vh directly.
// Compacted 1280-CTA grid (dead mems-Q tiles never launched).
__global__ __launch_bounds__(256)
void k_qkv(const float* __restrict__ rwb, const float* __restrict__ rrb)
{
    extern __shared__ char smg[];
    int id = blockIdx.x;
    int bx, by;
    if (id < 1024) { bx = 8 + (id & 15); by = id >> 4; }
    else           { int j = id - 1024; bx = j & 7; by = 32 + (j >> 3); }
    const int t = threadIdx.x, n0 = bx<<7, m0 = by<<7;
    const int lane = t&31, w = t>>5, wm = w>>2, wn = w&3;
    const int tig = lane&3, grp = lane>>2;
    float C[4][4][4];
    #pragma unroll
    for (int i = 0; i < 4; i++) {
        #pragma unroll
        for (int j = 0; j < 4; j++) {
            #pragma unroll
            for (int k = 0; k < 4; k++) C[i][j][k] = 0.f;
        }
    }
    gemm_h(g_A16, (size_t)m0, g_W316, 3072, n0, C, smg, t);

    #pragma unroll
    for (int mt = 0; mt < 4; mt++) {
        #pragma unroll
        for (int h = 0; h < 2; h++) {
            int m = m0 + wm*64 + mt*16 + grp + 8*h;
            int row = m >> 2, bb = m & 3;
            #pragma unroll
            for (int nt = 0; nt < 4; nt++) {
                int col = n0 + wn*32 + nt*8 + 2*tig;
                int sec = col >> 10, nn = (col>>6)&15, dd = col & 63;
                float c0 = C[mt][nt][2*h], c1 = C[mt][nt][2*h+1];
                if (sec == 0) {
                    if (row >= MLEN) {
                        size_t idx = (((size_t)bb*NH+nn)*QLEN + (row-MLEN))*DH + dd;
                        float2 wa = *(const float2*)&rwb[nn*DH + dd];
                        float2 wb = *(const float2*)&rrb[nn*DH + dd];
                        *(__half2*)&g_Qah[idx] = __floats2half2_rn(c0+wa.x, c1+wa.y);
                        *(__half2*)&g_Qbh[idx] = __floats2half2_rn(c0+wb.x, c1+wb.y);
                    }
                } else if (sec == 1) {
                    *(__half2*)&g_Kh[(((size_t)bb*NH+nn)*KLENN + row)*DH + dd] =
                        __floats2half2_rn(c0, c1);
                } else {
                    *(__half2*)&g_Vh[(((size_t)bb*NH+nn)*KLENN + row)*DH + dd] =
                        __floats2half2_rn(c0, c1);
                }
            }
        }
    }
}

// GEMM 2: rel_pos @ W_r -> fp16 g_Rh[n][m][d] directly.
__global__ __launch_bounds__(256)
void k_rproj()
{
    extern __shared__ char smg[];
    const int t = threadIdx.x, n0 = blockIdx.x<<7, m0 = blockIdx.y<<7;
    const int lane = t&31, w = t>>5, wm = w>>2, wn = w&3;
    const int tig = lane&3, grp = lane>>2;
    float C[4][4][4];
    #pragma unroll
    for (int i = 0; i < 4; i++) {
        #pragma unroll
        for (int j = 0; j < 4; j++) {
            #pragma unroll
            for (int k = 0; k < 4; k++) C[i][j][k] = 0.f;
        }
    }
    gemm_h(g_Rp16, (size_t)m0, g_Wr16, DM, n0, C, smg, t);

    #pragma unroll
    for (int mt = 0; mt < 4; mt++) {
        #pragma unroll
        for (int h = 0; h < 2; h++) {
            int m = m0 + wm*64 + mt*16 + grp + 8*h;
            #pragma unroll
            for (int nt = 0; nt < 4; nt++) {
                int col = n0 + wn*32 + nt*8 + 2*tig;
                int nn = col >> 6, dd = col & 63;
                *(__half2*)&g_Rh[((size_t)nn*KLENN + m)*DH + dd] =
                    __floats2half2_rn(C[mt][nt][2*h], C[mt][nt][2*h+1]);
            }
        }
    }
}

// GEMM 3: AV @ W_o + content -> g_O
__global__ __launch_bounds__(256)
void k_out(const float* __restrict__ content)
{
    extern __shared__ char smg[];
    const int t = threadIdx.x, n0 = blockIdx.x<<7, m0 = blockIdx.y<<7;
    const int lane = t&31, w = t>>5, wm = w>>2, wn = w&3;
    const int tig = lane&3, grp = lane>>2;
    float C[4][4][4];
    #pragma unroll
    for (int i = 0; i < 4; i++) {
        #pragma unroll
        for (int j = 0; j < 4; j++) {
            #pragma unroll
            for (int k = 0; k < 4; k++) C[i][j][k] = 0.f;
        }
    }
    gemm_h(g_AVf, (size_t)m0, g_Wo16, DM, n0, C, smg, t);

    #pragma unroll
    for (int mt = 0; mt < 4; mt++) {
        #pragma unroll
        for (int h = 0; h < 2; h++) {
            size_t m = m0 + wm*64 + mt*16 + grp + 8*h;
            #pragma unroll
            for (int nt = 0; nt < 4; nt++) {
                int col = n0 + wn*32 + nt*8 + 2*tig;
                float2 c4 = *(const float2*)(content + m*DM + col);
                float2 v = make_float2(C[mt][nt][2*h] + c4.x, C[mt][nt][2*h+1] + c4.y);
                *(float2*)&g_O[m*DM + col] = v;
            }
        }
    }
}

// ---------------------------------------------------------------------------
// MMA flash attention with XL rel-shift. KVR double-buffered via smem
// aliasing, P in-place over S1, fp16 S spill, 2 CTAs/SM.
// ---------------------------------------------------------------------------
#define AQA   0
#define AQB   9216
#define AKV1  0
#define AKV0  36864
#define AS1   73728
#define AS2   82944
#define ACF   100352
#define ALI   100608
#define SMEM_ATTN 100864

__global__ __launch_bounds__(256, 2)
void k_attn()
{
    extern __shared__ char sm[];
    uint32_t sb = (uint32_t)__cvta_generic_to_shared(sm);
    __half* sS1 = (__half*)(sm + AS1);   // [64][72], reused as P
    __half* sS2 = (__half*)(sm + AS2);   // [64][136]
    float* cfs = (float*)(sm + ACF);
    float* lis = (float*)(sm + ALI);

    const int t = threadIdx.x, lane = t&31, w = t>>5;
    const int tx = t&15, ty = t>>4;
    const int wm = w&3, wn = w>>2;
    const int tig = lane&3, grp = lane>>2;
    const int i0 = (15 - blockIdx.x)<<6;
    const int n = blockIdx.y, b = blockIdx.z;

    const __half* Qag = g_Qah + ((size_t)(b*NH+n)*QLEN + i0)*DH;
    const __half* Qbg = g_Qbh + ((size_t)(b*NH+n)*QLEN + i0)*DH;
    const __half* Kg  = g_Kh  + (size_t)(b*NH+n)*KLENN*DH;
    const __half* Vg  = g_Vh  + (size_t)(b*NH+n)*KLENN*DH;
    const __half* Rg  = g_Rh  + (size_t)n*KLENN*DH;

    const int ntiles = (i0>>6) + 17;

    #pragma unroll
    for (int i = 0; i < 4; i++) {
        int c = t + 256*i;
        int which = c >> 9, rc = c & 511;
        int row = rc >> 3, seg = rc & 7;
        const __half* src = (which ? Qbg : Qag) + row*DH + seg*8;
        cpa16(sb + (which ? AQB : AQA) + (uint32_t)(row*72 + seg*8)*2, src);
    }
    asm volatile("cp.async.commit_group;");

    {
        uint32_t kvb = sb + AKV0;
        #pragma unroll
        for (int i = 0; i < 8; i++) {
            int c = t + 256*i;
            if (c < 512) {
                int row = c >> 3, seg = c & 7;
                cpa16(kvb + (uint32_t)(row*72 + seg*8)*2, Kg + (size_t)row*DH + seg*8);
            } else if (c < 1024) {
                int rc = c - 512, row = rc >> 3, seg = rc & 7;
                cpa16(kvb + 9216 + (uint32_t)(row*72 + seg*8)*2, Vg + (size_t)row*DH + seg*8);
            } else {
                int rc = c - 1024, row = rc >> 3, seg = rc & 7;
                int mg = 960 - i0 + row;
                cpa16(kvb + 18432 + (uint32_t)(row*72 + seg*8)*2, Rg + (size_t)mg*DH + seg*8);
            }
        }
        asm volatile("cp.async.commit_group;");
    }

    asm volatile("cp.async.wait_group 1;");
    __syncthreads();
    uint32_t aQa[4][4], aQb[4][4];
    #pragma unroll
    for (int ks = 0; ks < 4; ks++) {
        uint32_t off = (uint32_t)(((wm*16 + (lane&15))*72 + ks*16 + ((lane>>4)<<3))*2);
        ldsm4(aQa[ks], sb + AQA + off);
        ldsm4(aQb[ks], sb + AQB + off);
    }
    __syncthreads();

    float mrow[4], lrow[4], oC[4][4];
    #pragma unroll
    for (int a = 0; a < 4; a++) { mrow[a] = -1e30f; lrow[a] = 0.f; }
    #pragma unroll
    for (int nb = 0; nb < 4; nb++) {
        #pragma unroll
        for (int k = 0; k < 4; k++) oC[nb][k] = 0.f;
    }

    const float fscale = 0.18033688011112042f;

    for (int tile = 0; tile < ntiles; tile++) {
        const int j0 = tile<<6;
        asm volatile("cp.async.wait_group 0;");
        __syncthreads();
        const uint32_t kvb = sb + ((tile & 1) ? AKV1 : AKV0);

        // S-MMA, spill fp16
        {
            const int r0 = wm*16 + grp;
            #pragma unroll
            for (int p = 0; p < 6; p++) {
                const int blk = wn*12 + 2*p;
                const bool isK = (blk < 8);
                uint32_t base = isK ? kvb : (kvb + 18432);
                int nrow = isK ? blk*8 : (blk-8)*8;
                float c0[4] = {0.f,0.f,0.f,0.f};
                float c1[4] = {0.f,0.f,0.f,0.f};
                #pragma unroll
                for (int ks = 0; ks < 4; ks++) {
                    uint32_t bf[4];
                    uint32_t addr = base + (uint32_t)(((nrow + (lane&7) + ((lane>>4)<<3))*72
                                     + ks*16 + (((lane>>3)&1)<<3))*2);
                    ldsm4(bf, addr);
                    const uint32_t (&aQ)[4] = isK ? aQa[ks] : aQb[ks];
                    mma16h(c0, aQ, bf[0], bf[1]);
                    mma16h(c1, aQ, bf[2], bf[3]);
                }
                if (isK) {
                    int col = blk*8 + 2*tig;
                    *(__half2*)&sS1[r0*72 + col]         = __floats2half2_rn(c0[0], c0[1]);
                    *(__half2*)&sS1[(r0+8)*72 + col]     = __floats2half2_rn(c0[2], c0[3]);
                    *(__half2*)&sS1[r0*72 + col + 8]     = __floats2half2_rn(c1[0], c1[1]);
                    *(__half2*)&sS1[(r0+8)*72 + col + 8] = __floats2half2_rn(c1[2], c1[3]);
                } else {
                    int col = (blk-8)*8 + 2*tig;
                    *(__half2*)&sS2[r0*136 + col]         = __floats2half2_rn(c0[0], c0[1]);
                    *(__half2*)&sS2[(r0+8)*136 + col]     = __floats2half2_rn(c0[2], c0[3]);
                    *(__half2*)&sS2[r0*136 + col + 8]     = __floats2half2_rn(c1[0], c1[1]);
                    *(__half2*)&sS2[(r0+8)*136 + col + 8] = __floats2half2_rn(c1[2], c1[3]);
                }
            }
        }
        __syncthreads();

        // prefetch next tile's KVR (overlaps softmax+PV)
        if (tile + 1 < ntiles) {
            const int j1 = (tile+1)<<6;
            uint32_t nkvb = sb + (((tile+1) & 1) ? AKV1 : AKV0);
            #pragma unroll
            for (int i = 0; i < 8; i++) {
                int c = t + 256*i;
                if (c < 512) {
                    int row = c >> 3, seg = c & 7;
                    cpa16(nkvb + (uint32_t)(row*72 + seg*8)*2, Kg + (size_t)(j1+row)*DH + seg*8);
                } else if (c < 1024) {
                    int rc = c - 512, row = rc >> 3, seg = rc & 7;
                    cpa16(nkvb + 9216 + (uint32_t)(row*72 + seg*8)*2, Vg + (size_t)(j1+row)*DH + seg*8);
                } else {
                    int rc = c - 1024, row = rc >> 3, seg = rc & 7;
                    int mg = j1 + 960 - i0 + row;
                    int ok = (mg < KLENN) ? 16 : 0;
                    if (mg >= KLENN) mg = KLENN - 1;
                    cpa16z(nkvb + 18432 + (uint32_t)(row*72 + seg*8)*2, Rg + (size_t)mg*DH + seg*8, ok);
                }
            }
            asm volatile("cp.async.commit_group;");
        }

        // softmax; S1 read vectorized, P written in place over S1
        #pragma unroll
        for (int a = 0; a < 4; a++) {
            const int il = ty*4 + a;
            const int iq = i0 + il;
            const __half* s2row = &sS2[il*136 + tx*4 - il + 63];
            uint2 s1v = *(const uint2*)&sS1[il*72 + tx*4];
            float2 f01 = __half22float2(*(__half2*)&s1v.x);
            float2 f23 = __half22float2(*(__half2*)&s1v.y);
            float s[4];
            s[0] = f01.x + __half2float(s2row[0]);
            s[1] = f01.y + __half2float(s2row[1]);
            s[2] = f23.x + __half2float(s2row[2]);
            s[3] = f23.y + __half2float(s2row[3]);
            #pragma unroll
            for (int c = 0; c < 4; c++) {
                int jk = j0 + tx*4 + c;
                s[c] = (jk > iq + MLEN) ? -1e30f : s[c]*fscale;
            }
            float tm = fmaxf(fmaxf(s[0],s[1]), fmaxf(s[2],s[3]));
            tm = fmaxf(tm, __shfl_xor_sync(0xffffffffu, tm, 8));
            tm = fmaxf(tm, __shfl_xor_sync(0xffffffffu, tm, 4));
            tm = fmaxf(tm, __shfl_xor_sync(0xffffffffu, tm, 2));
            tm = fmaxf(tm, __shfl_xor_sync(0xffffffffu, tm, 1));
            float mn = fmaxf(mrow[a], tm);
            float cf = ex2(mrow[a] - mn);
            mrow[a] = mn;
            float p0=ex2(s[0]-mn), p1=ex2(s[1]-mn), p2=ex2(s[2]-mn), p3=ex2(s[3]-mn);
            lrow[a] = lrow[a]*cf + (p0+p1+p2+p3);
            __half2 h01 = __floats2half2_rn(p0, p1);
            __half2 h23 = __floats2half2_rn(p2, p3);
            *(uint2*)&sS1[il*72 + tx*4] = make_uint2(*(uint32_t*)&h01, *(uint32_t*)&h23);
            if (tx == 0) cfs[il] = cf;
        }
        __syncthreads();

        // PV
        {
            int r0 = wm*16 + grp;
            float cf0 = cfs[r0], cf1 = cfs[r0+8];
            #pragma unroll
            for (int nb = 0; nb < 4; nb++) {
                oC[nb][0] *= cf0; oC[nb][1] *= cf0;
                oC[nb][2] *= cf1; oC[nb][3] *= cf1;
            }
        }
        #pragma unroll
        for (int ks = 0; ks < 4; ks++) {
            uint32_t aP[4];
            ldsm4(aP, sb + AS1 + (uint32_t)(((wm*16 + (lane&15))*72 + ks*16 + ((lane>>4)<<3))*2));
            uint32_t bv0[4], bv1[4];
            uint32_t vb = kvb + 9216 + (uint32_t)(((ks*16 + (lane&15))*72 + wn*32 + ((lane>>4)<<3))*2);
            ldsm4t(bv0, vb);
            ldsm4t(bv1, vb + 32);
            mma16h(oC[0], aP, bv0[0], bv0[1]);
            mma16h(oC[1], aP, bv0[2], bv0[3]);
            mma16h(oC[2], aP, bv1[0], bv1[1]);
            mma16h(oC[3], aP, bv1[2], bv1[3]);
        }
    }

    #pragma unroll
    for (int a = 0; a < 4; a++) {
        float lt = lrow[a];
        lt += __shfl_xor_sync(0xffffffffu, lt, 8);
        lt += __shfl_xor_sync(0xffffffffu, lt, 4);
        lt += __shfl_xor_sync(0xffffffffu, lt, 2);
        lt += __shfl_xor_sync(0xffffffffu, lt, 1);
        if (tx == 0) lis[ty*4+a] = 1.f / lt;
    }
    __syncthreads();
    {
        int r0 = wm*16 + grp;
        float li0 = lis[r0], li1 = lis[r0+8];
        #pragma unroll
        for (int nb = 0; nb < 4; nb++) {
            int col = n*DH + wn*32 + nb*8 + 2*tig;
            size_t row0 = (size_t)(i0 + r0)*BATCH + b;
            size_t row1 = (size_t)(i0 + r0 + 8)*BATCH + b;
            *(__half2*)&g_AVf[row0*DM + col] = __floats2half2_rn(oC[nb][0]*li0, oC[nb][1]*li0);
            *(__half2*)&g_AVf[row1*DM + col] = __floats2half2_rn(oC[nb][2]*li1, oC[nb][3]*li1);
        }
    }
}

// LayerNorm over g_O rows -> d_out
__global__ __launch_bounds__(256)
void k_ln(const float* __restrict__ gamma, const float* __restrict__ beta,
          float* __restrict__ out)
{
    __shared__ float red[16];
    const int t = threadIdx.x;
    const size_t row = blockIdx.x;
    float4 x = *(const float4*)&g_O[row*DM + t*4];
    float s = x.x + x.y + x.z + x.w;
    float ss = x.x*x.x + x.y*x.y + x.z*x.z + x.w*x.w;
    #pragma unroll
    for (int m = 16; m > 0; m >>= 1) {
        s  += __shfl_xor_sync(0xffffffffu, s, m);
        ss += __shfl_xor_sync(0xffffffffu, ss, m);
    }
    if ((t&31) == 0) { red[t>>5] = s; red[8 + (t>>5)] = ss; }
    __syncthreads();
    if (t < 8) {
        float a = red[t], bsum = red[8+t];
        #pragma unroll
        for (int m = 4; m > 0; m >>= 1) {
            a    += __shfl_xor_sync(0xffu, a, m);
            bsum += __shfl_xor_sync(0xffu, bsum, m);
        }
        if (t == 0) { red[0] = a; red[8] = bsum; }
    }
    __syncthreads();
    float mu = red[0] * (1.f/DM);
    float var = red[8] * (1.f/DM) - mu*mu;
    float rs = rsqrtf(var + 1e-5f);
    float4 g = *(const float4*)&gamma[t*4];
    float4 be = *(const float4*)&beta[t*4];
    float4 y;
    y.x = (x.x-mu)*rs*g.x + be.x;
    y.y = (x.y-mu)*rs*g.y + be.y;
    y.z = (x.z-mu)*rs*g.z + be.z;
    y.w = (x.w-mu)*rs*g.w + be.w;
    *(float4*)&out[row*DM + t*4] = y;
}

extern "C" void kernel_launch(void* const* d_in, const int* in_sizes, int n_in,
                              void* d_out, int out_size)
{
    const float* content = (const float*)d_in[0];
    const float* rel_pos = (const float*)d_in[1];
    const float* mems    = (const float*)d_in[2];
    const float* rwb     = (const float*)d_in[3];
    const float* rrb     = (const float*)d_in[4];
    const float* Wqkv    = (const float*)d_in[5];
    const float* Wr      = (const float*)d_in[6];
    const float* Wo      = (const float*)d_in[7];
    const float* gamma   = (const float*)d_in[8];
    const float* beta    = (const float*)d_in[9];
    float* out = (float*)d_out;

    cudaFuncSetAttribute(k_attn,  cudaFuncAttributeMaxDynamicSharedMemorySize, SMEM_ATTN);
    cudaFuncSetAttribute(k_qkv,   cudaFuncAttributeMaxDynamicSharedMemorySize, SMEM_GEMM);
    cudaFuncSetAttribute(k_rproj, cudaFuncAttributeMaxDynamicSharedMemorySize, SMEM_GEMM);
    cudaFuncSetAttribute(k_out,   cudaFuncAttributeMaxDynamicSharedMemorySize, SMEM_GEMM);

    k_toh_all<<<15360, 256>>>(mems, content, Wqkv, rel_pos, Wr, Wo);
    k_qkv  <<<1280, 256, SMEM_GEMM>>>(rwb, rrb);
    k_rproj<<<dim3(8, 16), 256, SMEM_GEMM>>>();
    k_attn <<<dim3(QLEN/64, NH, BATCH), 256, SMEM_ATTN>>>();
    k_out  <<<dim3(8, 32),  256, SMEM_GEMM>>>(content);
    k_ln   <<<QLEN*BATCH, 256>>>(gamma, beta, out);
}

// round 17
// speedup vs baseline: 2.3009x; 1.0531x over previous
#include <cuda_runtime.h>
#include <cuda_fp16.h>
#include <cstdint>

#define QLEN  1024
#define MLEN  1024
#define KLENN 2048
#define BATCH 4
#define NH    16
#define DH    64
#define DM    1024

// fp32 scratch
__device__ float g_O[QLEN*BATCH*DM];
// fp16 operand planes
__device__ __half g_A16[8192*DM];
__device__ __half g_W316[DM*3072];
__device__ __half g_Rp16[KLENN*DM];
__device__ __half g_Wr16[DM*DM];
__device__ __half g_Wo16[DM*DM];
__device__ __half g_AVf[4096*DM];
// fp16 attention operands
__device__ __half g_Qah[BATCH*NH*QLEN*DH];
__device__ __half g_Qbh[BATCH*NH*QLEN*DH];
__device__ __half g_Kh[BATCH*NH*KLENN*DH];
__device__ __half g_Vh[BATCH*NH*KLENN*DH];
__device__ __half g_Rh[NH*KLENN*DH];

__device__ __forceinline__ float ex2(float x) {
    float y; asm("ex2.approx.ftz.f32 %0, %1;" : "=f"(y) : "f"(x)); return y;
}

// ---------------------------------------------------------------------------
// Fused fp32 -> fp16 cast of all six input tensors in ONE launch.
// ---------------------------------------------------------------------------
#define C0 1048576
#define C1 (C0+1048576)
#define C2 (C1+786432)
#define C3 (C2+524288)
#define C4 (C3+262144)
#define C5 (C4+262144)

__global__ __launch_bounds__(256)
void k_toh_all(const float* __restrict__ mems, const float* __restrict__ content,
               const float* __restrict__ Wqkv, const float* __restrict__ relpos,
               const float* __restrict__ Wr, const float* __restrict__ Wo)
{
    int i = blockIdx.x*256 + threadIdx.x;
    const float* src; __half* dst; int off;
    if (i < C0)      { src = mems;    dst = g_A16;           off = i; }
    else if (i < C1) { src = content; dst = g_A16 + 4096*DM; off = i - C0; }
    else if (i < C2) { src = Wqkv;    dst = g_W316;          off = i - C1; }
    else if (i < C3) { src = relpos;  dst = g_Rp16;          off = i - C2; }
    else if (i < C4) { src = Wr;      dst = g_Wr16;          off = i - C3; }
    else             { src = Wo;      dst = g_Wo16;          off = i - C4; }
    float4 v = ((const float4*)src)[off];
    __half2 h01 = __floats2half2_rn(v.x, v.y);
    __half2 h23 = __floats2half2_rn(v.z, v.w);
    ((uint2*)dst)[off] = make_uint2(*(uint32_t*)&h01, *(uint32_t*)&h23);
}

// ---------------------------------------------------------------------------
// MMA primitives
// ---------------------------------------------------------------------------
__device__ __forceinline__ void ldsm4(uint32_t (&r)[4], uint32_t addr) {
    asm volatile("ldmatrix.sync.aligned.m8n8.x4.shared.b16 {%0,%1,%2,%3}, [%4];"
        : "=r"(r[0]), "=r"(r[1]), "=r"(r[2]), "=r"(r[3]) : "r"(addr));
}
__device__ __forceinline__ void ldsm4t(uint32_t (&r)[4], uint32_t addr) {
    asm volatile("ldmatrix.sync.aligned.m8n8.x4.trans.shared.b16 {%0,%1,%2,%3}, [%4];"
        : "=r"(r[0]), "=r"(r[1]), "=r"(r[2]), "=r"(r[3]) : "r"(addr));
}
__device__ __forceinline__ void mma16h(float (&c)[4], const uint32_t (&a)[4],
                                       uint32_t b0, uint32_t b1) {
    asm volatile(
        "mma.sync.aligned.m16n8k16.row.col.f32.f16.f16.f32 "
        "{%0,%1,%2,%3},{%4,%5,%6,%7},{%8,%9},{%0,%1,%2,%3};"
        : "+f"(c[0]), "+f"(c[1]), "+f"(c[2]), "+f"(c[3])
        : "r"(a[0]), "r"(a[1]), "r"(a[2]), "r"(a[3]), "r"(b0), "r"(b1));
}
__device__ __forceinline__ void cpa16(uint32_t dst, const void* src) {
    asm volatile("cp.async.cg.shared.global [%0], [%1], 16;" :: "r"(dst), "l"(src));
}
__device__ __forceinline__ void cpa16z(uint32_t dst, const void* src, int nbytes) {
    asm volatile("cp.async.cg.shared.global [%0], [%1], 16, %2;"
                 :: "r"(dst), "l"(src), "r"(nbytes));
}

// ---------------------------------------------------------------------------
// fp16 GEMM core: 128x128 CTA tile, k-step 32, 3-stage cp.async pipeline.
// ---------------------------------------------------------------------------
#define KS 32
#define A_PAD 40
#define B_PAD 136
#define A_PLANE (128*A_PAD)
#define B_PLANE (KS*B_PAD)
#define BUF_ELEMS (A_PLANE + B_PLANE)
#define SMEM_GEMM (3*BUF_ELEMS*2)

__device__ __forceinline__ void cta_load_h(
    uint32_t sb, int buf,
    const __half* __restrict__ A, size_t m0,
    const __half* __restrict__ B, int ldb, int n0, int kt, int t)
{
    uint32_t bo = sb + (uint32_t)buf * (BUF_ELEMS*2);
    #pragma unroll
    for (int i = 0; i < 2; i++) {
        int c = t + 256*i;
        int row = c >> 2, seg = c & 3;
        const __half* src = A + (m0 + row)*DM + kt + seg*8;
        cpa16(bo + (uint32_t)(row*A_PAD + seg*8)*2, src);
    }
    #pragma unroll
    for (int i = 0; i < 2; i++) {
        int c = t + 256*i;
        int row = c >> 4, seg = c & 15;
        const __half* src = B + (size_t)(kt + row)*ldb + n0 + seg*8;
        cpa16(bo + (uint32_t)(A_PLANE*2 + (row*B_PAD + seg*8)*2), src);
    }
}

__device__ __forceinline__ void gemm_h(
    const __half* __restrict__ A, size_t m0,
    const __half* __restrict__ B, int ldb, int n0,
    float (&C)[4][4][4], char* smem, int t)
{
    uint32_t sb = (uint32_t)__cvta_generic_to_shared(smem);
    const int lane = t&31, w = t>>5, wm = w>>2, wn = w&3;
    const uint32_t aBase = (uint32_t)(((wm*64 + (lane&15))*A_PAD + ((lane>>4)<<3))*2);
    const uint32_t bBase = (uint32_t)(A_PLANE*2 + (((lane&15))*B_PAD + wn*32 + ((lane>>4)<<3))*2);
    const int NIT = DM/KS;

    cta_load_h(sb, 0, A, m0, B, ldb, n0, 0, t);
    asm volatile("cp.async.commit_group;");
    cta_load_h(sb, 1, A, m0, B, ldb, n0, KS, t);
    asm volatile("cp.async.commit_group;");

    int buf = 0;
    for (int it = 0; it < NIT; ++it) {
        if (it + 2 < NIT) {
            int nb = buf + 2; if (nb >= 3) nb -= 3;
            cta_load_h(sb, nb, A, m0, B, ldb, n0, (it+2)*KS, t);
            asm volatile("cp.async.commit_group;");
            asm volatile("cp.async.wait_group 2;");
        } else if (it + 1 < NIT) {
            asm volatile("cp.async.wait_group 1;");
        } else {
            asm volatile("cp.async.wait_group 0;");
        }
        __syncthreads();

        uint32_t bo = sb + (uint32_t)buf*(BUF_ELEMS*2);
        #pragma unroll
        for (int c16 = 0; c16 < 2; c16++) {
            uint32_t bb = bo + bBase + (uint32_t)(c16*16*B_PAD*2);
            uint32_t bH0[4], bH1[4];
            ldsm4t(bH0, bb);
            ldsm4t(bH1, bb + 32);
            #pragma unroll
            for (int mt = 0; mt < 4; mt++) {
                uint32_t ab = bo + aBase + (uint32_t)(mt*16*A_PAD*2 + c16*32);
                uint32_t aH[4];
                ldsm4(aH, ab);
                mma16h(C[mt][0], aH, bH0[0], bH0[1]);
                mma16h(C[mt][1], aH, bH0[2], bH0[3]);
                mma16h(C[mt][2], aH, bH1[0], bH1[1]);
                mma16h(C[mt][3], aH, bH1[2], bH1[3]);
            }
        }
        __syncthreads();
        if (++buf == 3) buf = 0;
    }
}

// GEMM 1: cat @ W_qkv -> fp16 Qa/Qb (biases folded) + Kh + Vh directly.
__global__ __launch_bounds__(256)
void k_qkv(const float* __restrict__ rwb, const float* __restrict__ rrb)
{
    extern __shared__ char smg[];
    int id = blockIdx.x;
    int bx, by;
    if (id < 1024) { bx = 8 + (id & 15); by = id >> 4; }
    else           { int j = id - 1024; bx = j & 7; by = 32 + (j >> 3); }
    const int t = threadIdx.x, n0 = bx<<7, m0 = by<<7;
    const int lane = t&31, w = t>>5, wm = w>>2, wn = w&3;
    const int tig = lane&3, grp = lane>>2;
    float C[4][4][4];
    #pragma unroll
    for (int i = 0; i < 4; i++) {
        #pragma unroll
        for (int j = 0; j < 4; j++) {
            #pragma unroll
            for (int k = 0; k < 4; k++) C[i][j][k] = 0.f;
        }
    }
    gemm_h(g_A16, (size_t)m0, g_W316, 3072, n0, C, smg, t);

    #pragma unroll
    for (int mt = 0; mt < 4; mt++) {
        #pragma unroll
        for (int h = 0; h < 2; h++) {
            int m = m0 + wm*64 + mt*16 + grp + 8*h;
            int row = m >> 2, bb = m & 3;
            #pragma unroll
            for (int nt = 0; nt < 4; nt++) {
                int col = n0 + wn*32 + nt*8 + 2*tig;
                int sec = col >> 10, nn = (col>>6)&15, dd = col & 63;
                float c0 = C[mt][nt][2*h], c1 = C[mt][nt][2*h+1];
                if (sec == 0) {
                    if (row >= MLEN) {
                        size_t idx = (((size_t)bb*NH+nn)*QLEN + (row-MLEN))*DH + dd;
                        float2 wa = *(const float2*)&rwb[nn*DH + dd];
                        float2 wb = *(const float2*)&rrb[nn*DH + dd];
                        *(__half2*)&g_Qah[idx] = __floats2half2_rn(c0+wa.x, c1+wa.y);
                        *(__half2*)&g_Qbh[idx] = __floats2half2_rn(c0+wb.x, c1+wb.y);
                    }
                } else if (sec == 1) {
                    *(__half2*)&g_Kh[(((size_t)bb*NH+nn)*KLENN + row)*DH + dd] =
                        __floats2half2_rn(c0, c1);
                } else {
                    *(__half2*)&g_Vh[(((size_t)bb*NH+nn)*KLENN + row)*DH + dd] =
                        __floats2half2_rn(c0, c1);
                }
            }
        }
    }
}

// GEMM 2: rel_pos @ W_r -> fp16 g_Rh[n][m][d] directly.
__global__ __launch_bounds__(256)
void k_rproj()
{
    extern __shared__ char smg[];
    const int t = threadIdx.x, n0 = blockIdx.x<<7, m0 = blockIdx.y<<7;
    const int lane = t&31, w = t>>5, wm = w>>2, wn = w&3;
    const int tig = lane&3, grp = lane>>2;
    float C[4][4][4];
    #pragma unroll
    for (int i = 0; i < 4; i++) {
        #pragma unroll
        for (int j = 0; j < 4; j++) {
            #pragma unroll
            for (int k = 0; k < 4; k++) C[i][j][k] = 0.f;
        }
    }
    gemm_h(g_Rp16, (size_t)m0, g_Wr16, DM, n0, C, smg, t);

    #pragma unroll
    for (int mt = 0; mt < 4; mt++) {
        #pragma unroll
        for (int h = 0; h < 2; h++) {
            int m = m0 + wm*64 + mt*16 + grp + 8*h;
            #pragma unroll
            for (int nt = 0; nt < 4; nt++) {
                int col = n0 + wn*32 + nt*8 + 2*tig;
                int nn = col >> 6, dd = col & 63;
                *(__half2*)&g_Rh[((size_t)nn*KLENN + m)*DH + dd] =
                    __floats2half2_rn(C[mt][nt][2*h], C[mt][nt][2*h+1]);
            }
        }
    }
}

// GEMM 3: AV @ W_o + content -> g_O
__global__ __launch_bounds__(256)
void k_out(const float* __restrict__ content)
{
    extern __shared__ char smg[];
    const int t = threadIdx.x, n0 = blockIdx.x<<7, m0 = blockIdx.y<<7;
    const int lane = t&31, w = t>>5, wm = w>>2, wn = w&3;
    const int tig = lane&3, grp = lane>>2;
    float C[4][4][4];
    #pragma unroll
    for (int i = 0; i < 4; i++) {
        #pragma unroll
        for (int j = 0; j < 4; j++) {
            #pragma unroll
            for (int k = 0; k < 4; k++) C[i][j][k] = 0.f;
        }
    }
    gemm_h(g_AVf, (size_t)m0, g_Wo16, DM, n0, C, smg, t);

    #pragma unroll
    for (int mt = 0; mt < 4; mt++) {
        #pragma unroll
        for (int h = 0; h < 2; h++) {
            size_t m = m0 + wm*64 + mt*16 + grp + 8*h;
            #pragma unroll
            for (int nt = 0; nt < 4; nt++) {
                int col = n0 + wn*32 + nt*8 + 2*tig;
                float2 c4 = *(const float2*)(content + m*DM + col);
                float2 v = make_float2(C[mt][nt][2*h] + c4.x, C[mt][nt][2*h+1] + c4.y);
                *(float2*)&g_O[m*DM + col] = v;
            }
        }
    }
}

// ---------------------------------------------------------------------------
// MMA flash attention with XL rel-shift. Banded BD computation: per row-tile
// wm only rl-blocks [6-2wm, 15-2wm] are computed/spilled (all that the
// gather reads). KVR double-buffered via smem aliasing, P in-place over S1,
// fp16 S spill, 2 CTAs/SM.
// ---------------------------------------------------------------------------
#define AQA   0
#define AQB   9216
#define AKV1  0
#define AKV0  36864
#define AS1   73728
#define AS2   82944
#define ACF   100352
#define ALI   100608
#define SMEM_ATTN 100864

__global__ __launch_bounds__(256, 2)
void k_attn()
{
    extern __shared__ char sm[];
    uint32_t sb = (uint32_t)__cvta_generic_to_shared(sm);
    __half* sS1 = (__half*)(sm + AS1);   // [64][72], reused as P
    __half* sS2 = (__half*)(sm + AS2);   // [64][136]
    float* cfs = (float*)(sm + ACF);
    float* lis = (float*)(sm + ALI);

    const int t = threadIdx.x, lane = t&31, w = t>>5;
    const int tx = t&15, ty = t>>4;
    const int wm = w&3, wn = w>>2;
    const int tig = lane&3, grp = lane>>2;
    const int i0 = (15 - blockIdx.x)<<6;
    const int n = blockIdx.y, b = blockIdx.z;

    const __half* Qag = g_Qah + ((size_t)(b*NH+n)*QLEN + i0)*DH;
    const __half* Qbg = g_Qbh + ((size_t)(b*NH+n)*QLEN + i0)*DH;
    const __half* Kg  = g_Kh  + (size_t)(b*NH+n)*KLENN*DH;
    const __half* Vg  = g_Vh  + (size_t)(b*NH+n)*KLENN*DH;
    const __half* Rg  = g_Rh  + (size_t)n*KLENN*DH;

    const int ntiles = (i0>>6) + 17;

    #pragma unroll
    for (int i = 0; i < 4; i++) {
        int c = t + 256*i;
        int which = c >> 9, rc = c & 511;
        int row = rc >> 3, seg = rc & 7;
        const __half* src = (which ? Qbg : Qag) + row*DH + seg*8;
        cpa16(sb + (which ? AQB : AQA) + (uint32_t)(row*72 + seg*8)*2, src);
    }
    asm volatile("cp.async.commit_group;");

    {
        uint32_t kvb = sb + AKV0;
        #pragma unroll
        for (int i = 0; i < 8; i++) {
            int c = t + 256*i;
            if (c < 512) {
                int row = c >> 3, seg = c & 7;
                cpa16(kvb + (uint32_t)(row*72 + seg*8)*2, Kg + (size_t)row*DH + seg*8);
            } else if (c < 1024) {
                int rc = c - 512, row = rc >> 3, seg = rc & 7;
                cpa16(kvb + 9216 + (uint32_t)(row*72 + seg*8)*2, Vg + (size_t)row*DH + seg*8);
            } else {
                int rc = c - 1024, row = rc >> 3, seg = rc & 7;
                int mg = 960 - i0 + row;
                cpa16(kvb + 18432 + (uint32_t)(row*72 + seg*8)*2, Rg + (size_t)mg*DH + seg*8);
            }
        }
        asm volatile("cp.async.commit_group;");
    }

    asm volatile("cp.async.wait_group 1;");
    __syncthreads();
    uint32_t aQa[4][4], aQb[4][4];
    #pragma unroll
    for (int ks = 0; ks < 4; ks++) {
        uint32_t off = (uint32_t)(((wm*16 + (lane&15))*72 + ks*16 + ((lane>>4)<<3))*2);
        ldsm4(aQa[ks], sb + AQA + off);
        ldsm4(aQb[ks], sb + AQB + off);
    }
    __syncthreads();

    float mrow[4], lrow[4], oC[4][4];
    #pragma unroll
    for (int a = 0; a < 4; a++) { mrow[a] = -1e30f; lrow[a] = 0.f; }
    #pragma unroll
    for (int nb = 0; nb < 4; nb++) {
        #pragma unroll
        for (int k = 0; k < 4; k++) oC[nb][k] = 0.f;
    }

    const float fscale = 0.18033688011112042f;

    for (int tile = 0; tile < ntiles; tile++) {
        const int j0 = tile<<6;
        asm volatile("cp.async.wait_group 0;");
        __syncthreads();
        const uint32_t kvb = sb + ((tile & 1) ? AKV1 : AKV0);

        // S-MMA, banded BD. wn=0: 4 AC pairs + 1 BD pair (blocks 14-2wm,15-2wm);
        // wn=1: 4 BD pairs (blocks 6-2wm .. 13-2wm).
        {
            const int r0 = wm*16 + grp;
            #pragma unroll
            for (int pp = 0; pp < 5; pp++) {
                if (pp == 4 && wn != 0) break;
                bool isK; int nrow;
                if (wn == 0) {
                    if (pp < 4) { isK = true;  nrow = pp*16; }
                    else        { isK = false; nrow = 112 - 16*wm; }
                } else {
                    isK = false; nrow = 48 - 16*wm + 16*pp;
                }
                uint32_t base = isK ? kvb : (kvb + 18432);
                float c0[4] = {0.f,0.f,0.f,0.f};
                float c1[4] = {0.f,0.f,0.f,0.f};
                #pragma unroll
                for (int ks = 0; ks < 4; ks++) {
                    uint32_t bf[4];
                    uint32_t addr = base + (uint32_t)(((nrow + (lane&7) + ((lane>>4)<<3))*72
                                     + ks*16 + (((lane>>3)&1)<<3))*2);
                    ldsm4(bf, addr);
                    const uint32_t (&aQ)[4] = isK ? aQa[ks] : aQb[ks];
                    mma16h(c0, aQ, bf[0], bf[1]);
                    mma16h(c1, aQ, bf[2], bf[3]);
                }
                __half* sS = isK ? sS1 : sS2;
                const int pitch = isK ? 72 : 136;
                int col = nrow + 2*tig;
                *(__half2*)&sS[r0*pitch + col]         = __floats2half2_rn(c0[0], c0[1]);
                *(__half2*)&sS[(r0+8)*pitch + col]     = __floats2half2_rn(c0[2], c0[3]);
                *(__half2*)&sS[r0*pitch + col + 8]     = __floats2half2_rn(c1[0], c1[1]);
                *(__half2*)&sS[(r0+8)*pitch + col + 8] = __floats2half2_rn(c1[2], c1[3]);
            }
        }
        __syncthreads();

        // prefetch next tile's KVR (overlaps softmax+PV)
        if (tile + 1 < ntiles) {
            const int j1 = (tile+1)<<6;
            uint32_t nkvb = sb + (((tile+1) & 1) ? AKV1 : AKV0);
            #pragma unroll
            for (int i = 0; i < 8; i++) {
                int c = t + 256*i;
                if (c < 512) {
                    int row = c >> 3, seg = c & 7;
                    cpa16(nkvb + (uint32_t)(row*72 + seg*8)*2, Kg + (size_t)(j1+row)*DH + seg*8);
                } else if (c < 1024) {
                    int rc = c - 512, row = rc >> 3, seg = rc & 7;
                    cpa16(nkvb + 9216 + (uint32_t)(row*72 + seg*8)*2, Vg + (size_t)(j1+row)*DH + seg*8);
                } else {
                    int rc = c - 1024, row = rc >> 3, seg = rc & 7;
                    int mg = j1 + 960 - i0 + row;
                    int ok = (mg < KLENN) ? 16 : 0;
                    if (mg >= KLENN) mg = KLENN - 1;
                    cpa16z(nkvb + 18432 + (uint32_t)(row*72 + seg*8)*2, Rg + (size_t)mg*DH + seg*8, ok);
                }
            }
            asm volatile("cp.async.commit_group;");
        }

        // softmax; S1 read vectorized, P written in place over S1
        #pragma unroll
        for (int a = 0; a < 4; a++) {
            const int il = ty*4 + a;
            const int iq = i0 + il;
            const __half* s2row = &sS2[il*136 + tx*4 - il + 63];
            uint2 s1v = *(const uint2*)&sS1[il*72 + tx*4];
            float2 f01 = __half22float2(*(__half2*)&s1v.x);
            float2 f23 = __half22float2(*(__half2*)&s1v.y);
            float s[4];
            s[0] = f01.x + __half2float(s2row[0]);
            s[1] = f01.y + __half2float(s2row[1]);
            s[2] = f23.x + __half2float(s2row[2]);
            s[3] = f23.y + __half2float(s2row[3]);
            #pragma unroll
            for (int c = 0; c < 4; c++) {
                int jk = j0 + tx*4 + c;
                s[c] = (jk > iq + MLEN) ? -1e30f : s[c]*fscale;
            }
            float tm = fmaxf(fmaxf(s[0],s[1]), fmaxf(s[2],s[3]));
            tm = fmaxf(tm, __shfl_xor_sync(0xffffffffu, tm, 8));
            tm = fmaxf(tm, __shfl_xor_sync(0xffffffffu, tm, 4));
            tm = fmaxf(tm, __shfl_xor_sync(0xffffffffu, tm, 2));
            tm = fmaxf(tm, __shfl_xor_sync(0xffffffffu, tm, 1));
            float mn = fmaxf(mrow[a], tm);
            float cf = ex2(mrow[a] - mn);
            mrow[a] = mn;
            float p0=ex2(s[0]-mn), p1=ex2(s[1]-mn), p2=ex2(s[2]-mn), p3=ex2(s[3]-mn);
            lrow[a] = lrow[a]*cf + (p0+p1+p2+p3);
            __half2 h01 = __floats2half2_rn(p0, p1);
            __half2 h23 = __floats2half2_rn(p2, p3);
            *(uint2*)&sS1[il*72 + tx*4] = make_uint2(*(uint32_t*)&h01, *(uint32_t*)&h23);
            if (tx == 0) cfs[il] = cf;
        }
        __syncthreads();

        // PV
        {
            int r0 = wm*16 + grp;
            float cf0 = cfs[r0], cf1 = cfs[r0+8];
            #pragma unroll
            for (int nb = 0; nb < 4; nb++) {
                oC[nb][0] *= cf0; oC[nb][1] *= cf0;
                oC[nb][2] *= cf1; oC[nb][3] *= cf1;
            }
        }
        #pragma unroll
        for (int ks = 0; ks < 4; ks++) {
            uint32_t aP[4];
            ldsm4(aP, sb + AS1 + (uint32_t)(((wm*16 + (lane&15))*72 + ks*16 + ((lane>>4)<<3))*2));
            uint32_t bv0[4], bv1[4];
            uint32_t vb = kvb + 9216 + (uint32_t)(((ks*16 + (lane&15))*72 + wn*32 + ((lane>>4)<<3))*2);
            ldsm4t(bv0, vb);
            ldsm4t(bv1, vb + 32);
            mma16h(oC[0], aP, bv0[0], bv0[1]);
            mma16h(oC[1], aP, bv0[2], bv0[3]);
            mma16h(oC[2], aP, bv1[0], bv1[1]);
            mma16h(oC[3], aP, bv1[2], bv1[3]);
        }
    }

    #pragma unroll
    for (int a = 0; a < 4; a++) {
        float lt = lrow[a];
        lt += __shfl_xor_sync(0xffffffffu, lt, 8);
        lt += __shfl_xor_sync(0xffffffffu, lt, 4);
        lt += __shfl_xor_sync(0xffffffffu, lt, 2);
        lt += __shfl_xor_sync(0xffffffffu, lt, 1);
        if (tx == 0) lis[ty*4+a] = 1.f / lt;
    }
    __syncthreads();
    {
        int r0 = wm*16 + grp;
        float li0 = lis[r0], li1 = lis[r0+8];
        #pragma unroll
        for (int nb = 0; nb < 4; nb++) {
            int col = n*DH + wn*32 + nb*8 + 2*tig;
            size_t row0 = (size_t)(i0 + r0)*BATCH + b;
            size_t row1 = (size_t)(i0 + r0 + 8)*BATCH + b;
            *(__half2*)&g_AVf[row0*DM + col] = __floats2half2_rn(oC[nb][0]*li0, oC[nb][1]*li0);
            *(__half2*)&g_AVf[row1*DM + col] = __floats2half2_rn(oC[nb][2]*li1, oC[nb][3]*li1);
        }
    }
}

// LayerNorm over g_O rows -> d_out
__global__ __launch_bounds__(256)
void k_ln(const float* __restrict__ gamma, const float* __restrict__ beta,
          float* __restrict__ out)
{
    __shared__ float red[16];
    const int t = threadIdx.x;
    const size_t row = blockIdx.x;
    float4 x = *(const float4*)&g_O[row*DM + t*4];
    float s = x.x + x.y + x.z + x.w;
    float ss = x.x*x.x + x.y*x.y + x.z*x.z + x.w*x.w;
    #pragma unroll
    for (int m = 16; m > 0; m >>= 1) {
        s  += __shfl_xor_sync(0xffffffffu, s, m);
        ss += __shfl_xor_sync(0xffffffffu, ss, m);
    }
    if ((t&31) == 0) { red[t>>5] = s; red[8 + (t>>5)] = ss; }
    __syncthreads();
    if (t < 8) {
        float a = red[t], bsum = red[8+t];
        #pragma unroll
        for (int m = 4; m > 0; m >>= 1) {
            a    += __shfl_xor_sync(0xffu, a, m);
            bsum += __shfl_xor_sync(0xffu, bsum, m);
        }
        if (t == 0) { red[0] = a; red[8] = bsum; }
    }
    __syncthreads();
    float mu = red[0] * (1.f/DM);
    float var = red[8] * (1.f/DM) - mu*mu;
    float rs = rsqrtf(var + 1e-5f);
    float4 g = *(const float4*)&gamma[t*4];
    float4 be = *(const float4*)&beta[t*4];
    float4 y;
    y.x = (x.x-mu)*rs*g.x + be.x;
    y.y = (x.y-mu)*rs*g.y + be.y;
    y.z = (x.z-mu)*rs*g.z + be.z;
    y.w = (x.w-mu)*rs*g.w + be.w;
    *(float4*)&out[row*DM + t*4] = y;
}

extern "C" void kernel_launch(void* const* d_in, const int* in_sizes, int n_in,
                              void* d_out, int out_size)
{
    const float* content = (const float*)d_in[0];
    const float* rel_pos = (const float*)d_in[1];
    const float* mems    = (const float*)d_in[2];
    const float* rwb     = (const float*)d_in[3];
    const float* rrb     = (const float*)d_in[4];
    const float* Wqkv    = (const float*)d_in[5];
    const float* Wr      = (const float*)d_in[6];
    const float* Wo      = (const float*)d_in[7];
    const float* gamma   = (const float*)d_in[8];
    const float* beta    = (const float*)d_in[9];
    float* out = (float*)d_out;

    cudaFuncSetAttribute(k_attn,  cudaFuncAttributeMaxDynamicSharedMemorySize, SMEM_ATTN);
    cudaFuncSetAttribute(k_qkv,   cudaFuncAttributeMaxDynamicSharedMemorySize, SMEM_GEMM);
    cudaFuncSetAttribute(k_rproj, cudaFuncAttributeMaxDynamicSharedMemorySize, SMEM_GEMM);
    cudaFuncSetAttribute(k_out,   cudaFuncAttributeMaxDynamicSharedMemorySize, SMEM_GEMM);

    k_toh_all<<<15360, 256>>>(mems, content, Wqkv, rel_pos, Wr, Wo);
    k_qkv  <<<1280, 256, SMEM_GEMM>>>(rwb, rrb);
    k_rproj<<<dim3(8, 16), 256, SMEM_GEMM>>>();
    k_attn <<<dim3(QLEN/64, NH, BATCH), 256, SMEM_ATTN>>>();
    k_out  <<<dim3(8, 32),  256, SMEM_GEMM>>>(content);
    k_ln   <<<QLEN*BATCH, 256>>>(gamma, beta, out);
}